// round 1
// baseline (speedup 1.0000x reference)
#include <cuda_runtime.h>
#include <math.h>

// ---------------- problem constants ----------------
#define Bq 2
#define Tt 2048
#define Cc 2048
#define Hh 32
#define Nn 64
#define Ff 7168
#define MM (Bq*Tt)          // 4096 tokens

// ---------------- device scratch (no allocs allowed) ----------------
__device__ float g_h  [(size_t)MM*Cc];
__device__ float g_xx [(size_t)MM*Cc];
__device__ float g_xxx[(size_t)MM*Cc];
__device__ float g_a  [(size_t)MM*160];
__device__ float g_xw [(size_t)MM*Cc];
__device__ float g_xk [(size_t)MM*Cc];
__device__ float g_xv [(size_t)MM*Cc];
__device__ float g_xr [(size_t)MM*Cc];
__device__ float g_xg [(size_t)MM*Cc];
__device__ float g_r  [(size_t)MM*Cc];
__device__ float g_k  [(size_t)MM*Cc];
__device__ float g_v  [(size_t)MM*Cc];
__device__ float g_g  [(size_t)MM*Cc];
__device__ float g_w  [(size_t)MM*Cc];
__device__ float g_wt [(size_t)MM*64];
__device__ float g_y  [(size_t)MM*Cc];
__device__ float g_att[(size_t)MM*Cc];
__device__ float g_x1 [(size_t)MM*Cc];
__device__ float g_xk2[(size_t)MM*Cc];
__device__ float g_xr2[(size_t)MM*Cc];
__device__ float g_kf [(size_t)MM*Ff];
__device__ float g_sig[(size_t)MM*Cc];

// ---------------- generic fp32 GEMM: C = epi(A @ B) ----------------
// A: [M,K] row-major with row stride lda
// B: [K,N] row-major
// C: [M,N] with row stride ldc
#define BMt 128
#define BNt 128
#define BKt 8
#define TMt 8
#define TNt 8

enum { E_NONE=0, E_TANH, E_SILU, E_SIGMOID, E_RELU2, E_ADDVEC, E_ADDX, E_MIX, E_CVMIX };

template<int EPI>
__global__ __launch_bounds__(256)
void gemm_f32(const float* __restrict__ A, const float* __restrict__ Bm,
              float* __restrict__ Cm,
              int M, int N, int K, int lda, int ldc,
              const float* __restrict__ aux0,
              const float* __restrict__ aux1,
              const float* __restrict__ aux2)
{
    __shared__ float As[BKt][BMt];
    __shared__ float Bs[BKt][BNt];
    const int bm = blockIdx.y * BMt;
    const int bn = blockIdx.x * BNt;
    const int tid = threadIdx.x;
    const int tcol = tid & 15;       // 0..15
    const int trow = tid >> 4;       // 0..15
    const int a_row = tid >> 1;      // 0..127
    const int a_col = (tid & 1) * 4; // 0 or 4
    const int b_row = tid >> 5;      // 0..7
    const int b_col = (tid & 31) * 4;
    const bool nfull = (bn + BNt) <= N;

    float acc[TMt][TNt];
    #pragma unroll
    for (int i = 0; i < TMt; i++)
        #pragma unroll
        for (int j = 0; j < TNt; j++) acc[i][j] = 0.f;

    for (int k0 = 0; k0 < K; k0 += BKt) {
        float4 av = *reinterpret_cast<const float4*>(A + (size_t)(bm + a_row)*lda + k0 + a_col);
        As[a_col+0][a_row] = av.x;
        As[a_col+1][a_row] = av.y;
        As[a_col+2][a_row] = av.z;
        As[a_col+3][a_row] = av.w;
        if (nfull) {
            *reinterpret_cast<float4*>(&Bs[b_row][b_col]) =
                *reinterpret_cast<const float4*>(Bm + (size_t)(k0 + b_row)*N + bn + b_col);
        } else {
            #pragma unroll
            for (int q = 0; q < 4; q++) {
                int n = bn + b_col + q;
                Bs[b_row][b_col+q] = (n < N) ? Bm[(size_t)(k0 + b_row)*N + n] : 0.f;
            }
        }
        __syncthreads();
        #pragma unroll
        for (int kk = 0; kk < BKt; kk++) {
            float regM[TMt], regN[TNt];
            *(float4*)&regM[0] = *(const float4*)&As[kk][trow*TMt];
            *(float4*)&regM[4] = *(const float4*)&As[kk][trow*TMt + 4];
            *(float4*)&regN[0] = *(const float4*)&Bs[kk][tcol*TNt];
            *(float4*)&regN[4] = *(const float4*)&Bs[kk][tcol*TNt + 4];
            #pragma unroll
            for (int i = 0; i < TMt; i++)
                #pragma unroll
                for (int j = 0; j < TNt; j++)
                    acc[i][j] = fmaf(regM[i], regN[j], acc[i][j]);
        }
        __syncthreads();
    }

    #pragma unroll
    for (int i = 0; i < TMt; i++) {
        int m = bm + trow*TMt + i;   // M is always a multiple of 128
        #pragma unroll
        for (int j = 0; j < TNt; j++) {
            int n = bn + tcol*TNt + j;
            if (n >= N) continue;
            float v = acc[i][j];
            size_t idx = (size_t)m * N + n;  // matrix aux (valid: ldc==N for those epis)
            if (EPI == E_TANH)        v = tanhf(v);
            else if (EPI == E_SILU)   v = v / (1.f + expf(-v));
            else if (EPI == E_SIGMOID)v = 1.f / (1.f + expf(-v));
            else if (EPI == E_RELU2) { float r = v > 0.f ? v : 0.f; v = r*r; }
            else if (EPI == E_ADDVEC) v = aux0[n] + v;
            else if (EPI == E_ADDX)   v = aux0[idx] + v;
            else if (EPI == E_MIX)    v = aux1[idx] + aux2[idx] * (aux0[n] + v);
            else if (EPI == E_CVMIX)  v = aux0[idx] + aux1[idx] * v;
            Cm[(size_t)m * ldc + n] = v;
        }
    }
}

// ---------------- LayerNorm over C per token ----------------
__global__ __launch_bounds__(256)
void ln_kernel(const float* __restrict__ x, const float* __restrict__ w,
               const float* __restrict__ b, float* __restrict__ out, float eps)
{
    const size_t base = (size_t)blockIdx.x * Cc;
    float sum = 0.f, sq = 0.f;
    for (int c = threadIdx.x; c < Cc; c += 256) { float v = x[base + c]; sum += v; sq += v*v; }
    #pragma unroll
    for (int o = 16; o; o >>= 1) {
        sum += __shfl_xor_sync(0xffffffffu, sum, o);
        sq  += __shfl_xor_sync(0xffffffffu, sq,  o);
    }
    __shared__ float s1[8], s2[8];
    int wid = threadIdx.x >> 5, lane = threadIdx.x & 31;
    if (!lane) { s1[wid] = sum; s2[wid] = sq; }
    __syncthreads();
    if (threadIdx.x == 0) {
        float ts = 0.f, tq = 0.f;
        #pragma unroll
        for (int i = 0; i < 8; i++) { ts += s1[i]; tq += s2[i]; }
        float m = ts / (float)Cc;
        float var = tq / (float)Cc - m*m;
        s1[0] = m; s2[0] = rsqrtf(var + eps);
    }
    __syncthreads();
    float m = s1[0], rstd = s2[0];
    for (int c = threadIdx.x; c < Cc; c += 256)
        out[base + c] = (x[base + c] - m) * rstd * w[c] + b[c];
}

// ---------------- token shift + first mix (time mixing) ----------------
__global__ void shift1_kernel(const float* __restrict__ tm_maa)
{
    size_t idx = (size_t)blockIdx.x * 256 + threadIdx.x;
    int c  = (int)(idx % Cc);
    int tt = (int)(idx / Cc);
    int t  = tt % Tt;
    float hv = g_h[idx];
    float hp = t ? g_h[idx - Cc] : 0.f;
    float d = hp - hv;
    g_xx[idx]  = d;
    g_xxx[idx] = hv + d * tm_maa[c];   // tm_maa row 0
}

// ---------------- token shift (channel mixing) ----------------
__global__ void shift2_kernel(const float* __restrict__ cm_maa)
{
    size_t idx = (size_t)blockIdx.x * 256 + threadIdx.x;
    int c  = (int)(idx % Cc);
    int tt = (int)(idx / Cc);
    int t  = tt % Tt;
    float hv = g_h[idx];
    float hp = t ? g_h[idx - Cc] : 0.f;
    float d = hp - hv;
    g_xk2[idx] = hv + d * cm_maa[c];
    g_xr2[idx] = hv + d * cm_maa[Cc + c];
}

// ---------------- WKV6 recurrent scan ----------------
// grid = B*H blocks, 128 threads. Thread (j = tid&63, half = tid>>6) owns
// rows [half*32, half*32+32) of state column j. Per step: 64 loader threads
// stage (r_i, k_i, u_i*k_i, d_i) as float4 in smem; every thread does 32
// LDS.128 + 4 FMA-class ops; partial y reduced across the two halves in smem.
__global__ __launch_bounds__(128)
void wkv6_kernel(const float* __restrict__ u)
{
    const int bh = blockIdx.x;
    const int b  = bh >> 5;
    const int hh = bh & 31;
    const int tid = threadIdx.x;
    const int j = tid & 63;
    const int ibase = (tid >> 6) * 32;
    __shared__ float4 sv[64];
    __shared__ float  yp[128];
    float S[32];
    #pragma unroll
    for (int i = 0; i < 32; i++) S[i] = 0.f;
    size_t off = (size_t)b * Tt * Cc + (size_t)hh * Nn;
    float ur = (tid < 64) ? u[hh * Nn + j] : 0.f;

    for (int t = 0; t < Tt; t++) {
        if (tid < 64) {
            float ri = g_r[off + j];
            float ki = g_k[off + j];
            float wi = g_w[off + j];
            sv[j] = make_float4(ri, ki, ur * ki, expf(-expf(wi)));
        }
        __syncthreads();
        float vj = g_v[off + j];
        float acc = 0.f;
        #pragma unroll
        for (int ii = 0; ii < 32; ii++) {
            float4 q = sv[ibase + ii];
            acc   = fmaf(q.x, fmaf(q.z, vj, S[ii]), acc);  // r_i*(S_ij + u_i*k_i*v_j)
            S[ii] = fmaf(S[ii], q.w, q.y * vj);            // S = S*d + k_i*v_j
        }
        yp[tid] = acc;
        __syncthreads();
        if (tid < 64) g_y[off + j] = yp[j] + yp[64 + j];
        off += Cc;
    }
}

// ---------------- GroupNorm(H groups) * silu(g) ----------------
__global__ __launch_bounds__(256)
void gnsilu_kernel(const float* __restrict__ lnw, const float* __restrict__ lnb)
{
    int gw  = blockIdx.x * 8 + (threadIdx.x >> 5);  // global warp = (token, head)
    int lane = threadIdx.x & 31;
    int t  = gw >> 5;   // / H
    int hh = gw & 31;
    size_t base = (size_t)t * Cc + (size_t)hh * Nn;
    float y0 = g_y[base + lane], y1 = g_y[base + 32 + lane];
    float sum = y0 + y1, sq = y0*y0 + y1*y1;
    #pragma unroll
    for (int o = 16; o; o >>= 1) {
        sum += __shfl_xor_sync(0xffffffffu, sum, o);
        sq  += __shfl_xor_sync(0xffffffffu, sq,  o);
    }
    float m = sum * (1.f / 64.f);
    float rstd = rsqrtf(sq * (1.f / 64.f) - m*m + 6.4e-4f);  // eps = 1e-5 * 8^2
    int ch = hh * Nn + lane;
    float gv0 = g_g[base + lane], gv1 = g_g[base + 32 + lane];  // already silu'd
    g_att[base + lane]      = ((y0 - m) * rstd * lnw[ch]      + lnb[ch])      * gv0;
    g_att[base + 32 + lane] = ((y1 - m) * rstd * lnw[ch + 32] + lnb[ch + 32]) * gv1;
}

// ---------------- host launch ----------------
static inline dim3 ggrid(int M, int N) { return dim3((N + BNt - 1) / BNt, M / BMt); }

extern "C" void kernel_launch(void* const* d_in, const int* in_sizes, int n_in,
                              void* d_out, int out_size)
{
    (void)in_sizes; (void)n_in; (void)out_size;
    const float* x          = (const float*)d_in[0];
    const float* ln1_w      = (const float*)d_in[1];
    const float* ln1_b      = (const float*)d_in[2];
    const float* ln2_w      = (const float*)d_in[3];
    const float* ln2_b      = (const float*)d_in[4];
    const float* tm_maa     = (const float*)d_in[5];
    const float* maa_w1     = (const float*)d_in[6];
    const float* maa_w2     = (const float*)d_in[7];
    const float* time_decay = (const float*)d_in[8];
    const float* td_w1      = (const float*)d_in[9];
    const float* td_w2      = (const float*)d_in[10];
    const float* time_faaaa = (const float*)d_in[11];
    const float* Wr  = (const float*)d_in[12];
    const float* Wk  = (const float*)d_in[13];
    const float* Wv  = (const float*)d_in[14];
    const float* Wg  = (const float*)d_in[15];
    const float* Wo  = (const float*)d_in[16];
    const float* lnx_w = (const float*)d_in[17];
    const float* lnx_b = (const float*)d_in[18];
    const float* cm_maa = (const float*)d_in[19];
    const float* Wck = (const float*)d_in[20];
    const float* Wcr = (const float*)d_in[21];
    const float* Wcv = (const float*)d_in[22];
    float* out = (float*)d_out;

    float *ph, *pxx, *pxxx, *pa, *pxw, *pxk, *pxv, *pxr, *pxg;
    float *pr, *pk, *pv, *pg, *pw, *pwt, *py, *patt, *px1, *pxk2, *pxr2, *pkf, *psig;
    cudaGetSymbolAddress((void**)&ph,   g_h);
    cudaGetSymbolAddress((void**)&pxx,  g_xx);
    cudaGetSymbolAddress((void**)&pxxx, g_xxx);
    cudaGetSymbolAddress((void**)&pa,   g_a);
    cudaGetSymbolAddress((void**)&pxw,  g_xw);
    cudaGetSymbolAddress((void**)&pxk,  g_xk);
    cudaGetSymbolAddress((void**)&pxv,  g_xv);
    cudaGetSymbolAddress((void**)&pxr,  g_xr);
    cudaGetSymbolAddress((void**)&pxg,  g_xg);
    cudaGetSymbolAddress((void**)&pr,   g_r);
    cudaGetSymbolAddress((void**)&pk,   g_k);
    cudaGetSymbolAddress((void**)&pv,   g_v);
    cudaGetSymbolAddress((void**)&pg,   g_g);
    cudaGetSymbolAddress((void**)&pw,   g_w);
    cudaGetSymbolAddress((void**)&pwt,  g_wt);
    cudaGetSymbolAddress((void**)&py,   g_y);
    cudaGetSymbolAddress((void**)&patt, g_att);
    cudaGetSymbolAddress((void**)&px1,  g_x1);
    cudaGetSymbolAddress((void**)&pxk2, g_xk2);
    cudaGetSymbolAddress((void**)&pxr2, g_xr2);
    cudaGetSymbolAddress((void**)&pkf,  g_kf);
    cudaGetSymbolAddress((void**)&psig, g_sig);

    const int ELT_BLOCKS = (MM * Cc) / 256;

    // ---- time mixing ----
    ln_kernel<<<MM, 256>>>(x, ln1_w, ln1_b, ph, 1e-5f);
    shift1_kernel<<<ELT_BLOCKS, 256>>>(tm_maa);
    gemm_f32<E_TANH><<<ggrid(MM, 160), 256>>>(pxxx, maa_w1, pa, MM, 160, Cc, Cc, 160,
                                              nullptr, nullptr, nullptr);
    float* mixout[5] = { pxw, pxk, pxv, pxr, pxg };
    for (int f = 0; f < 5; f++)
        gemm_f32<E_MIX><<<ggrid(MM, Cc), 256>>>(pa + f * 32, maa_w2 + (size_t)f * 32 * Cc,
                                                mixout[f], MM, Cc, 32, 160, Cc,
                                                tm_maa + (size_t)(1 + f) * Cc, ph, pxx);
    gemm_f32<E_NONE><<<ggrid(MM, Cc), 256>>>(pxr, Wr, pr, MM, Cc, Cc, Cc, Cc, 0, 0, 0);
    gemm_f32<E_NONE><<<ggrid(MM, Cc), 256>>>(pxk, Wk, pk, MM, Cc, Cc, Cc, Cc, 0, 0, 0);
    gemm_f32<E_NONE><<<ggrid(MM, Cc), 256>>>(pxv, Wv, pv, MM, Cc, Cc, Cc, Cc, 0, 0, 0);
    gemm_f32<E_SILU><<<ggrid(MM, Cc), 256>>>(pxg, Wg, pg, MM, Cc, Cc, Cc, Cc, 0, 0, 0);
    gemm_f32<E_TANH><<<ggrid(MM, 64), 256>>>(pxw, td_w1, pwt, MM, 64, Cc, Cc, 64, 0, 0, 0);
    gemm_f32<E_ADDVEC><<<ggrid(MM, Cc), 256>>>(pwt, td_w2, pw, MM, Cc, 64, 64, Cc,
                                               time_decay, 0, 0);
    wkv6_kernel<<<Bq * Hh, 128>>>(time_faaaa);
    gnsilu_kernel<<<MM * Hh / 8, 256>>>(lnx_w, lnx_b);
    gemm_f32<E_ADDX><<<ggrid(MM, Cc), 256>>>(patt, Wo, px1, MM, Cc, Cc, Cc, Cc, x, 0, 0);

    // ---- channel mixing ----
    ln_kernel<<<MM, 256>>>(px1, ln2_w, ln2_b, ph, 1e-5f);
    shift2_kernel<<<ELT_BLOCKS, 256>>>(cm_maa);
    gemm_f32<E_RELU2><<<ggrid(MM, Ff), 256>>>(pxk2, Wck, pkf, MM, Ff, Cc, Cc, Ff, 0, 0, 0);
    gemm_f32<E_SIGMOID><<<ggrid(MM, Cc), 256>>>(pxr2, Wcr, psig, MM, Cc, Cc, Cc, Cc, 0, 0, 0);
    gemm_f32<E_CVMIX><<<ggrid(MM, Cc), 256>>>(pkf, Wcv, out, MM, Cc, Ff, Ff, Cc,
                                              px1, psig, 0);
}

// round 3
// speedup vs baseline: 2.2863x; 2.2863x over previous
#include <cuda_runtime.h>
#include <cuda_bf16.h>
#include <math.h>

// ---------------- problem constants ----------------
#define Bq 2
#define Tt 2048
#define Cc 2048
#define Hh 32
#define Nn 64
#define Ff 7168
#define MM (Bq*Tt)          // 4096 tokens

typedef unsigned int u32;
typedef unsigned long long u64;
typedef __nv_bfloat16 bf16;

// ---------------- device scratch (no allocs allowed) ----------------
__device__ float g_h  [(size_t)MM*Cc];
__device__ float g_xx [(size_t)MM*Cc];
__device__ float g_xxx[(size_t)MM*Cc];
__device__ float g_a  [(size_t)MM*160];
__device__ float g_xw [(size_t)MM*Cc];
__device__ float g_r  [(size_t)MM*Cc];
__device__ float g_k  [(size_t)MM*Cc];
__device__ float g_v  [(size_t)MM*Cc];
__device__ float g_g  [(size_t)MM*Cc];
__device__ float g_w  [(size_t)MM*Cc];
__device__ float g_wt [(size_t)MM*64];
__device__ float g_y  [(size_t)MM*Cc];
__device__ float g_x1 [(size_t)MM*Cc];
__device__ float g_sig[(size_t)MM*Cc];

// bf16 hi/lo activation splits (A operands of tensor GEMMs)
__device__ __align__(16) bf16 g_xk_h[(size_t)MM*Cc], g_xk_l[(size_t)MM*Cc];
__device__ __align__(16) bf16 g_xv_h[(size_t)MM*Cc], g_xv_l[(size_t)MM*Cc];
__device__ __align__(16) bf16 g_xr_h[(size_t)MM*Cc], g_xr_l[(size_t)MM*Cc];
__device__ __align__(16) bf16 g_xg_h[(size_t)MM*Cc], g_xg_l[(size_t)MM*Cc];
__device__ __align__(16) bf16 g_att_h[(size_t)MM*Cc], g_att_l[(size_t)MM*Cc];
__device__ __align__(16) bf16 g_xk2_h[(size_t)MM*Cc], g_xk2_l[(size_t)MM*Cc];
__device__ __align__(16) bf16 g_xr2_h[(size_t)MM*Cc], g_xr2_l[(size_t)MM*Cc];
__device__ __align__(16) bf16 g_kf_h[(size_t)MM*Ff],  g_kf_l[(size_t)MM*Ff];

// bf16 hi/lo transposed weights ([N,K] K-major, B operands)
__device__ __align__(16) bf16 g_Wr_h [(size_t)Cc*Cc], g_Wr_l [(size_t)Cc*Cc];
__device__ __align__(16) bf16 g_Wk_h [(size_t)Cc*Cc], g_Wk_l [(size_t)Cc*Cc];
__device__ __align__(16) bf16 g_Wv_h [(size_t)Cc*Cc], g_Wv_l [(size_t)Cc*Cc];
__device__ __align__(16) bf16 g_Wg_h [(size_t)Cc*Cc], g_Wg_l [(size_t)Cc*Cc];
__device__ __align__(16) bf16 g_Wo_h [(size_t)Cc*Cc], g_Wo_l [(size_t)Cc*Cc];
__device__ __align__(16) bf16 g_Wcr_h[(size_t)Cc*Cc], g_Wcr_l[(size_t)Cc*Cc];
__device__ __align__(16) bf16 g_Wck_h[(size_t)Cc*Ff], g_Wck_l[(size_t)Cc*Ff]; // [7168,2048]
__device__ __align__(16) bf16 g_Wcv_h[(size_t)Ff*Cc], g_Wcv_l[(size_t)Ff*Cc]; // [2048,7168]

// ---------------- PTX helpers (baseline PTX only; no sm_103a features) ----
__device__ __forceinline__ u32 smem_u32(const void* p){
    u32 a;
    asm("{ .reg .u64 t; cvta.to.shared.u64 t, %1; cvt.u32.u64 %0, t; }" : "=r"(a) : "l"(p));
    return a;
}
__device__ __forceinline__ void cp16(u32 s, const void* g){
    asm volatile("cp.async.cg.shared.global [%0], [%1], 16;" :: "r"(s), "l"(g) : "memory");
}
__device__ __forceinline__ void cp_commit(){
    asm volatile("cp.async.commit_group;" ::: "memory");
}
template<int NG> __device__ __forceinline__ void cp_wait(){
    asm volatile("cp.async.wait_group %0;" :: "n"(NG) : "memory");
}
__device__ __forceinline__ void ldsm4(u32* r, u32 a){
    asm volatile("ldmatrix.sync.aligned.m8n8.x4.shared.b16 {%0,%1,%2,%3}, [%4];"
        : "=r"(r[0]), "=r"(r[1]), "=r"(r[2]), "=r"(r[3]) : "r"(a));
}
__device__ __forceinline__ void hmma(float* c, const u32* a, u32 b0, u32 b1){
    asm volatile(
        "mma.sync.aligned.m16n8k16.row.col.f32.bf16.bf16.f32 "
        "{%0,%1,%2,%3},{%4,%5,%6,%7},{%8,%9},{%0,%1,%2,%3};"
        : "+f"(c[0]), "+f"(c[1]), "+f"(c[2]), "+f"(c[3])
        : "r"(a[0]), "r"(a[1]), "r"(a[2]), "r"(a[3]), "r"(b0), "r"(b1));
}
__device__ __forceinline__ void split_bf16(float v, bf16& h, bf16& l){
    h = __float2bfloat16(v);
    l = __float2bfloat16(v - __bfloat162float(h));
}

// ---------------- split-bf16 HMMA GEMM ----------------
// C[M,N] = epi(A @ B^T): A = Ahi+Alo [M,K] bf16 K-major; B = Bhi+Blo [N,K] bf16 K-major.
// CTA tile 128x128, warp tile 64x32 (2x4 warps), KC=64, 3-stage cp.async.
// 3 MMA terms: AhBh + AhBl + AlBh (fp32 accum) -> ~1e-5 rel err.
#define STAGE_BYTES 65536u    // Ah(16K) Al(16K) Bh(16K) Bl(16K)
#define SM_MMA_TOTAL (3*65536)

enum { TC_NONE=0, TC_SILU, TC_ADDX, TC_RELU2, TC_SIGM, TC_CVMIX };

template<int EPI>
__global__ __launch_bounds__(256, 1)
void gemm_mma(const bf16* __restrict__ Ahi, const bf16* __restrict__ Alo,
              const bf16* __restrict__ Bhi, const bf16* __restrict__ Blo,
              float* __restrict__ C, int M, int N, int K,
              const float* __restrict__ aux0, const float* __restrict__ aux1,
              bf16* __restrict__ Ch, bf16* __restrict__ Cl)
{
    extern __shared__ char sm_dyn[];
    const u32 sb = smem_u32(sm_dyn);
    const int tid  = threadIdx.x;
    const int wid  = tid >> 5;
    const int lane = tid & 31;
    const int m0 = blockIdx.y * 128;
    const int n0 = blockIdx.x * 128;
    const int wm = (wid & 1) * 64;     // warp m offset in CTA tile
    const int wn = (wid >> 1) * 32;    // warp n offset

    // -------- loader mapping: 16B chunks, 128B rows, SW128 swizzle --------
    const int col16 = tid & 7;         // 16B chunk within 128B row
    const int lrow  = tid >> 3;        // 0..31 base row
    const u32 soff  = (u32)(lrow * 128 + col16 * 16);
    const u32 swz   = soff ^ ((soff >> 3) & 0x70);
    const size_t rstep = (size_t)32 * K * 2;     // 32 rows in bytes
    const char* gAh = (const char*)Ahi + ((size_t)(m0 + lrow) * K + col16 * 8) * 2;
    const char* gAl = (const char*)Alo + ((size_t)(m0 + lrow) * K + col16 * 8) * 2;
    const char* gBh = (const char*)Bhi + ((size_t)(n0 + lrow) * K + col16 * 8) * 2;
    const char* gBl = (const char*)Blo + ((size_t)(n0 + lrow) * K + col16 * 8) * 2;

    auto load_stage = [&](int s){
        u32 base = sb + (u32)(s % 3) * STAGE_BYTES + swz;
        size_t ko = (size_t)s * 128;   // 64 bf16 = 128B along K
        #pragma unroll
        for (int i = 0; i < 4; i++){
            cp16(base +          i*4096u, gAh + ko + i*rstep);
            cp16(base + 16384u + i*4096u, gAl + ko + i*rstep);
            cp16(base + 32768u + i*4096u, gBh + ko + i*rstep);
            cp16(base + 49152u + i*4096u, gBl + ko + i*rstep);
        }
        cp_commit();
    };

    // -------- ldmatrix per-lane invariants --------
    // A x4 mats: (m0-7,k0-7),(m8-15,k0-7),(m0-7,k8-15),(m8-15,k8-15)
    const u32 a_row = (u32)(wm + ((lane >> 3) & 1) * 8 + (lane & 7));
    const u32 a_kb  = (u32)((lane >> 4) * 16);
    // B x4 mats: (n0-7,k0-7),(n0-7,k8-15),(n8-15,k0-7),(n8-15,k8-15)
    const u32 b_row = (u32)(wn + (lane >> 4) * 8 + (lane & 7));
    const u32 b_kb  = (u32)(((lane >> 3) & 1) * 16);

    float acc[4][4][4];
    #pragma unroll
    for (int mi = 0; mi < 4; mi++)
        #pragma unroll
        for (int ni = 0; ni < 4; ni++)
            #pragma unroll
            for (int q = 0; q < 4; q++) acc[mi][ni][q] = 0.f;

    auto compute_stage = [&](u32 base){
        #pragma unroll
        for (int kk = 0; kk < 4; kk++){
            u32 ah[4][4], al[4][4], bh[2][4], bl[2][4];
            #pragma unroll
            for (int mi = 0; mi < 4; mi++){
                u32 off = (a_row + mi*16u) * 128u + (u32)kk*32u + a_kb;
                off ^= (off >> 3) & 0x70;
                ldsm4(ah[mi], base + off);
                ldsm4(al[mi], base + 16384u + off);
            }
            #pragma unroll
            for (int nj = 0; nj < 2; nj++){
                u32 off = (b_row + nj*16u) * 128u + (u32)kk*32u + b_kb;
                off ^= (off >> 3) & 0x70;
                ldsm4(bh[nj], base + 32768u + off);
                ldsm4(bl[nj], base + 49152u + off);
            }
            #pragma unroll
            for (int mi = 0; mi < 4; mi++)
                #pragma unroll
                for (int ni = 0; ni < 4; ni++){
                    const u32* ph = &bh[ni >> 1][(ni & 1) * 2];
                    const u32* pl = &bl[ni >> 1][(ni & 1) * 2];
                    hmma(acc[mi][ni], ah[mi], ph[0], ph[1]);  // Ah*Bh
                    hmma(acc[mi][ni], ah[mi], pl[0], pl[1]);  // Ah*Bl
                    hmma(acc[mi][ni], al[mi], ph[0], ph[1]);  // Al*Bh
                }
        }
    };

    const int NS = K >> 6;
    load_stage(0);
    load_stage(1);
    for (int s = 0; s < NS; s++){
        if (s + 1 < NS) cp_wait<1>(); else cp_wait<0>();
        __syncthreads();
        if (s + 2 < NS) load_stage(s + 2);
        compute_stage(sb + (u32)(s % 3) * STAGE_BYTES);
    }

    // -------- epilogue --------
    #pragma unroll
    for (int mi = 0; mi < 4; mi++){
        #pragma unroll
        for (int ni = 0; ni < 4; ni++){
            const int n = n0 + wn + ni*8 + (lane & 3)*2;
            #pragma unroll
            for (int half = 0; half < 2; half++){
                const int m = m0 + wm + mi*16 + (lane >> 2) + half*8;
                const size_t idx = (size_t)m * N + n;
                float v0 = acc[mi][ni][half*2 + 0];
                float v1 = acc[mi][ni][half*2 + 1];
                if (EPI == TC_SILU){
                    v0 = v0 / (1.f + expf(-v0));
                    v1 = v1 / (1.f + expf(-v1));
                } else if (EPI == TC_ADDX){
                    v0 += aux0[idx]; v1 += aux0[idx + 1];
                } else if (EPI == TC_SIGM){
                    v0 = 1.f / (1.f + expf(-v0));
                    v1 = 1.f / (1.f + expf(-v1));
                } else if (EPI == TC_CVMIX){
                    v0 = aux0[idx]     + aux1[idx]     * v0;
                    v1 = aux0[idx + 1] + aux1[idx + 1] * v1;
                } else if (EPI == TC_RELU2){
                    float r0 = v0 > 0.f ? v0 : 0.f;
                    float r1 = v1 > 0.f ? v1 : 0.f;
                    v0 = r0 * r0; v1 = r1 * r1;
                    bf16 h0, l0, h1, l1;
                    split_bf16(v0, h0, l0);
                    split_bf16(v1, h1, l1);
                    __nv_bfloat162 hp; hp.x = h0; hp.y = h1;
                    __nv_bfloat162 lp; lp.x = l0; lp.y = l1;
                    *reinterpret_cast<__nv_bfloat162*>(Ch + idx) = hp;
                    *reinterpret_cast<__nv_bfloat162*>(Cl + idx) = lp;
                    continue;
                }
                float2 o; o.x = v0; o.y = v1;
                *reinterpret_cast<float2*>(C + idx) = o;
            }
        }
    }
}

// ---------------- weight transpose + split:  W[K,N] f32 -> T[N,K] bf16 hi/lo ----------------
__global__ __launch_bounds__(256)
void wtrans(const float* __restrict__ W, bf16* __restrict__ Th, bf16* __restrict__ Tl,
            int K, int N)
{
    __shared__ float s[32][33];
    const int tx = threadIdx.x & 31, ty = threadIdx.x >> 5;  // 32x8
    const int n0 = blockIdx.x * 32, k0 = blockIdx.y * 32;
    #pragma unroll
    for (int r = 0; r < 32; r += 8)
        s[ty + r][tx] = W[(size_t)(k0 + ty + r) * N + n0 + tx];
    __syncthreads();
    #pragma unroll
    for (int r = 0; r < 32; r += 8){
        float v = s[tx][ty + r];
        size_t o = (size_t)(n0 + ty + r) * K + k0 + tx;
        bf16 hb, lb; split_bf16(v, hb, lb);
        Th[o] = hb; Tl[o] = lb;
    }
}

// ---------------- small SIMT fp32 GEMM (mixers) ----------------
#define BMt 128
#define BNt 128
#define BKt 8
#define TMt 8
#define TNt 8
enum { E_NONE=0, E_TANH, E_SILU, E_SIGMOID, E_RELU2, E_ADDVEC, E_ADDX, E_MIX, E_CVMIX, E_MIXB };

template<int EPI>
__global__ __launch_bounds__(256)
void gemm_f32(const float* __restrict__ A, const float* __restrict__ Bm,
              float* __restrict__ Cm,
              int M, int N, int K, int lda, int ldc,
              const float* __restrict__ aux0,
              const float* __restrict__ aux1,
              const float* __restrict__ aux2,
              bf16* __restrict__ Ch, bf16* __restrict__ Cl)
{
    __shared__ float As[BKt][BMt];
    __shared__ float Bs[BKt][BNt];
    const int bm = blockIdx.y * BMt;
    const int bn = blockIdx.x * BNt;
    const int tid = threadIdx.x;
    const int tcol = tid & 15;
    const int trow = tid >> 4;
    const int a_row = tid >> 1;
    const int a_col = (tid & 1) * 4;
    const int b_row = tid >> 5;
    const int b_col = (tid & 31) * 4;
    const bool nfull = (bn + BNt) <= N;

    float acc[TMt][TNt];
    #pragma unroll
    for (int i = 0; i < TMt; i++)
        #pragma unroll
        for (int j = 0; j < TNt; j++) acc[i][j] = 0.f;

    for (int k0 = 0; k0 < K; k0 += BKt) {
        float4 av = *reinterpret_cast<const float4*>(A + (size_t)(bm + a_row)*lda + k0 + a_col);
        As[a_col+0][a_row] = av.x;
        As[a_col+1][a_row] = av.y;
        As[a_col+2][a_row] = av.z;
        As[a_col+3][a_row] = av.w;
        if (nfull) {
            *reinterpret_cast<float4*>(&Bs[b_row][b_col]) =
                *reinterpret_cast<const float4*>(Bm + (size_t)(k0 + b_row)*N + bn + b_col);
        } else {
            #pragma unroll
            for (int q = 0; q < 4; q++) {
                int n = bn + b_col + q;
                Bs[b_row][b_col+q] = (n < N) ? Bm[(size_t)(k0 + b_row)*N + n] : 0.f;
            }
        }
        __syncthreads();
        #pragma unroll
        for (int kk = 0; kk < BKt; kk++) {
            float regM[TMt], regN[TNt];
            *(float4*)&regM[0] = *(const float4*)&As[kk][trow*TMt];
            *(float4*)&regM[4] = *(const float4*)&As[kk][trow*TMt + 4];
            *(float4*)&regN[0] = *(const float4*)&Bs[kk][tcol*TNt];
            *(float4*)&regN[4] = *(const float4*)&Bs[kk][tcol*TNt + 4];
            #pragma unroll
            for (int i = 0; i < TMt; i++)
                #pragma unroll
                for (int j = 0; j < TNt; j++)
                    acc[i][j] = fmaf(regM[i], regN[j], acc[i][j]);
        }
        __syncthreads();
    }

    #pragma unroll
    for (int i = 0; i < TMt; i++) {
        int m = bm + trow*TMt + i;
        #pragma unroll
        for (int j = 0; j < TNt; j++) {
            int n = bn + tcol*TNt + j;
            if (n >= N) continue;
            float v = acc[i][j];
            size_t idx = (size_t)m * N + n;
            if (EPI == E_TANH)        v = tanhf(v);
            else if (EPI == E_SILU)   v = v / (1.f + expf(-v));
            else if (EPI == E_SIGMOID)v = 1.f / (1.f + expf(-v));
            else if (EPI == E_RELU2) { float r = v > 0.f ? v : 0.f; v = r*r; }
            else if (EPI == E_ADDVEC) v = aux0[n] + v;
            else if (EPI == E_ADDX)   v = aux0[idx] + v;
            else if (EPI == E_MIX)    v = aux1[idx] + aux2[idx] * (aux0[n] + v);
            else if (EPI == E_CVMIX)  v = aux0[idx] + aux1[idx] * v;
            else if (EPI == E_MIXB) {
                v = aux1[idx] + aux2[idx] * (aux0[n] + v);
                bf16 hb, lb; split_bf16(v, hb, lb);
                Ch[idx] = hb; Cl[idx] = lb;
            }
            if (EPI != E_MIXB)
                Cm[(size_t)m * ldc + n] = v;
        }
    }
}

// ---------------- LayerNorm over C per token ----------------
__global__ __launch_bounds__(256)
void ln_kernel(const float* __restrict__ x, const float* __restrict__ w,
               const float* __restrict__ b, float* __restrict__ out, float eps)
{
    const size_t base = (size_t)blockIdx.x * Cc;
    float sum = 0.f, sq = 0.f;
    for (int c = threadIdx.x; c < Cc; c += 256) { float v = x[base + c]; sum += v; sq += v*v; }
    #pragma unroll
    for (int o = 16; o; o >>= 1) {
        sum += __shfl_xor_sync(0xffffffffu, sum, o);
        sq  += __shfl_xor_sync(0xffffffffu, sq,  o);
    }
    __shared__ float s1[8], s2[8];
    int wid = threadIdx.x >> 5, lane = threadIdx.x & 31;
    if (!lane) { s1[wid] = sum; s2[wid] = sq; }
    __syncthreads();
    if (threadIdx.x == 0) {
        float ts = 0.f, tq = 0.f;
        #pragma unroll
        for (int i = 0; i < 8; i++) { ts += s1[i]; tq += s2[i]; }
        float m = ts / (float)Cc;
        float var = tq / (float)Cc - m*m;
        s1[0] = m; s2[0] = rsqrtf(var + eps);
    }
    __syncthreads();
    float m = s1[0], rstd = s2[0];
    for (int c = threadIdx.x; c < Cc; c += 256)
        out[base + c] = (x[base + c] - m) * rstd * w[c] + b[c];
}

// ---------------- token shift + first mix (time mixing) ----------------
__global__ void shift1_kernel(const float* __restrict__ tm_maa)
{
    size_t idx = (size_t)blockIdx.x * 256 + threadIdx.x;
    int c  = (int)(idx % Cc);
    int tt = (int)(idx / Cc);
    int t  = tt % Tt;
    float hv = g_h[idx];
    float hp = t ? g_h[idx - Cc] : 0.f;
    float d = hp - hv;
    g_xx[idx]  = d;
    g_xxx[idx] = hv + d * tm_maa[c];
}

// ---------------- token shift (channel mixing) -> bf16 hi/lo ----------------
__global__ void shift2_kernel(const float* __restrict__ cm_maa)
{
    size_t idx = (size_t)blockIdx.x * 256 + threadIdx.x;
    int c  = (int)(idx % Cc);
    int tt = (int)(idx / Cc);
    int t  = tt % Tt;
    float hv = g_h[idx];
    float hp = t ? g_h[idx - Cc] : 0.f;
    float d = hp - hv;
    float a = hv + d * cm_maa[c];
    float b = hv + d * cm_maa[Cc + c];
    bf16 hb, lb;
    split_bf16(a, hb, lb); g_xk2_h[idx] = hb; g_xk2_l[idx] = lb;
    split_bf16(b, hb, lb); g_xr2_h[idx] = hb; g_xr2_l[idx] = lb;
}

// ---------------- WKV6 recurrent scan ----------------
__global__ __launch_bounds__(128)
void wkv6_kernel(const float* __restrict__ u)
{
    const int bh = blockIdx.x;
    const int b  = bh >> 5;
    const int hh = bh & 31;
    const int tid = threadIdx.x;
    const int j = tid & 63;
    const int ibase = (tid >> 6) * 32;
    __shared__ float4 sv[64];
    __shared__ float  yp[128];
    float S[32];
    #pragma unroll
    for (int i = 0; i < 32; i++) S[i] = 0.f;
    size_t off = (size_t)b * Tt * Cc + (size_t)hh * Nn;
    float ur = (tid < 64) ? u[hh * Nn + j] : 0.f;

    for (int t = 0; t < Tt; t++) {
        if (tid < 64) {
            float ri = g_r[off + j];
            float ki = g_k[off + j];
            float wi = g_w[off + j];
            sv[j] = make_float4(ri, ki, ur * ki, expf(-expf(wi)));
        }
        __syncthreads();
        float vj = g_v[off + j];
        float acc = 0.f;
        #pragma unroll
        for (int ii = 0; ii < 32; ii++) {
            float4 q = sv[ibase + ii];
            acc   = fmaf(q.x, fmaf(q.z, vj, S[ii]), acc);
            S[ii] = fmaf(S[ii], q.w, q.y * vj);
        }
        yp[tid] = acc;
        __syncthreads();
        if (tid < 64) g_y[off + j] = yp[j] + yp[64 + j];
        off += Cc;
    }
}

// ---------------- GroupNorm(H) * silu-gate -> att bf16 hi/lo ----------------
__global__ __launch_bounds__(256)
void gnsilu_kernel(const float* __restrict__ lnw, const float* __restrict__ lnb)
{
    int gw  = blockIdx.x * 8 + (threadIdx.x >> 5);
    int lane = threadIdx.x & 31;
    int t  = gw >> 5;
    int hh = gw & 31;
    size_t base = (size_t)t * Cc + (size_t)hh * Nn;
    float y0 = g_y[base + lane], y1 = g_y[base + 32 + lane];
    float sum = y0 + y1, sq = y0*y0 + y1*y1;
    #pragma unroll
    for (int o = 16; o; o >>= 1) {
        sum += __shfl_xor_sync(0xffffffffu, sum, o);
        sq  += __shfl_xor_sync(0xffffffffu, sq,  o);
    }
    float m = sum * (1.f / 64.f);
    float rstd = rsqrtf(sq * (1.f / 64.f) - m*m + 6.4e-4f);
    int ch = hh * Nn + lane;
    float gv0 = g_g[base + lane], gv1 = g_g[base + 32 + lane];
    float o0 = ((y0 - m) * rstd * lnw[ch]      + lnb[ch])      * gv0;
    float o1 = ((y1 - m) * rstd * lnw[ch + 32] + lnb[ch + 32]) * gv1;
    bf16 hb, lb;
    split_bf16(o0, hb, lb); g_att_h[base + lane]      = hb; g_att_l[base + lane]      = lb;
    split_bf16(o1, hb, lb); g_att_h[base + 32 + lane] = hb; g_att_l[base + 32 + lane] = lb;
}

// ---------------- host launch ----------------
static inline dim3 ggrid(int M, int N)  { return dim3((N + BNt - 1) / BNt, M / BMt); }
static inline dim3 mmagrid(int M, int N){ return dim3(N / 128, M / 128); }

#define SYMADDR(v, s) cudaGetSymbolAddress((void**)&v, s)

extern "C" void kernel_launch(void* const* d_in, const int* in_sizes, int n_in,
                              void* d_out, int out_size)
{
    (void)in_sizes; (void)n_in; (void)out_size;
    const float* x          = (const float*)d_in[0];
    const float* ln1_w      = (const float*)d_in[1];
    const float* ln1_b      = (const float*)d_in[2];
    const float* ln2_w      = (const float*)d_in[3];
    const float* ln2_b      = (const float*)d_in[4];
    const float* tm_maa     = (const float*)d_in[5];
    const float* maa_w1     = (const float*)d_in[6];
    const float* maa_w2     = (const float*)d_in[7];
    const float* time_decay = (const float*)d_in[8];
    const float* td_w1      = (const float*)d_in[9];
    const float* td_w2      = (const float*)d_in[10];
    const float* time_faaaa = (const float*)d_in[11];
    const float* Wr  = (const float*)d_in[12];
    const float* Wk  = (const float*)d_in[13];
    const float* Wv  = (const float*)d_in[14];
    const float* Wg  = (const float*)d_in[15];
    const float* Wo  = (const float*)d_in[16];
    const float* lnx_w = (const float*)d_in[17];
    const float* lnx_b = (const float*)d_in[18];
    const float* cm_maa = (const float*)d_in[19];
    const float* Wck = (const float*)d_in[20];
    const float* Wcr = (const float*)d_in[21];
    const float* Wcv = (const float*)d_in[22];
    float* out = (float*)d_out;

    float *ph, *pxx, *pxxx, *pa, *pxw, *pr, *pk, *pv, *pg, *pw, *pwt, *py, *px1, *psig;
    SYMADDR(ph, g_h);   SYMADDR(pxx, g_xx); SYMADDR(pxxx, g_xxx); SYMADDR(pa, g_a);
    SYMADDR(pxw, g_xw); SYMADDR(pr, g_r);   SYMADDR(pk, g_k);     SYMADDR(pv, g_v);
    SYMADDR(pg, g_g);   SYMADDR(pw, g_w);   SYMADDR(pwt, g_wt);   SYMADDR(py, g_y);
    SYMADDR(px1, g_x1); SYMADDR(psig, g_sig);

    bf16 *xkh,*xkl,*xvh,*xvl,*xrh,*xrl,*xgh,*xgl,*atth,*attl,*xk2h,*xk2l,*xr2h,*xr2l,*kfh,*kfl;
    SYMADDR(xkh, g_xk_h); SYMADDR(xkl, g_xk_l);
    SYMADDR(xvh, g_xv_h); SYMADDR(xvl, g_xv_l);
    SYMADDR(xrh, g_xr_h); SYMADDR(xrl, g_xr_l);
    SYMADDR(xgh, g_xg_h); SYMADDR(xgl, g_xg_l);
    SYMADDR(atth, g_att_h); SYMADDR(attl, g_att_l);
    SYMADDR(xk2h, g_xk2_h); SYMADDR(xk2l, g_xk2_l);
    SYMADDR(xr2h, g_xr2_h); SYMADDR(xr2l, g_xr2_l);
    SYMADDR(kfh, g_kf_h);   SYMADDR(kfl, g_kf_l);

    bf16 *wrh,*wrl,*wkh,*wkl,*wvh,*wvl,*wgh,*wgl,*woh,*wol,*wcrh,*wcrl,*wckh,*wckl,*wcvh,*wcvl;
    SYMADDR(wrh, g_Wr_h);   SYMADDR(wrl, g_Wr_l);
    SYMADDR(wkh, g_Wk_h);   SYMADDR(wkl, g_Wk_l);
    SYMADDR(wvh, g_Wv_h);   SYMADDR(wvl, g_Wv_l);
    SYMADDR(wgh, g_Wg_h);   SYMADDR(wgl, g_Wg_l);
    SYMADDR(woh, g_Wo_h);   SYMADDR(wol, g_Wo_l);
    SYMADDR(wcrh, g_Wcr_h); SYMADDR(wcrl, g_Wcr_l);
    SYMADDR(wckh, g_Wck_h); SYMADDR(wckl, g_Wck_l);
    SYMADDR(wcvh, g_Wcv_h); SYMADDR(wcvl, g_Wcv_l);

    // opt-in dynamic smem for the HMMA GEMMs (192 KB)
    cudaFuncSetAttribute(gemm_mma<TC_NONE>,  cudaFuncAttributeMaxDynamicSharedMemorySize, SM_MMA_TOTAL);
    cudaFuncSetAttribute(gemm_mma<TC_SILU>,  cudaFuncAttributeMaxDynamicSharedMemorySize, SM_MMA_TOTAL);
    cudaFuncSetAttribute(gemm_mma<TC_ADDX>,  cudaFuncAttributeMaxDynamicSharedMemorySize, SM_MMA_TOTAL);
    cudaFuncSetAttribute(gemm_mma<TC_RELU2>, cudaFuncAttributeMaxDynamicSharedMemorySize, SM_MMA_TOTAL);
    cudaFuncSetAttribute(gemm_mma<TC_SIGM>,  cudaFuncAttributeMaxDynamicSharedMemorySize, SM_MMA_TOTAL);
    cudaFuncSetAttribute(gemm_mma<TC_CVMIX>, cudaFuncAttributeMaxDynamicSharedMemorySize, SM_MMA_TOTAL);

    const int ELT_BLOCKS = (MM * Cc) / 256;

    // ---- weight transpose + split (independent of activations) ----
    wtrans<<<dim3(Cc/32, Cc/32), 256>>>(Wr,  wrh,  wrl,  Cc, Cc);
    wtrans<<<dim3(Cc/32, Cc/32), 256>>>(Wk,  wkh,  wkl,  Cc, Cc);
    wtrans<<<dim3(Cc/32, Cc/32), 256>>>(Wv,  wvh,  wvl,  Cc, Cc);
    wtrans<<<dim3(Cc/32, Cc/32), 256>>>(Wg,  wgh,  wgl,  Cc, Cc);
    wtrans<<<dim3(Cc/32, Cc/32), 256>>>(Wo,  woh,  wol,  Cc, Cc);
    wtrans<<<dim3(Cc/32, Cc/32), 256>>>(Wcr, wcrh, wcrl, Cc, Cc);
    wtrans<<<dim3(Ff/32, Cc/32), 256>>>(Wck, wckh, wckl, Cc, Ff);
    wtrans<<<dim3(Cc/32, Ff/32), 256>>>(Wcv, wcvh, wcvl, Ff, Cc);

    // ---- time mixing ----
    ln_kernel<<<MM, 256>>>(x, ln1_w, ln1_b, ph, 1e-5f);
    shift1_kernel<<<ELT_BLOCKS, 256>>>(tm_maa);
    gemm_f32<E_TANH><<<ggrid(MM, 160), 256>>>(pxxx, maa_w1, pa, MM, 160, Cc, Cc, 160,
                                              nullptr, nullptr, nullptr, nullptr, nullptr);
    // f=0 (w) -> f32; f=1..4 (k,v,r,g) -> bf16 hi/lo
    gemm_f32<E_MIX><<<ggrid(MM, Cc), 256>>>(pa + 0*32, maa_w2 + (size_t)0*32*Cc, pxw,
                                            MM, Cc, 32, 160, Cc,
                                            tm_maa + (size_t)1*Cc, ph, pxx, nullptr, nullptr);
    bf16* mh[4]  = { xkh, xvh, xrh, xgh };
    bf16* mlv[4] = { xkl, xvl, xrl, xgl };
    for (int f = 1; f < 5; f++)
        gemm_f32<E_MIXB><<<ggrid(MM, Cc), 256>>>(pa + f*32, maa_w2 + (size_t)f*32*Cc, nullptr,
                                                 MM, Cc, 32, 160, Cc,
                                                 tm_maa + (size_t)(1+f)*Cc, ph, pxx,
                                                 mh[f-1], mlv[f-1]);
    gemm_f32<E_TANH><<<ggrid(MM, 64), 256>>>(pxw, td_w1, pwt, MM, 64, Cc, Cc, 64,
                                             nullptr, nullptr, nullptr, nullptr, nullptr);
    gemm_f32<E_ADDVEC><<<ggrid(MM, Cc), 256>>>(pwt, td_w2, pw, MM, Cc, 64, 64, Cc,
                                               time_decay, nullptr, nullptr, nullptr, nullptr);

    gemm_mma<TC_NONE><<<mmagrid(MM, Cc), 256, SM_MMA_TOTAL>>>(xrh, xrl, wrh, wrl, pr,
        MM, Cc, Cc, nullptr, nullptr, nullptr, nullptr);
    gemm_mma<TC_NONE><<<mmagrid(MM, Cc), 256, SM_MMA_TOTAL>>>(xkh, xkl, wkh, wkl, pk,
        MM, Cc, Cc, nullptr, nullptr, nullptr, nullptr);
    gemm_mma<TC_NONE><<<mmagrid(MM, Cc), 256, SM_MMA_TOTAL>>>(xvh, xvl, wvh, wvl, pv,
        MM, Cc, Cc, nullptr, nullptr, nullptr, nullptr);
    gemm_mma<TC_SILU><<<mmagrid(MM, Cc), 256, SM_MMA_TOTAL>>>(xgh, xgl, wgh, wgl, pg,
        MM, Cc, Cc, nullptr, nullptr, nullptr, nullptr);

    wkv6_kernel<<<Bq * Hh, 128>>>(time_faaaa);
    gnsilu_kernel<<<MM * Hh / 8, 256>>>(lnx_w, lnx_b);
    gemm_mma<TC_ADDX><<<mmagrid(MM, Cc), 256, SM_MMA_TOTAL>>>(atth, attl, woh, wol, px1,
        MM, Cc, Cc, x, nullptr, nullptr, nullptr);

    // ---- channel mixing ----
    ln_kernel<<<MM, 256>>>(px1, ln2_w, ln2_b, ph, 1e-5f);
    shift2_kernel<<<ELT_BLOCKS, 256>>>(cm_maa);
    gemm_mma<TC_RELU2><<<mmagrid(MM, Ff), 256, SM_MMA_TOTAL>>>(xk2h, xk2l, wckh, wckl, nullptr,
        MM, Ff, Cc, nullptr, nullptr, kfh, kfl);
    gemm_mma<TC_SIGM><<<mmagrid(MM, Cc), 256, SM_MMA_TOTAL>>>(xr2h, xr2l, wcrh, wcrl, psig,
        MM, Cc, Cc, nullptr, nullptr, nullptr, nullptr);
    gemm_mma<TC_CVMIX><<<mmagrid(MM, Cc), 256, SM_MMA_TOTAL>>>(kfh, kfl, wcvh, wcvl, out,
        MM, Cc, Ff, px1, psig, nullptr, nullptr);
}

// round 4
// speedup vs baseline: 3.3539x; 1.4669x over previous
#include <cuda_runtime.h>
#include <cuda_fp16.h>
#include <math.h>

// ---------------- problem constants ----------------
#define Bq 2
#define Tt 2048
#define Cc 2048
#define Hh 32
#define Nn 64
#define Ff 7168
#define MM (Bq*Tt)          // 4096 tokens

typedef unsigned int u32;
typedef unsigned long long u64;

// ---------------- device scratch (no allocs allowed) ----------------
__device__ float g_h  [(size_t)MM*Cc];
__device__ float g_xx [(size_t)MM*Cc];
__device__ float g_xxx[(size_t)MM*Cc];
__device__ float g_a  [(size_t)MM*160];
__device__ float g_xw [(size_t)MM*Cc];
__device__ float g_r  [(size_t)MM*Cc];
__device__ float g_k  [(size_t)MM*Cc];
__device__ float g_v  [(size_t)MM*Cc];
__device__ float g_g  [(size_t)MM*Cc];
__device__ float g_w  [(size_t)MM*Cc];
__device__ float g_wt [(size_t)MM*64];
__device__ float g_y  [(size_t)MM*Cc];
__device__ float g_x1 [(size_t)MM*Cc];
__device__ float g_sig[(size_t)MM*Cc];

// fp16 hi/lo activation splits (A operands)
__device__ __align__(16) __half g_xk_h[(size_t)MM*Cc], g_xk_l[(size_t)MM*Cc];
__device__ __align__(16) __half g_xv_h[(size_t)MM*Cc], g_xv_l[(size_t)MM*Cc];
__device__ __align__(16) __half g_xr_h[(size_t)MM*Cc], g_xr_l[(size_t)MM*Cc];
__device__ __align__(16) __half g_xg_h[(size_t)MM*Cc], g_xg_l[(size_t)MM*Cc];
__device__ __align__(16) __half g_att_h[(size_t)MM*Cc], g_att_l[(size_t)MM*Cc];
__device__ __align__(16) __half g_xk2_h[(size_t)MM*Cc], g_xk2_l[(size_t)MM*Cc];
__device__ __align__(16) __half g_xr2_h[(size_t)MM*Cc], g_xr2_l[(size_t)MM*Cc];
__device__ __align__(16) __half g_kf_h[(size_t)MM*Ff],  g_kf_l[(size_t)MM*Ff];

// fp16 transposed weights ([N,K] K-major, single-precision-rounded B operands)
__device__ __align__(16) __half g_Wr16 [(size_t)Cc*Cc];
__device__ __align__(16) __half g_Wk16 [(size_t)Cc*Cc];
__device__ __align__(16) __half g_Wv16 [(size_t)Cc*Cc];
__device__ __align__(16) __half g_Wg16 [(size_t)Cc*Cc];
__device__ __align__(16) __half g_Wo16 [(size_t)Cc*Cc];
__device__ __align__(16) __half g_Wcr16[(size_t)Cc*Cc];
__device__ __align__(16) __half g_Wck16[(size_t)Cc*Ff]; // [7168,2048]
__device__ __align__(16) __half g_Wcv16[(size_t)Ff*Cc]; // [2048,7168]

// ---------------- PTX helpers (baseline PTX; no sm_103a-only features) ----
__device__ __forceinline__ u32 smem_u32(const void* p){
    u32 a;
    asm("{ .reg .u64 t; cvta.to.shared.u64 t, %1; cvt.u32.u64 %0, t; }" : "=r"(a) : "l"(p));
    return a;
}
__device__ __forceinline__ void cp16(u32 s, const void* g){
    asm volatile("cp.async.cg.shared.global [%0], [%1], 16;" :: "r"(s), "l"(g) : "memory");
}
__device__ __forceinline__ void cp_commit(){
    asm volatile("cp.async.commit_group;" ::: "memory");
}
template<int NG> __device__ __forceinline__ void cp_wait(){
    asm volatile("cp.async.wait_group %0;" :: "n"(NG) : "memory");
}
__device__ __forceinline__ void ldsm4(u32* r, u32 a){
    asm volatile("ldmatrix.sync.aligned.m8n8.x4.shared.b16 {%0,%1,%2,%3}, [%4];"
        : "=r"(r[0]), "=r"(r[1]), "=r"(r[2]), "=r"(r[3]) : "r"(a));
}
__device__ __forceinline__ void hmma16(float* c, const u32* a, u32 b0, u32 b1){
    asm volatile(
        "mma.sync.aligned.m16n8k16.row.col.f32.f16.f16.f32 "
        "{%0,%1,%2,%3},{%4,%5,%6,%7},{%8,%9},{%0,%1,%2,%3};"
        : "+f"(c[0]), "+f"(c[1]), "+f"(c[2]), "+f"(c[3])
        : "r"(a[0]), "r"(a[1]), "r"(a[2]), "r"(a[3]), "r"(b0), "r"(b1));
}
__device__ __forceinline__ void split_f16(float v, __half& h, __half& l){
    h = __float2half_rn(v);
    l = __float2half_rn(v - __half2float(h));
}

// ---------------- split-fp16 HMMA GEMM (2 terms) ----------------
// C[M,N] = epi(A @ B^T): A = Ah+Al [M,K] fp16 K-major (exact); B fp16 [N,K].
// Error = A*deltaB ~ 2^-12 relative. CTA 128x128, warp 64x32, KC=64, 3-stage cp.async.
#define STAGE_BYTES 49152u    // Ah(16K) Al(16K) B(16K)
#define SM_MMA_TOTAL (3*49152)

enum { TC_NONE=0, TC_SILU, TC_ADDX, TC_RELU2, TC_SIGM, TC_CVMIX };

template<int EPI>
__global__ __launch_bounds__(256, 1)
void gemm_mma(const __half* __restrict__ Ahi, const __half* __restrict__ Alo,
              const __half* __restrict__ Bh16,
              float* __restrict__ C, int M, int N, int K,
              const float* __restrict__ aux0, const float* __restrict__ aux1,
              __half* __restrict__ Ch, __half* __restrict__ Cl)
{
    extern __shared__ char sm_dyn[];
    const u32 sb = smem_u32(sm_dyn);
    const int tid  = threadIdx.x;
    const int wid  = tid >> 5;
    const int lane = tid & 31;
    const int m0 = blockIdx.y * 128;
    const int n0 = blockIdx.x * 128;
    const int wm = (wid & 1) * 64;
    const int wn = (wid >> 1) * 32;

    // loader mapping: 16B chunks, 128B rows, SW128 swizzle
    const int col16 = tid & 7;
    const int lrow  = tid >> 3;
    const u32 soff  = (u32)(lrow * 128 + col16 * 16);
    const u32 swz   = soff ^ ((soff >> 3) & 0x70);
    const size_t rstep = (size_t)32 * K * 2;
    const char* gAh = (const char*)Ahi  + ((size_t)(m0 + lrow) * K + col16 * 8) * 2;
    const char* gAl = (const char*)Alo  + ((size_t)(m0 + lrow) * K + col16 * 8) * 2;
    const char* gB  = (const char*)Bh16 + ((size_t)(n0 + lrow) * K + col16 * 8) * 2;

    auto load_stage = [&](int s){
        u32 base = sb + (u32)(s % 3) * STAGE_BYTES + swz;
        size_t ko = (size_t)s * 128;   // 64 fp16 = 128B along K
        #pragma unroll
        for (int i = 0; i < 4; i++){
            cp16(base +          i*4096u, gAh + ko + i*rstep);
            cp16(base + 16384u + i*4096u, gAl + ko + i*rstep);
            cp16(base + 32768u + i*4096u, gB  + ko + i*rstep);
        }
        cp_commit();
    };

    const u32 a_row = (u32)(wm + ((lane >> 3) & 1) * 8 + (lane & 7));
    const u32 a_kb  = (u32)((lane >> 4) * 16);
    const u32 b_row = (u32)(wn + (lane >> 4) * 8 + (lane & 7));
    const u32 b_kb  = (u32)(((lane >> 3) & 1) * 16);

    float acc[4][4][4];
    #pragma unroll
    for (int mi = 0; mi < 4; mi++)
        #pragma unroll
        for (int ni = 0; ni < 4; ni++)
            #pragma unroll
            for (int q = 0; q < 4; q++) acc[mi][ni][q] = 0.f;

    auto compute_stage = [&](u32 base){
        #pragma unroll
        for (int kk = 0; kk < 4; kk++){
            u32 ah[4][4], al[4][4], bb[2][4];
            #pragma unroll
            for (int mi = 0; mi < 4; mi++){
                u32 off = (a_row + mi*16u) * 128u + (u32)kk*32u + a_kb;
                off ^= (off >> 3) & 0x70;
                ldsm4(ah[mi], base + off);
                ldsm4(al[mi], base + 16384u + off);
            }
            #pragma unroll
            for (int nj = 0; nj < 2; nj++){
                u32 off = (b_row + nj*16u) * 128u + (u32)kk*32u + b_kb;
                off ^= (off >> 3) & 0x70;
                ldsm4(bb[nj], base + 32768u + off);
            }
            #pragma unroll
            for (int mi = 0; mi < 4; mi++)
                #pragma unroll
                for (int ni = 0; ni < 4; ni++){
                    const u32* pb = &bb[ni >> 1][(ni & 1) * 2];
                    hmma16(acc[mi][ni], ah[mi], pb[0], pb[1]);  // Ah*B
                    hmma16(acc[mi][ni], al[mi], pb[0], pb[1]);  // Al*B
                }
        }
    };

    const int NS = K >> 6;
    load_stage(0);
    load_stage(1);
    for (int s = 0; s < NS; s++){
        if (s + 1 < NS) cp_wait<1>(); else cp_wait<0>();
        __syncthreads();
        if (s + 2 < NS) load_stage(s + 2);
        compute_stage(sb + (u32)(s % 3) * STAGE_BYTES);
    }

    // epilogue
    #pragma unroll
    for (int mi = 0; mi < 4; mi++){
        #pragma unroll
        for (int ni = 0; ni < 4; ni++){
            const int n = n0 + wn + ni*8 + (lane & 3)*2;
            #pragma unroll
            for (int half = 0; half < 2; half++){
                const int m = m0 + wm + mi*16 + (lane >> 2) + half*8;
                const size_t idx = (size_t)m * N + n;
                float v0 = acc[mi][ni][half*2 + 0];
                float v1 = acc[mi][ni][half*2 + 1];
                if (EPI == TC_SILU){
                    v0 = v0 / (1.f + expf(-v0));
                    v1 = v1 / (1.f + expf(-v1));
                } else if (EPI == TC_ADDX){
                    v0 += aux0[idx]; v1 += aux0[idx + 1];
                } else if (EPI == TC_SIGM){
                    v0 = 1.f / (1.f + expf(-v0));
                    v1 = 1.f / (1.f + expf(-v1));
                } else if (EPI == TC_CVMIX){
                    v0 = aux0[idx]     + aux1[idx]     * v0;
                    v1 = aux0[idx + 1] + aux1[idx + 1] * v1;
                } else if (EPI == TC_RELU2){
                    float r0 = v0 > 0.f ? v0 : 0.f;
                    float r1 = v1 > 0.f ? v1 : 0.f;
                    v0 = r0 * r0; v1 = r1 * r1;
                    __half h0, l0, h1, l1;
                    split_f16(v0, h0, l0);
                    split_f16(v1, h1, l1);
                    __half2 hp; hp.x = h0; hp.y = h1;
                    __half2 lp; lp.x = l0; lp.y = l1;
                    *reinterpret_cast<__half2*>(Ch + idx) = hp;
                    *reinterpret_cast<__half2*>(Cl + idx) = lp;
                    continue;
                }
                float2 o; o.x = v0; o.y = v1;
                *reinterpret_cast<float2*>(C + idx) = o;
            }
        }
    }
}

// ---------------- weight transpose:  W[K,N] f32 -> T[N,K] fp16 ----------------
__global__ __launch_bounds__(256)
void wtrans16(const float* __restrict__ W, __half* __restrict__ Th, int K, int N)
{
    __shared__ float s[32][33];
    const int tx = threadIdx.x & 31, ty = threadIdx.x >> 5;  // 32x8
    const int n0 = blockIdx.x * 32, k0 = blockIdx.y * 32;
    #pragma unroll
    for (int r = 0; r < 32; r += 8)
        s[ty + r][tx] = W[(size_t)(k0 + ty + r) * N + n0 + tx];
    __syncthreads();
    #pragma unroll
    for (int r = 0; r < 32; r += 8){
        float v = s[tx][ty + r];
        Th[(size_t)(n0 + ty + r) * K + k0 + tx] = __float2half_rn(v);
    }
}

// ---------------- fused 5-way mix: all lerp outputs in one pass ----------------
// m_f = a[:,f*32:(f+1)*32] @ w2[f]; x_f = h + xx*(tm_maa[1+f] + m_f)
// f=0 -> xw (f32); f=1..4 -> (xk,xv,xr,xg) fp16 hi/lo
#define MIX_SM 163840
__global__ __launch_bounds__(256, 1)
void mix5_kernel(const float* __restrict__ a, const float* __restrict__ w2,
                 const float* __restrict__ tm_maa,
                 float* __restrict__ xw,
                 __half* __restrict__ xkh, __half* __restrict__ xkl,
                 __half* __restrict__ xvh, __half* __restrict__ xvl,
                 __half* __restrict__ xrh, __half* __restrict__ xrl,
                 __half* __restrict__ xgh, __half* __restrict__ xgl)
{
    extern __shared__ float sm[];
    float* As = sm;            // [128][160]
    float* Ws = sm + 20480;    // [160][128]
    const int tid = threadIdx.x;
    const int c0 = blockIdx.x * 128;
    const int m0 = blockIdx.y * 128;
    const int tcol = tid & 15, trow = tid >> 4;

    for (int i = tid; i < 128 * 40; i += 256){
        int row = i / 40, c4 = i % 40;
        *reinterpret_cast<float4*>(As + row*160 + c4*4) =
            *reinterpret_cast<const float4*>(a + (size_t)(m0 + row)*160 + c4*4);
    }
    for (int i = tid; i < 160 * 32; i += 256){
        int row = i / 32, c4 = i % 32;
        *reinterpret_cast<float4*>(Ws + row*128 + c4*4) =
            *reinterpret_cast<const float4*>(w2 + (size_t)row*Cc + c0 + c4*4);
    }
    __syncthreads();

    __half* oh[4] = { xkh, xvh, xrh, xgh };
    __half* ol[4] = { xkl, xvl, xrl, xgl };

    #pragma unroll 1
    for (int f = 0; f < 5; f++){
        float acc[8][8];
        #pragma unroll
        for (int i = 0; i < 8; i++)
            #pragma unroll
            for (int j = 0; j < 8; j++) acc[i][j] = 0.f;
        const int rb = f * 32;
        #pragma unroll 4
        for (int d = 0; d < 32; d++){
            float regM[8], regN[8];
            #pragma unroll
            for (int i = 0; i < 8; i++) regM[i] = As[(trow*8 + i)*160 + rb + d];
            *(float4*)&regN[0] = *(const float4*)&Ws[(rb + d)*128 + tcol*8];
            *(float4*)&regN[4] = *(const float4*)&Ws[(rb + d)*128 + tcol*8 + 4];
            #pragma unroll
            for (int i = 0; i < 8; i++)
                #pragma unroll
                for (int j = 0; j < 8; j++)
                    acc[i][j] = fmaf(regM[i], regN[j], acc[i][j]);
        }
        const float* maa = tm_maa + (size_t)(1 + f) * Cc + c0 + tcol*8;
        #pragma unroll
        for (int i = 0; i < 8; i++){
            const int m = m0 + trow*8 + i;
            const size_t idx = (size_t)m * Cc + c0 + tcol*8;
            #pragma unroll
            for (int j = 0; j < 8; j += 2){
                float h0 = g_h[idx + j],     xx0 = g_xx[idx + j];
                float h1 = g_h[idx + j + 1], xx1 = g_xx[idx + j + 1];
                float v0 = h0 + xx0 * (maa[j]     + acc[i][j]);
                float v1 = h1 + xx1 * (maa[j + 1] + acc[i][j + 1]);
                if (f == 0){
                    xw[idx + j] = v0; xw[idx + j + 1] = v1;
                } else {
                    __half a0, b0, a1, b1;
                    split_f16(v0, a0, b0);
                    split_f16(v1, a1, b1);
                    __half2 hp; hp.x = a0; hp.y = a1;
                    __half2 lp; lp.x = b0; lp.y = b1;
                    *reinterpret_cast<__half2*>(oh[f-1] + idx + j) = hp;
                    *reinterpret_cast<__half2*>(ol[f-1] + idx + j) = lp;
                }
            }
        }
    }
}

// ---------------- small SIMT fp32 GEMM (maa / td) ----------------
#define BMt 128
#define BNt 128
#define BKt 8
#define TMt 8
#define TNt 8
enum { E_TANH=1, E_ADDVEC=5 };

template<int EPI>
__global__ __launch_bounds__(256)
void gemm_f32(const float* __restrict__ A, const float* __restrict__ Bm,
              float* __restrict__ Cm,
              int M, int N, int K, int lda, int ldc,
              const float* __restrict__ aux0)
{
    __shared__ float As[BKt][BMt];
    __shared__ float Bs[BKt][BNt];
    const int bm = blockIdx.y * BMt;
    const int bn = blockIdx.x * BNt;
    const int tid = threadIdx.x;
    const int tcol = tid & 15;
    const int trow = tid >> 4;
    const int a_row = tid >> 1;
    const int a_col = (tid & 1) * 4;
    const int b_row = tid >> 5;
    const int b_col = (tid & 31) * 4;
    const bool nfull = (bn + BNt) <= N;

    float acc[TMt][TNt];
    #pragma unroll
    for (int i = 0; i < TMt; i++)
        #pragma unroll
        for (int j = 0; j < TNt; j++) acc[i][j] = 0.f;

    for (int k0 = 0; k0 < K; k0 += BKt) {
        float4 av = *reinterpret_cast<const float4*>(A + (size_t)(bm + a_row)*lda + k0 + a_col);
        As[a_col+0][a_row] = av.x;
        As[a_col+1][a_row] = av.y;
        As[a_col+2][a_row] = av.z;
        As[a_col+3][a_row] = av.w;
        if (nfull) {
            *reinterpret_cast<float4*>(&Bs[b_row][b_col]) =
                *reinterpret_cast<const float4*>(Bm + (size_t)(k0 + b_row)*N + bn + b_col);
        } else {
            #pragma unroll
            for (int q = 0; q < 4; q++) {
                int n = bn + b_col + q;
                Bs[b_row][b_col+q] = (n < N) ? Bm[(size_t)(k0 + b_row)*N + n] : 0.f;
            }
        }
        __syncthreads();
        #pragma unroll
        for (int kk = 0; kk < BKt; kk++) {
            float regM[TMt], regN[TNt];
            *(float4*)&regM[0] = *(const float4*)&As[kk][trow*TMt];
            *(float4*)&regM[4] = *(const float4*)&As[kk][trow*TMt + 4];
            *(float4*)&regN[0] = *(const float4*)&Bs[kk][tcol*TNt];
            *(float4*)&regN[4] = *(const float4*)&Bs[kk][tcol*TNt + 4];
            #pragma unroll
            for (int i = 0; i < TMt; i++)
                #pragma unroll
                for (int j = 0; j < TNt; j++)
                    acc[i][j] = fmaf(regM[i], regN[j], acc[i][j]);
        }
        __syncthreads();
    }

    #pragma unroll
    for (int i = 0; i < TMt; i++) {
        int m = bm + trow*TMt + i;
        #pragma unroll
        for (int j = 0; j < TNt; j++) {
            int n = bn + tcol*TNt + j;
            if (n >= N) continue;
            float v = acc[i][j];
            if (EPI == E_TANH)        v = tanhf(v);
            else if (EPI == E_ADDVEC) v = aux0[n] + v;
            Cm[(size_t)m * ldc + n] = v;
        }
    }
}

// ---------------- LayerNorm over C per token ----------------
__global__ __launch_bounds__(256)
void ln_kernel(const float* __restrict__ x, const float* __restrict__ w,
               const float* __restrict__ b, float* __restrict__ out, float eps)
{
    const size_t base = (size_t)blockIdx.x * Cc;
    float sum = 0.f, sq = 0.f;
    for (int c = threadIdx.x; c < Cc; c += 256) { float v = x[base + c]; sum += v; sq += v*v; }
    #pragma unroll
    for (int o = 16; o; o >>= 1) {
        sum += __shfl_xor_sync(0xffffffffu, sum, o);
        sq  += __shfl_xor_sync(0xffffffffu, sq,  o);
    }
    __shared__ float s1[8], s2[8];
    int wid = threadIdx.x >> 5, lane = threadIdx.x & 31;
    if (!lane) { s1[wid] = sum; s2[wid] = sq; }
    __syncthreads();
    if (threadIdx.x == 0) {
        float ts = 0.f, tq = 0.f;
        #pragma unroll
        for (int i = 0; i < 8; i++) { ts += s1[i]; tq += s2[i]; }
        float m = ts / (float)Cc;
        float var = tq / (float)Cc - m*m;
        s1[0] = m; s2[0] = rsqrtf(var + eps);
    }
    __syncthreads();
    float m = s1[0], rstd = s2[0];
    for (int c = threadIdx.x; c < Cc; c += 256)
        out[base + c] = (x[base + c] - m) * rstd * w[c] + b[c];
}

// ---------------- token shift + first mix (time mixing) ----------------
__global__ void shift1_kernel(const float* __restrict__ tm_maa)
{
    size_t idx = (size_t)blockIdx.x * 256 + threadIdx.x;
    int c  = (int)(idx % Cc);
    int tt = (int)(idx / Cc);
    int t  = tt % Tt;
    float hv = g_h[idx];
    float hp = t ? g_h[idx - Cc] : 0.f;
    float d = hp - hv;
    g_xx[idx]  = d;
    g_xxx[idx] = hv + d * tm_maa[c];
}

// ---------------- token shift (channel mixing) -> fp16 hi/lo ----------------
__global__ void shift2_kernel(const float* __restrict__ cm_maa)
{
    size_t idx = (size_t)blockIdx.x * 256 + threadIdx.x;
    int c  = (int)(idx % Cc);
    int tt = (int)(idx / Cc);
    int t  = tt % Tt;
    float hv = g_h[idx];
    float hp = t ? g_h[idx - Cc] : 0.f;
    float d = hp - hv;
    float a = hv + d * cm_maa[c];
    float b = hv + d * cm_maa[Cc + c];
    __half hb, lb;
    split_f16(a, hb, lb); g_xk2_h[idx] = hb; g_xk2_l[idx] = lb;
    split_f16(b, hb, lb); g_xr2_h[idx] = hb; g_xr2_l[idx] = lb;
}

// ---------------- WKV6 recurrent scan (1-step register prefetch) ----------------
__global__ __launch_bounds__(128)
void wkv6_kernel(const float* __restrict__ u)
{
    const int bh = blockIdx.x;
    const int b  = bh >> 5;
    const int hh = bh & 31;
    const int tid = threadIdx.x;
    const int j = tid & 63;
    const int ibase = (tid >> 6) * 32;
    __shared__ float4 sv[64];
    __shared__ float  yp[128];
    float S[32];
    #pragma unroll
    for (int i = 0; i < 32; i++) S[i] = 0.f;
    size_t off = (size_t)b * Tt * Cc + (size_t)hh * Nn;
    float ur = (tid < 64) ? u[hh * Nn + j] : 0.f;

    float rn = 0.f, kn = 0.f, wn = 0.f, vn;
    if (tid < 64){ rn = g_r[off + j]; kn = g_k[off + j]; wn = g_w[off + j]; }
    vn = g_v[off + j];

    for (int t = 0; t < Tt; t++) {
        float rc = rn, kc = kn, wc = wn, vc = vn;
        size_t offn = off + Cc;
        if (t + 1 < Tt){
            if (tid < 64){ rn = g_r[offn + j]; kn = g_k[offn + j]; wn = g_w[offn + j]; }
            vn = g_v[offn + j];
        }
        if (tid < 64)
            sv[j] = make_float4(rc, kc, ur * kc, expf(-expf(wc)));
        __syncthreads();
        float acc = 0.f;
        #pragma unroll
        for (int ii = 0; ii < 32; ii++) {
            float4 q = sv[ibase + ii];
            acc   = fmaf(q.x, fmaf(q.z, vc, S[ii]), acc);
            S[ii] = fmaf(S[ii], q.w, q.y * vc);
        }
        yp[tid] = acc;
        __syncthreads();
        if (tid < 64) g_y[off + j] = yp[j] + yp[64 + j];
        off = offn;
    }
}

// ---------------- GroupNorm(H) * silu-gate -> att fp16 hi/lo ----------------
__global__ __launch_bounds__(256)
void gnsilu_kernel(const float* __restrict__ lnw, const float* __restrict__ lnb)
{
    int gw  = blockIdx.x * 8 + (threadIdx.x >> 5);
    int lane = threadIdx.x & 31;
    int t  = gw >> 5;
    int hh = gw & 31;
    size_t base = (size_t)t * Cc + (size_t)hh * Nn;
    float y0 = g_y[base + lane], y1 = g_y[base + 32 + lane];
    float sum = y0 + y1, sq = y0*y0 + y1*y1;
    #pragma unroll
    for (int o = 16; o; o >>= 1) {
        sum += __shfl_xor_sync(0xffffffffu, sum, o);
        sq  += __shfl_xor_sync(0xffffffffu, sq,  o);
    }
    float m = sum * (1.f / 64.f);
    float rstd = rsqrtf(sq * (1.f / 64.f) - m*m + 6.4e-4f);
    int ch = hh * Nn + lane;
    float gv0 = g_g[base + lane], gv1 = g_g[base + 32 + lane];
    float o0 = ((y0 - m) * rstd * lnw[ch]      + lnb[ch])      * gv0;
    float o1 = ((y1 - m) * rstd * lnw[ch + 32] + lnb[ch + 32]) * gv1;
    __half hb, lb;
    split_f16(o0, hb, lb); g_att_h[base + lane]      = hb; g_att_l[base + lane]      = lb;
    split_f16(o1, hb, lb); g_att_h[base + 32 + lane] = hb; g_att_l[base + 32 + lane] = lb;
}

// ---------------- host launch ----------------
static inline dim3 ggrid(int M, int N)  { return dim3((N + BNt - 1) / BNt, M / BMt); }
static inline dim3 mmagrid(int M, int N){ return dim3(N / 128, M / 128); }

#define SYMADDR(v, s) cudaGetSymbolAddress((void**)&v, s)

extern "C" void kernel_launch(void* const* d_in, const int* in_sizes, int n_in,
                              void* d_out, int out_size)
{
    (void)in_sizes; (void)n_in; (void)out_size;
    const float* x          = (const float*)d_in[0];
    const float* ln1_w      = (const float*)d_in[1];
    const float* ln1_b      = (const float*)d_in[2];
    const float* ln2_w      = (const float*)d_in[3];
    const float* ln2_b      = (const float*)d_in[4];
    const float* tm_maa     = (const float*)d_in[5];
    const float* maa_w1     = (const float*)d_in[6];
    const float* maa_w2     = (const float*)d_in[7];
    const float* time_decay = (const float*)d_in[8];
    const float* td_w1      = (const float*)d_in[9];
    const float* td_w2      = (const float*)d_in[10];
    const float* time_faaaa = (const float*)d_in[11];
    const float* Wr  = (const float*)d_in[12];
    const float* Wk  = (const float*)d_in[13];
    const float* Wv  = (const float*)d_in[14];
    const float* Wg  = (const float*)d_in[15];
    const float* Wo  = (const float*)d_in[16];
    const float* lnx_w = (const float*)d_in[17];
    const float* lnx_b = (const float*)d_in[18];
    const float* cm_maa = (const float*)d_in[19];
    const float* Wck = (const float*)d_in[20];
    const float* Wcr = (const float*)d_in[21];
    const float* Wcv = (const float*)d_in[22];
    float* out = (float*)d_out;

    float *ph, *pxx, *pxxx, *pa, *pxw, *pr, *pk, *pv, *pg, *pw, *pwt, *py, *px1, *psig;
    SYMADDR(ph, g_h);   SYMADDR(pxx, g_xx); SYMADDR(pxxx, g_xxx); SYMADDR(pa, g_a);
    SYMADDR(pxw, g_xw); SYMADDR(pr, g_r);   SYMADDR(pk, g_k);     SYMADDR(pv, g_v);
    SYMADDR(pg, g_g);   SYMADDR(pw, g_w);   SYMADDR(pwt, g_wt);   SYMADDR(py, g_y);
    SYMADDR(px1, g_x1); SYMADDR(psig, g_sig);

    __half *xkh,*xkl,*xvh,*xvl,*xrh,*xrl,*xgh,*xgl,*atth,*attl,*xk2h,*xk2l,*xr2h,*xr2l,*kfh,*kfl;
    SYMADDR(xkh, g_xk_h); SYMADDR(xkl, g_xk_l);
    SYMADDR(xvh, g_xv_h); SYMADDR(xvl, g_xv_l);
    SYMADDR(xrh, g_xr_h); SYMADDR(xrl, g_xr_l);
    SYMADDR(xgh, g_xg_h); SYMADDR(xgl, g_xg_l);
    SYMADDR(atth, g_att_h); SYMADDR(attl, g_att_l);
    SYMADDR(xk2h, g_xk2_h); SYMADDR(xk2l, g_xk2_l);
    SYMADDR(xr2h, g_xr2_h); SYMADDR(xr2l, g_xr2_l);
    SYMADDR(kfh, g_kf_h);   SYMADDR(kfl, g_kf_l);

    __half *wr16,*wk16,*wv16,*wg16,*wo16,*wcr16,*wck16,*wcv16;
    SYMADDR(wr16, g_Wr16);   SYMADDR(wk16, g_Wk16);
    SYMADDR(wv16, g_Wv16);   SYMADDR(wg16, g_Wg16);
    SYMADDR(wo16, g_Wo16);   SYMADDR(wcr16, g_Wcr16);
    SYMADDR(wck16, g_Wck16); SYMADDR(wcv16, g_Wcv16);

    cudaFuncSetAttribute(gemm_mma<TC_NONE>,  cudaFuncAttributeMaxDynamicSharedMemorySize, SM_MMA_TOTAL);
    cudaFuncSetAttribute(gemm_mma<TC_SILU>,  cudaFuncAttributeMaxDynamicSharedMemorySize, SM_MMA_TOTAL);
    cudaFuncSetAttribute(gemm_mma<TC_ADDX>,  cudaFuncAttributeMaxDynamicSharedMemorySize, SM_MMA_TOTAL);
    cudaFuncSetAttribute(gemm_mma<TC_RELU2>, cudaFuncAttributeMaxDynamicSharedMemorySize, SM_MMA_TOTAL);
    cudaFuncSetAttribute(gemm_mma<TC_SIGM>,  cudaFuncAttributeMaxDynamicSharedMemorySize, SM_MMA_TOTAL);
    cudaFuncSetAttribute(gemm_mma<TC_CVMIX>, cudaFuncAttributeMaxDynamicSharedMemorySize, SM_MMA_TOTAL);
    cudaFuncSetAttribute(mix5_kernel, cudaFuncAttributeMaxDynamicSharedMemorySize, MIX_SM);

    const int ELT_BLOCKS = (MM * Cc) / 256;

    // ---- time mixing (ordered so launch #6 is a gemm_mma for ncu) ----
    ln_kernel<<<MM, 256>>>(x, ln1_w, ln1_b, ph, 1e-5f);                      // 1
    shift1_kernel<<<ELT_BLOCKS, 256>>>(tm_maa);                              // 2
    gemm_f32<E_TANH><<<ggrid(MM, 160), 256>>>(pxxx, maa_w1, pa,
                                              MM, 160, Cc, Cc, 160, nullptr);// 3
    mix5_kernel<<<dim3(Cc/128, MM/128), 256, MIX_SM>>>(pa, maa_w2, tm_maa, pxw,
        xkh, xkl, xvh, xvl, xrh, xrl, xgh, xgl);                             // 4
    wtrans16<<<dim3(Cc/32, Cc/32), 256>>>(Wr, wr16, Cc, Cc);                 // 5
    gemm_mma<TC_NONE><<<mmagrid(MM, Cc), 256, SM_MMA_TOTAL>>>(xrh, xrl, wr16, pr,
        MM, Cc, Cc, nullptr, nullptr, nullptr, nullptr);                     // 6 <- profiled
    wtrans16<<<dim3(Cc/32, Cc/32), 256>>>(Wk,  wk16,  Cc, Cc);
    wtrans16<<<dim3(Cc/32, Cc/32), 256>>>(Wv,  wv16,  Cc, Cc);
    wtrans16<<<dim3(Cc/32, Cc/32), 256>>>(Wg,  wg16,  Cc, Cc);
    wtrans16<<<dim3(Cc/32, Cc/32), 256>>>(Wo,  wo16,  Cc, Cc);
    wtrans16<<<dim3(Cc/32, Cc/32), 256>>>(Wcr, wcr16, Cc, Cc);
    wtrans16<<<dim3(Ff/32, Cc/32), 256>>>(Wck, wck16, Cc, Ff);
    wtrans16<<<dim3(Cc/32, Ff/32), 256>>>(Wcv, wcv16, Ff, Cc);
    gemm_mma<TC_NONE><<<mmagrid(MM, Cc), 256, SM_MMA_TOTAL>>>(xkh, xkl, wk16, pk,
        MM, Cc, Cc, nullptr, nullptr, nullptr, nullptr);
    gemm_mma<TC_NONE><<<mmagrid(MM, Cc), 256, SM_MMA_TOTAL>>>(xvh, xvl, wv16, pv,
        MM, Cc, Cc, nullptr, nullptr, nullptr, nullptr);
    gemm_mma<TC_SILU><<<mmagrid(MM, Cc), 256, SM_MMA_TOTAL>>>(xgh, xgl, wg16, pg,
        MM, Cc, Cc, nullptr, nullptr, nullptr, nullptr);
    gemm_f32<E_TANH><<<ggrid(MM, 64), 256>>>(pxw, td_w1, pwt,
                                             MM, 64, Cc, Cc, 64, nullptr);
    gemm_f32<E_ADDVEC><<<ggrid(MM, Cc), 256>>>(pwt, td_w2, pw,
                                               MM, Cc, 64, 64, Cc, time_decay);
    wkv6_kernel<<<Bq * Hh, 128>>>(time_faaaa);
    gnsilu_kernel<<<MM * Hh / 8, 256>>>(lnx_w, lnx_b);
    gemm_mma<TC_ADDX><<<mmagrid(MM, Cc), 256, SM_MMA_TOTAL>>>(atth, attl, wo16, px1,
        MM, Cc, Cc, x, nullptr, nullptr, nullptr);

    // ---- channel mixing ----
    ln_kernel<<<MM, 256>>>(px1, ln2_w, ln2_b, ph, 1e-5f);
    shift2_kernel<<<ELT_BLOCKS, 256>>>(cm_maa);
    gemm_mma<TC_RELU2><<<mmagrid(MM, Ff), 256, SM_MMA_TOTAL>>>(xk2h, xk2l, wck16, nullptr,
        MM, Ff, Cc, nullptr, nullptr, kfh, kfl);
    gemm_mma<TC_SIGM><<<mmagrid(MM, Cc), 256, SM_MMA_TOTAL>>>(xr2h, xr2l, wcr16, psig,
        MM, Cc, Cc, nullptr, nullptr, nullptr, nullptr);
    gemm_mma<TC_CVMIX><<<mmagrid(MM, Cc), 256, SM_MMA_TOTAL>>>(kfh, kfl, wcv16, out,
        MM, Cc, Ff, px1, psig, nullptr, nullptr);
}

// round 5
// speedup vs baseline: 4.2532x; 1.2682x over previous
#include <cuda_runtime.h>
#include <cuda_fp16.h>
#include <math.h>

// ---------------- problem constants ----------------
#define Bq 2
#define Tt 2048
#define Cc 2048
#define Hh 32
#define Nn 64
#define Ff 7168
#define MM (Bq*Tt)          // 4096 tokens

typedef unsigned int u32;
typedef unsigned long long u64;

// ---------------- device scratch (no allocs allowed) ----------------
__device__ float g_h  [(size_t)MM*Cc];
__device__ float g_xx [(size_t)MM*Cc];
__device__ float g_a  [(size_t)MM*160];
__device__ float g_w  [(size_t)MM*Cc];
__device__ float g_wt [(size_t)MM*64];
__device__ float g_y  [(size_t)MM*Cc];
__device__ float g_x1 [(size_t)MM*Cc];
__device__ float g_sig[(size_t)MM*Cc];
__device__ float g_out4[(size_t)4*MM*Cc];   // r,k,v,g

// fp16 hi/lo activation splits
__device__ __align__(16) __half g_xxx_h[(size_t)MM*Cc], g_xxx_l[(size_t)MM*Cc];
__device__ __align__(16) __half g_xw_h [(size_t)MM*Cc], g_xw_l [(size_t)MM*Cc];
__device__ __align__(16) __half g_act4_h[(size_t)4*MM*Cc], g_act4_l[(size_t)4*MM*Cc]; // xr,xk,xv,xg
__device__ __align__(16) __half g_att_h[(size_t)MM*Cc], g_att_l[(size_t)MM*Cc];
__device__ __align__(16) __half g_xk2_h[(size_t)MM*Cc], g_xk2_l[(size_t)MM*Cc];
__device__ __align__(16) __half g_xr2_h[(size_t)MM*Cc], g_xr2_l[(size_t)MM*Cc];
__device__ __align__(16) __half g_kf_h[(size_t)MM*Ff],  g_kf_l[(size_t)MM*Ff];

// fp16 transposed weights ([N,K] K-major)
__device__ __align__(16) __half g_W4_16 [(size_t)4*Cc*Cc];  // Wr,Wk,Wv,Wg
__device__ __align__(16) __half g_Wo16  [(size_t)Cc*Cc];
__device__ __align__(16) __half g_Wcr16 [(size_t)Cc*Cc];
__device__ __align__(16) __half g_Wck16 [(size_t)Cc*Ff];    // [7168,2048]
__device__ __align__(16) __half g_Wcv16 [(size_t)Ff*Cc];    // [2048,7168]
__device__ __align__(16) __half g_maaw1T[(size_t)256*Cc];   // padded [256,2048]
__device__ __align__(16) __half g_tdw1T [(size_t)128*Cc];   // padded [128,2048]

// ---------------- PTX helpers (baseline PTX; no sm_103a-only features) ----
__device__ __forceinline__ u32 smem_u32(const void* p){
    u32 a;
    asm("{ .reg .u64 t; cvta.to.shared.u64 t, %1; cvt.u32.u64 %0, t; }" : "=r"(a) : "l"(p));
    return a;
}
__device__ __forceinline__ void cp16(u32 s, const void* g){
    asm volatile("cp.async.cg.shared.global [%0], [%1], 16;" :: "r"(s), "l"(g) : "memory");
}
__device__ __forceinline__ void cp_commit(){
    asm volatile("cp.async.commit_group;" ::: "memory");
}
template<int NG> __device__ __forceinline__ void cp_wait(){
    asm volatile("cp.async.wait_group %0;" :: "n"(NG) : "memory");
}
__device__ __forceinline__ void ldsm4(u32* r, u32 a){
    asm volatile("ldmatrix.sync.aligned.m8n8.x4.shared.b16 {%0,%1,%2,%3}, [%4];"
        : "=r"(r[0]), "=r"(r[1]), "=r"(r[2]), "=r"(r[3]) : "r"(a));
}
__device__ __forceinline__ void hmma16(float* c, const u32* a, u32 b0, u32 b1){
    asm volatile(
        "mma.sync.aligned.m16n8k16.row.col.f32.f16.f16.f32 "
        "{%0,%1,%2,%3},{%4,%5,%6,%7},{%8,%9},{%0,%1,%2,%3};"
        : "+f"(c[0]), "+f"(c[1]), "+f"(c[2]), "+f"(c[3])
        : "r"(a[0]), "r"(a[1]), "r"(a[2]), "r"(a[3]), "r"(b0), "r"(b1));
}
__device__ __forceinline__ void split_f16(float v, __half& h, __half& l){
    h = __float2half_rn(v);
    l = __float2half_rn(v - __half2float(h));
}

// ---------------- split-fp16 HMMA GEMM body (2 terms) ----------------
#define STAGE_BYTES 49152u    // Ah(16K) Al(16K) B(16K)
#define SM_MMA_TOTAL (3*49152)

enum { TC_NONE=0, TC_SILU, TC_ADDX, TC_RELU2, TC_SIGM, TC_CVMIX, TC_TANH };

template<int EPI>
__device__ __forceinline__
void mma_body(const __half* __restrict__ Ahi, const __half* __restrict__ Alo,
              const __half* __restrict__ Bh16,
              float* __restrict__ C, int M, int N, int K, int ldc, int nvalid,
              const float* __restrict__ aux0, const float* __restrict__ aux1,
              __half* __restrict__ Ch, __half* __restrict__ Cl)
{
    extern __shared__ char sm_dyn[];
    const u32 sb = smem_u32(sm_dyn);
    const int tid  = threadIdx.x;
    const int wid  = tid >> 5;
    const int lane = tid & 31;
    const int m0 = blockIdx.y * 128;
    const int n0 = blockIdx.x * 128;
    const int wm = (wid & 1) * 64;
    const int wn = (wid >> 1) * 32;

    const int col16 = tid & 7;
    const int lrow  = tid >> 3;
    const u32 soff  = (u32)(lrow * 128 + col16 * 16);
    const u32 swz   = soff ^ ((soff >> 3) & 0x70);
    const size_t rstep = (size_t)32 * K * 2;
    const char* gAh = (const char*)Ahi  + ((size_t)(m0 + lrow) * K + col16 * 8) * 2;
    const char* gAl = (const char*)Alo  + ((size_t)(m0 + lrow) * K + col16 * 8) * 2;
    const char* gB  = (const char*)Bh16 + ((size_t)(n0 + lrow) * K + col16 * 8) * 2;

    auto load_stage = [&](int s){
        u32 base = sb + (u32)(s % 3) * STAGE_BYTES + swz;
        size_t ko = (size_t)s * 128;   // 64 fp16 = 128B along K
        #pragma unroll
        for (int i = 0; i < 4; i++){
            cp16(base +          i*4096u, gAh + ko + i*rstep);
            cp16(base + 16384u + i*4096u, gAl + ko + i*rstep);
            cp16(base + 32768u + i*4096u, gB  + ko + i*rstep);
        }
        cp_commit();
    };

    const u32 a_row = (u32)(wm + ((lane >> 3) & 1) * 8 + (lane & 7));
    const u32 a_kb  = (u32)((lane >> 4) * 16);
    const u32 b_row = (u32)(wn + (lane >> 4) * 8 + (lane & 7));
    const u32 b_kb  = (u32)(((lane >> 3) & 1) * 16);

    float acc[4][4][4];
    #pragma unroll
    for (int mi = 0; mi < 4; mi++)
        #pragma unroll
        for (int ni = 0; ni < 4; ni++)
            #pragma unroll
            for (int q = 0; q < 4; q++) acc[mi][ni][q] = 0.f;

    auto compute_stage = [&](u32 base){
        #pragma unroll
        for (int kk = 0; kk < 4; kk++){
            u32 ah[4][4], al[4][4], bb[2][4];
            #pragma unroll
            for (int mi = 0; mi < 4; mi++){
                u32 off = (a_row + mi*16u) * 128u + (u32)kk*32u + a_kb;
                off ^= (off >> 3) & 0x70;
                ldsm4(ah[mi], base + off);
                ldsm4(al[mi], base + 16384u + off);
            }
            #pragma unroll
            for (int nj = 0; nj < 2; nj++){
                u32 off = (b_row + nj*16u) * 128u + (u32)kk*32u + b_kb;
                off ^= (off >> 3) & 0x70;
                ldsm4(bb[nj], base + 32768u + off);
            }
            #pragma unroll
            for (int mi = 0; mi < 4; mi++)
                #pragma unroll
                for (int ni = 0; ni < 4; ni++){
                    const u32* pb = &bb[ni >> 1][(ni & 1) * 2];
                    hmma16(acc[mi][ni], ah[mi], pb[0], pb[1]);
                    hmma16(acc[mi][ni], al[mi], pb[0], pb[1]);
                }
        }
    };

    const int NS = K >> 6;
    load_stage(0);
    load_stage(1);
    for (int s = 0; s < NS; s++){
        if (s + 1 < NS) cp_wait<1>(); else cp_wait<0>();
        __syncthreads();
        if (s + 2 < NS) load_stage(s + 2);
        compute_stage(sb + (u32)(s % 3) * STAGE_BYTES);
    }

    #pragma unroll
    for (int mi = 0; mi < 4; mi++){
        #pragma unroll
        for (int ni = 0; ni < 4; ni++){
            const int n = n0 + wn + ni*8 + (lane & 3)*2;
            if (n >= nvalid) continue;
            #pragma unroll
            for (int half = 0; half < 2; half++){
                const int m = m0 + wm + mi*16 + (lane >> 2) + half*8;
                const size_t idx = (size_t)m * ldc + n;
                float v0 = acc[mi][ni][half*2 + 0];
                float v1 = acc[mi][ni][half*2 + 1];
                if (EPI == TC_SILU){
                    v0 = v0 / (1.f + expf(-v0));
                    v1 = v1 / (1.f + expf(-v1));
                } else if (EPI == TC_TANH){
                    v0 = tanhf(v0); v1 = tanhf(v1);
                } else if (EPI == TC_ADDX){
                    v0 += aux0[idx]; v1 += aux0[idx + 1];
                } else if (EPI == TC_SIGM){
                    v0 = 1.f / (1.f + expf(-v0));
                    v1 = 1.f / (1.f + expf(-v1));
                } else if (EPI == TC_CVMIX){
                    v0 = aux0[idx]     + aux1[idx]     * v0;
                    v1 = aux0[idx + 1] + aux1[idx + 1] * v1;
                } else if (EPI == TC_RELU2){
                    float r0 = v0 > 0.f ? v0 : 0.f;
                    float r1 = v1 > 0.f ? v1 : 0.f;
                    v0 = r0 * r0; v1 = r1 * r1;
                    __half h0, l0, h1, l1;
                    split_f16(v0, h0, l0);
                    split_f16(v1, h1, l1);
                    __half2 hp; hp.x = h0; hp.y = h1;
                    __half2 lp; lp.x = l0; lp.y = l1;
                    *reinterpret_cast<__half2*>(Ch + idx) = hp;
                    *reinterpret_cast<__half2*>(Cl + idx) = lp;
                    continue;
                }
                float2 o; o.x = v0; o.y = v1;
                *reinterpret_cast<float2*>(C + idx) = o;
            }
        }
    }
}

template<int EPI>
__global__ __launch_bounds__(256, 1)
void gemm_mma(const __half* __restrict__ Ahi, const __half* __restrict__ Alo,
              const __half* __restrict__ Bh16,
              float* __restrict__ C, int M, int N, int K, int ldc, int nvalid,
              const float* __restrict__ aux0, const float* __restrict__ aux1,
              __half* __restrict__ Ch, __half* __restrict__ Cl)
{
    mma_body<EPI>(Ahi, Alo, Bh16, C, M, N, K, ldc, nvalid, aux0, aux1, Ch, Cl);
}

// merged r/k/v/g GEMM: z selects operand set; z==3 (g) applies silu
__global__ __launch_bounds__(256, 1)
void gemm_rkvg(const __half* __restrict__ A4h, const __half* __restrict__ A4l,
               const __half* __restrict__ W4, float* __restrict__ C4)
{
    const int z = blockIdx.z;
    const size_t ao = (size_t)z * MM * Cc;
    const size_t wo = (size_t)z * Cc * Cc;
    if (z == 3)
        mma_body<TC_SILU>(A4h + ao, A4l + ao, W4 + wo, C4 + ao, MM, Cc, Cc, Cc, Cc,
                          nullptr, nullptr, nullptr, nullptr);
    else
        mma_body<TC_NONE>(A4h + ao, A4l + ao, W4 + wo, C4 + ao, MM, Cc, Cc, Cc, Cc,
                          nullptr, nullptr, nullptr, nullptr);
}

// ---------------- weight transposes ----------------
// W[K,N] f32 -> T[N,K] fp16
__global__ __launch_bounds__(256)
void wtrans16(const float* __restrict__ W, __half* __restrict__ Th, int K, int N)
{
    __shared__ float s[32][33];
    const int tx = threadIdx.x & 31, ty = threadIdx.x >> 5;
    const int n0 = blockIdx.x * 32, k0 = blockIdx.y * 32;
    #pragma unroll
    for (int r = 0; r < 32; r += 8)
        s[ty + r][tx] = W[(size_t)(k0 + ty + r) * N + n0 + tx];
    __syncthreads();
    #pragma unroll
    for (int r = 0; r < 32; r += 8)
        Th[(size_t)(n0 + ty + r) * K + k0 + tx] = __float2half_rn(s[tx][ty + r]);
}

// padded variant: rows n >= N read as 0 (grid.x = Npad/32)
__global__ __launch_bounds__(256)
void wtrans16p(const float* __restrict__ W, __half* __restrict__ Th, int K, int N)
{
    __shared__ float s[32][33];
    const int tx = threadIdx.x & 31, ty = threadIdx.x >> 5;
    const int n0 = blockIdx.x * 32, k0 = blockIdx.y * 32;
    #pragma unroll
    for (int r = 0; r < 32; r += 8){
        int n = n0 + tx;
        s[ty + r][tx] = (n < N) ? W[(size_t)(k0 + ty + r) * N + n] : 0.f;
    }
    __syncthreads();
    #pragma unroll
    for (int r = 0; r < 32; r += 8)
        Th[(size_t)(n0 + ty + r) * K + k0 + tx] = __float2half_rn(s[tx][ty + r]);
}

// merged 6x square transpose (Wr,Wk,Wv,Wg -> W4; Wo; Wcr)
__global__ __launch_bounds__(256)
void wtrans6(const float* __restrict__ W0, const float* __restrict__ W1,
             const float* __restrict__ W2, const float* __restrict__ W3,
             const float* __restrict__ W4w, const float* __restrict__ W5,
             __half* __restrict__ T4, __half* __restrict__ To, __half* __restrict__ Tcr)
{
    __shared__ float s[32][33];
    const int z = blockIdx.z;
    const float* W = (z==0)?W0:(z==1)?W1:(z==2)?W2:(z==3)?W3:(z==4)?W4w:W5;
    __half* T = (z < 4) ? (T4 + (size_t)z * Cc * Cc) : (z == 4 ? To : Tcr);
    const int tx = threadIdx.x & 31, ty = threadIdx.x >> 5;
    const int n0 = blockIdx.x * 32, k0 = blockIdx.y * 32;
    #pragma unroll
    for (int r = 0; r < 32; r += 8)
        s[ty + r][tx] = W[(size_t)(k0 + ty + r) * Cc + n0 + tx];
    __syncthreads();
    #pragma unroll
    for (int r = 0; r < 32; r += 8)
        T[(size_t)(n0 + ty + r) * Cc + k0 + tx] = __float2half_rn(s[tx][ty + r]);
}

// ---------------- fused 5-way mix, grid.z = f ----------------
// m_f = a[:,f*32:(f+1)*32] @ w2[f]; v = h + xx*(tm_maa[1+f] + m_f)
// f=0 -> xw hi/lo; f=1(k)->slot1, f=2(v)->slot2, f=3(r)->slot0, f=4(g)->slot3
__global__ __launch_bounds__(256)
void mix5_kernel(const float* __restrict__ a, const float* __restrict__ w2,
                 const float* __restrict__ tm_maa,
                 __half* __restrict__ xwh, __half* __restrict__ xwl,
                 __half* __restrict__ a4h, __half* __restrict__ a4l)
{
    __shared__ float AsT[32][129];
    __shared__ float Ws[32][128];
    const int tid = threadIdx.x;
    const int f  = blockIdx.z;
    const int c0 = blockIdx.x * 128;
    const int m0 = blockIdx.y * 128;
    const int tcol = tid & 15, trow = tid >> 4;

    #pragma unroll
    for (int i = tid; i < 128 * 32; i += 256){
        int r = i >> 5, d = i & 31;
        AsT[d][r] = a[(size_t)(m0 + r) * 160 + f * 32 + d];
    }
    #pragma unroll
    for (int i = tid; i < 32 * 128; i += 256){
        int d = i >> 7, c = i & 127;
        Ws[d][c] = w2[((size_t)f * 32 + d) * Cc + c0 + c];
    }
    __syncthreads();

    float acc[8][8];
    #pragma unroll
    for (int i = 0; i < 8; i++)
        #pragma unroll
        for (int j = 0; j < 8; j++) acc[i][j] = 0.f;

    #pragma unroll 8
    for (int d = 0; d < 32; d++){
        float regM[8], regN[8];
        #pragma unroll
        for (int i = 0; i < 8; i++) regM[i] = AsT[d][trow*8 + i];
        *(float4*)&regN[0] = *(const float4*)&Ws[d][tcol*8];
        *(float4*)&regN[4] = *(const float4*)&Ws[d][tcol*8 + 4];
        #pragma unroll
        for (int i = 0; i < 8; i++)
            #pragma unroll
            for (int j = 0; j < 8; j++)
                acc[i][j] = fmaf(regM[i], regN[j], acc[i][j]);
    }

    const int slot = (f == 1) ? 1 : (f == 2) ? 2 : (f == 3) ? 0 : 3;
    __half* oh = (f == 0) ? xwh : a4h + (size_t)slot * MM * Cc;
    __half* ol = (f == 0) ? xwl : a4l + (size_t)slot * MM * Cc;
    const float* maa = tm_maa + (size_t)(1 + f) * Cc + c0 + tcol*8;

    #pragma unroll
    for (int i = 0; i < 8; i++){
        const size_t idx = (size_t)(m0 + trow*8 + i) * Cc + c0 + tcol*8;
        #pragma unroll
        for (int j = 0; j < 8; j += 2){
            float2 hv = *reinterpret_cast<const float2*>(&g_h[idx + j]);
            float2 xv = *reinterpret_cast<const float2*>(&g_xx[idx + j]);
            float v0 = hv.x + xv.x * (maa[j]     + acc[i][j]);
            float v1 = hv.y + xv.y * (maa[j + 1] + acc[i][j + 1]);
            __half a0, b0, a1, b1;
            split_f16(v0, a0, b0);
            split_f16(v1, a1, b1);
            __half2 hp; hp.x = a0; hp.y = a1;
            __half2 lp; lp.x = b0; lp.y = b1;
            *reinterpret_cast<__half2*>(oh + idx + j) = hp;
            *reinterpret_cast<__half2*>(ol + idx + j) = lp;
        }
    }
}

// ---------------- small SIMT fp32 GEMM (td_w2 only) ----------------
#define BMt 128
#define BNt 128
#define BKt 8
#define TMt 8
#define TNt 8
__global__ __launch_bounds__(256)
void gemm_addvec(const float* __restrict__ A, const float* __restrict__ Bm,
                 float* __restrict__ Cm, int M, int N, int K, int lda, int ldc,
                 const float* __restrict__ aux0)
{
    __shared__ float As[BKt][BMt];
    __shared__ float Bs[BKt][BNt];
    const int bm = blockIdx.y * BMt;
    const int bn = blockIdx.x * BNt;
    const int tid = threadIdx.x;
    const int tcol = tid & 15;
    const int trow = tid >> 4;
    const int a_row = tid >> 1;
    const int a_col = (tid & 1) * 4;
    const int b_row = tid >> 5;
    const int b_col = (tid & 31) * 4;

    float acc[TMt][TNt];
    #pragma unroll
    for (int i = 0; i < TMt; i++)
        #pragma unroll
        for (int j = 0; j < TNt; j++) acc[i][j] = 0.f;

    for (int k0 = 0; k0 < K; k0 += BKt) {
        float4 av = *reinterpret_cast<const float4*>(A + (size_t)(bm + a_row)*lda + k0 + a_col);
        As[a_col+0][a_row] = av.x;
        As[a_col+1][a_row] = av.y;
        As[a_col+2][a_row] = av.z;
        As[a_col+3][a_row] = av.w;
        *reinterpret_cast<float4*>(&Bs[b_row][b_col]) =
            *reinterpret_cast<const float4*>(Bm + (size_t)(k0 + b_row)*N + bn + b_col);
        __syncthreads();
        #pragma unroll
        for (int kk = 0; kk < BKt; kk++) {
            float regM[TMt], regN[TNt];
            *(float4*)&regM[0] = *(const float4*)&As[kk][trow*TMt];
            *(float4*)&regM[4] = *(const float4*)&As[kk][trow*TMt + 4];
            *(float4*)&regN[0] = *(const float4*)&Bs[kk][tcol*TNt];
            *(float4*)&regN[4] = *(const float4*)&Bs[kk][tcol*TNt + 4];
            #pragma unroll
            for (int i = 0; i < TMt; i++)
                #pragma unroll
                for (int j = 0; j < TNt; j++)
                    acc[i][j] = fmaf(regM[i], regN[j], acc[i][j]);
        }
        __syncthreads();
    }

    #pragma unroll
    for (int i = 0; i < TMt; i++) {
        int m = bm + trow*TMt + i;
        #pragma unroll
        for (int j = 0; j < TNt; j++) {
            int n = bn + tcol*TNt + j;
            Cm[(size_t)m * ldc + n] = aux0[n] + acc[i][j];
        }
    }
}

// ---------------- LayerNorm over C per token ----------------
__global__ __launch_bounds__(256)
void ln_kernel(const float* __restrict__ x, const float* __restrict__ w,
               const float* __restrict__ b, float* __restrict__ out, float eps)
{
    const size_t base = (size_t)blockIdx.x * Cc;
    float sum = 0.f, sq = 0.f;
    for (int c = threadIdx.x; c < Cc; c += 256) { float v = x[base + c]; sum += v; sq += v*v; }
    #pragma unroll
    for (int o = 16; o; o >>= 1) {
        sum += __shfl_xor_sync(0xffffffffu, sum, o);
        sq  += __shfl_xor_sync(0xffffffffu, sq,  o);
    }
    __shared__ float s1[8], s2[8];
    int wid = threadIdx.x >> 5, lane = threadIdx.x & 31;
    if (!lane) { s1[wid] = sum; s2[wid] = sq; }
    __syncthreads();
    if (threadIdx.x == 0) {
        float ts = 0.f, tq = 0.f;
        #pragma unroll
        for (int i = 0; i < 8; i++) { ts += s1[i]; tq += s2[i]; }
        float m = ts / (float)Cc;
        float var = tq / (float)Cc - m*m;
        s1[0] = m; s2[0] = rsqrtf(var + eps);
    }
    __syncthreads();
    float m = s1[0], rstd = s2[0];
    for (int c = threadIdx.x; c < Cc; c += 256)
        out[base + c] = (x[base + c] - m) * rstd * w[c] + b[c];
}

// ---------------- token shift + first mix -> fp16 hi/lo ----------------
__global__ void shift1_kernel(const float* __restrict__ tm_maa)
{
    size_t idx = (size_t)blockIdx.x * 256 + threadIdx.x;
    int c  = (int)(idx % Cc);
    int tt = (int)(idx / Cc);
    int t  = tt % Tt;
    float hv = g_h[idx];
    float hp = t ? g_h[idx - Cc] : 0.f;
    float d = hp - hv;
    g_xx[idx] = d;
    float v = hv + d * tm_maa[c];
    __half hb, lb; split_f16(v, hb, lb);
    g_xxx_h[idx] = hb; g_xxx_l[idx] = lb;
}

// ---------------- token shift (channel mixing) -> fp16 hi/lo ----------------
__global__ void shift2_kernel(const float* __restrict__ cm_maa)
{
    size_t idx = (size_t)blockIdx.x * 256 + threadIdx.x;
    int c  = (int)(idx % Cc);
    int tt = (int)(idx / Cc);
    int t  = tt % Tt;
    float hv = g_h[idx];
    float hp = t ? g_h[idx - Cc] : 0.f;
    float d = hp - hv;
    float a = hv + d * cm_maa[c];
    float b = hv + d * cm_maa[Cc + c];
    __half hb, lb;
    split_f16(a, hb, lb); g_xk2_h[idx] = hb; g_xk2_l[idx] = lb;
    split_f16(b, hb, lb); g_xr2_h[idx] = hb; g_xr2_l[idx] = lb;
}

// ---------------- WKV6 recurrent scan: 256 threads, 16 rows/thread ----------
__global__ __launch_bounds__(256)
void wkv6_kernel(const float* __restrict__ u,
                 const float* __restrict__ rr, const float* __restrict__ kk,
                 const float* __restrict__ vv, const float* __restrict__ ww,
                 float* __restrict__ yy)
{
    const int bh = blockIdx.x;
    const int b  = bh >> 5;
    const int hh = bh & 31;
    const int tid = threadIdx.x;
    const int j = tid & 63;
    const int ib = (tid >> 6) * 16;
    __shared__ float4 sv[64];
    __shared__ float  yp[256];
    float S[16];
    #pragma unroll
    for (int i = 0; i < 16; i++) S[i] = 0.f;
    size_t off = (size_t)b * Tt * Cc + (size_t)hh * Nn;
    float ur = (tid < 64) ? u[hh * Nn + j] : 0.f;

    float rn = 0.f, kn = 0.f, wn = 0.f, vn;
    if (tid < 64){ rn = rr[off + j]; kn = kk[off + j]; wn = ww[off + j]; }
    vn = vv[off + j];

    for (int t = 0; t < Tt; t++) {
        float rc = rn, kc = kn, wc = wn, vc = vn;
        size_t offn = off + Cc;
        if (t + 1 < Tt){
            if (tid < 64){ rn = rr[offn + j]; kn = kk[offn + j]; wn = ww[offn + j]; }
            vn = vv[offn + j];
        }
        if (tid < 64)
            sv[j] = make_float4(rc, kc, ur * kc, expf(-expf(wc)));
        __syncthreads();
        float a0 = 0.f, a1 = 0.f;
        #pragma unroll
        for (int ii = 0; ii < 16; ii += 2) {
            float4 q0 = sv[ib + ii];
            float4 q1 = sv[ib + ii + 1];
            a0 = fmaf(q0.x, fmaf(q0.z, vc, S[ii]), a0);
            S[ii] = fmaf(S[ii], q0.w, q0.y * vc);
            a1 = fmaf(q1.x, fmaf(q1.z, vc, S[ii + 1]), a1);
            S[ii + 1] = fmaf(S[ii + 1], q1.w, q1.y * vc);
        }
        yp[tid] = a0 + a1;
        __syncthreads();
        if (tid < 64) yy[off + j] = yp[j] + yp[64 + j] + yp[128 + j] + yp[192 + j];
        off = offn;
    }
}

// ---------------- GroupNorm(H) * silu-gate -> att fp16 hi/lo ----------------
__global__ __launch_bounds__(256)
void gnsilu_kernel(const float* __restrict__ lnw, const float* __restrict__ lnb,
                   const float* __restrict__ gg, const float* __restrict__ yy)
{
    int gw  = blockIdx.x * 8 + (threadIdx.x >> 5);
    int lane = threadIdx.x & 31;
    int t  = gw >> 5;
    int hh = gw & 31;
    size_t base = (size_t)t * Cc + (size_t)hh * Nn;
    float y0 = yy[base + lane], y1 = yy[base + 32 + lane];
    float sum = y0 + y1, sq = y0*y0 + y1*y1;
    #pragma unroll
    for (int o = 16; o; o >>= 1) {
        sum += __shfl_xor_sync(0xffffffffu, sum, o);
        sq  += __shfl_xor_sync(0xffffffffu, sq,  o);
    }
    float m = sum * (1.f / 64.f);
    float rstd = rsqrtf(sq * (1.f / 64.f) - m*m + 6.4e-4f);
    int ch = hh * Nn + lane;
    float gv0 = gg[base + lane], gv1 = gg[base + 32 + lane];
    float o0 = ((y0 - m) * rstd * lnw[ch]      + lnb[ch])      * gv0;
    float o1 = ((y1 - m) * rstd * lnw[ch + 32] + lnb[ch + 32]) * gv1;
    __half hb, lb;
    split_f16(o0, hb, lb); g_att_h[base + lane]      = hb; g_att_l[base + lane]      = lb;
    split_f16(o1, hb, lb); g_att_h[base + 32 + lane] = hb; g_att_l[base + 32 + lane] = lb;
}

// ---------------- host launch ----------------
static inline dim3 mmagrid(int M, int N){ return dim3(N / 128, M / 128); }

#define SYMADDR(v, s) cudaGetSymbolAddress((void**)&v, s)

extern "C" void kernel_launch(void* const* d_in, const int* in_sizes, int n_in,
                              void* d_out, int out_size)
{
    (void)in_sizes; (void)n_in; (void)out_size;
    const float* x          = (const float*)d_in[0];
    const float* ln1_w      = (const float*)d_in[1];
    const float* ln1_b      = (const float*)d_in[2];
    const float* ln2_w      = (const float*)d_in[3];
    const float* ln2_b      = (const float*)d_in[4];
    const float* tm_maa     = (const float*)d_in[5];
    const float* maa_w1     = (const float*)d_in[6];
    const float* maa_w2     = (const float*)d_in[7];
    const float* time_decay = (const float*)d_in[8];
    const float* td_w1      = (const float*)d_in[9];
    const float* td_w2      = (const float*)d_in[10];
    const float* time_faaaa = (const float*)d_in[11];
    const float* Wr  = (const float*)d_in[12];
    const float* Wk  = (const float*)d_in[13];
    const float* Wv  = (const float*)d_in[14];
    const float* Wg  = (const float*)d_in[15];
    const float* Wo  = (const float*)d_in[16];
    const float* lnx_w = (const float*)d_in[17];
    const float* lnx_b = (const float*)d_in[18];
    const float* cm_maa = (const float*)d_in[19];
    const float* Wck = (const float*)d_in[20];
    const float* Wcr = (const float*)d_in[21];
    const float* Wcv = (const float*)d_in[22];
    float* out = (float*)d_out;

    float *ph, *pxx, *pa, *pw, *pwt, *py, *px1, *psig, *pout4;
    SYMADDR(ph, g_h);   SYMADDR(pxx, g_xx); SYMADDR(pa, g_a);
    SYMADDR(pw, g_w);   SYMADDR(pwt, g_wt); SYMADDR(py, g_y);
    SYMADDR(px1, g_x1); SYMADDR(psig, g_sig); SYMADDR(pout4, g_out4);

    __half *xxxh,*xxxl,*xwh,*xwl,*a4h,*a4l,*atth,*attl,*xk2h,*xk2l,*xr2h,*xr2l,*kfh,*kfl;
    SYMADDR(xxxh, g_xxx_h); SYMADDR(xxxl, g_xxx_l);
    SYMADDR(xwh, g_xw_h);   SYMADDR(xwl, g_xw_l);
    SYMADDR(a4h, g_act4_h); SYMADDR(a4l, g_act4_l);
    SYMADDR(atth, g_att_h); SYMADDR(attl, g_att_l);
    SYMADDR(xk2h, g_xk2_h); SYMADDR(xk2l, g_xk2_l);
    SYMADDR(xr2h, g_xr2_h); SYMADDR(xr2l, g_xr2_l);
    SYMADDR(kfh, g_kf_h);   SYMADDR(kfl, g_kf_l);

    __half *w4,*wo16,*wcr16,*wck16,*wcv16,*maaT,*tdT;
    SYMADDR(w4, g_W4_16);   SYMADDR(wo16, g_Wo16);
    SYMADDR(wcr16, g_Wcr16);
    SYMADDR(wck16, g_Wck16); SYMADDR(wcv16, g_Wcv16);
    SYMADDR(maaT, g_maaw1T); SYMADDR(tdT, g_tdw1T);

    cudaFuncSetAttribute(gemm_mma<TC_TANH>,  cudaFuncAttributeMaxDynamicSharedMemorySize, SM_MMA_TOTAL);
    cudaFuncSetAttribute(gemm_mma<TC_ADDX>,  cudaFuncAttributeMaxDynamicSharedMemorySize, SM_MMA_TOTAL);
    cudaFuncSetAttribute(gemm_mma<TC_RELU2>, cudaFuncAttributeMaxDynamicSharedMemorySize, SM_MMA_TOTAL);
    cudaFuncSetAttribute(gemm_mma<TC_SIGM>,  cudaFuncAttributeMaxDynamicSharedMemorySize, SM_MMA_TOTAL);
    cudaFuncSetAttribute(gemm_mma<TC_CVMIX>, cudaFuncAttributeMaxDynamicSharedMemorySize, SM_MMA_TOTAL);
    cudaFuncSetAttribute(gemm_rkvg,          cudaFuncAttributeMaxDynamicSharedMemorySize, SM_MMA_TOTAL);

    const int ELT_BLOCKS = (MM * Cc) / 256;

    // ---- time mixing ----
    ln_kernel<<<MM, 256>>>(x, ln1_w, ln1_b, ph, 1e-5f);
    shift1_kernel<<<ELT_BLOCKS, 256>>>(tm_maa);
    wtrans6<<<dim3(Cc/32, Cc/32, 6), 256>>>(Wr, Wk, Wv, Wg, Wo, Wcr, w4, wo16, wcr16);
    wtrans16p<<<dim3(256/32, Cc/32), 256>>>(maa_w1, maaT, Cc, 160);
    gemm_mma<TC_TANH><<<mmagrid(MM, 256), 256, SM_MMA_TOTAL>>>(xxxh, xxxl, maaT, pa,
        MM, 256, Cc, 160, 160, nullptr, nullptr, nullptr, nullptr);
    mix5_kernel<<<dim3(Cc/128, MM/128, 5), 256>>>(pa, maa_w2, tm_maa, xwh, xwl, a4h, a4l);
    gemm_rkvg<<<dim3(Cc/128, MM/128, 4), 256, SM_MMA_TOTAL>>>(a4h, a4l, w4, pout4);
    wtrans16p<<<dim3(128/32, Cc/32), 256>>>(td_w1, tdT, Cc, 64);
    gemm_mma<TC_TANH><<<mmagrid(MM, 128), 256, SM_MMA_TOTAL>>>(xwh, xwl, tdT, pwt,
        MM, 128, Cc, 64, 64, nullptr, nullptr, nullptr, nullptr);
    gemm_addvec<<<dim3(Cc/128, MM/128), 256>>>(pwt, td_w2, pw, MM, Cc, 64, 64, Cc, time_decay);
    wkv6_kernel<<<Bq * Hh, 256>>>(time_faaaa,
        pout4 + (size_t)0*MM*Cc, pout4 + (size_t)1*MM*Cc, pout4 + (size_t)2*MM*Cc, pw, py);
    gnsilu_kernel<<<MM * Hh / 8, 256>>>(lnx_w, lnx_b, pout4 + (size_t)3*MM*Cc, py);
    gemm_mma<TC_ADDX><<<mmagrid(MM, Cc), 256, SM_MMA_TOTAL>>>(atth, attl, wo16, px1,
        MM, Cc, Cc, Cc, Cc, x, nullptr, nullptr, nullptr);

    // ---- channel mixing ----
    ln_kernel<<<MM, 256>>>(px1, ln2_w, ln2_b, ph, 1e-5f);
    shift2_kernel<<<ELT_BLOCKS, 256>>>(cm_maa);
    wtrans16<<<dim3(Ff/32, Cc/32), 256>>>(Wck, wck16, Cc, Ff);
    gemm_mma<TC_RELU2><<<mmagrid(MM, Ff), 256, SM_MMA_TOTAL>>>(xk2h, xk2l, wck16, nullptr,
        MM, Ff, Cc, Ff, Ff, nullptr, nullptr, kfh, kfl);
    gemm_mma<TC_SIGM><<<mmagrid(MM, Cc), 256, SM_MMA_TOTAL>>>(xr2h, xr2l, wcr16, psig,
        MM, Cc, Cc, Cc, Cc, nullptr, nullptr, nullptr, nullptr);
    wtrans16<<<dim3(Cc/32, Ff/32), 256>>>(Wcv, wcv16, Ff, Cc);
    gemm_mma<TC_CVMIX><<<mmagrid(MM, Cc), 256, SM_MMA_TOTAL>>>(kfh, kfl, wcv16, out,
        MM, Cc, Ff, Cc, Cc, px1, psig, nullptr, nullptr);
}

// round 6
// speedup vs baseline: 6.3241x; 1.4869x over previous
#include <cuda_runtime.h>
#include <cuda_fp16.h>
#include <math.h>

// ---------------- problem constants ----------------
#define Bq 2
#define Tt 2048
#define Cc 2048
#define Hh 32
#define Nn 64
#define Ff 7168
#define MM (Bq*Tt)          // 4096 tokens

typedef unsigned int u32;
typedef unsigned long long u64;

// ---------------- device scratch (no allocs allowed) ----------------
__device__ float g_h  [(size_t)MM*Cc];
__device__ float g_xx [(size_t)MM*Cc];
__device__ float g_a  [(size_t)MM*160];
__device__ float g_w  [(size_t)MM*Cc];
__device__ float g_wt [(size_t)MM*64];
__device__ float g_y  [(size_t)MM*Cc];
__device__ float g_x1 [(size_t)MM*Cc];
__device__ float g_sig[(size_t)MM*Cc];
__device__ float g_out4[(size_t)4*MM*Cc];   // r,k,v,g

// fp16 activations (A operands, single precision-rounded)
__device__ __align__(16) __half g_xxx16[(size_t)MM*Cc];
__device__ __align__(16) __half g_xw16 [(size_t)MM*Cc];
__device__ __align__(16) __half g_act4 [(size_t)4*MM*Cc];   // xr,xk,xv,xg
__device__ __align__(16) __half g_att16[(size_t)MM*Cc];
__device__ __align__(16) __half g_xk216[(size_t)MM*Cc];
__device__ __align__(16) __half g_xr216[(size_t)MM*Cc];
__device__ __align__(16) __half g_kf16 [(size_t)MM*Ff];

// fp16 transposed weights ([N,K] K-major)
__device__ __align__(16) __half g_W4_16 [(size_t)4*Cc*Cc];  // Wr,Wk,Wv,Wg
__device__ __align__(16) __half g_Wo16  [(size_t)Cc*Cc];
__device__ __align__(16) __half g_Wcr16 [(size_t)Cc*Cc];
__device__ __align__(16) __half g_Wck16 [(size_t)Cc*Ff];    // [7168,2048]
__device__ __align__(16) __half g_Wcv16 [(size_t)Ff*Cc];    // [2048,7168]
__device__ __align__(16) __half g_maaw1T[(size_t)256*Cc];   // padded [256,2048]
__device__ __align__(16) __half g_tdw1T [(size_t)128*Cc];   // padded [128,2048]

// ---------------- PTX helpers (baseline PTX; no sm_103a-only features) ----
__device__ __forceinline__ u32 smem_u32(const void* p){
    u32 a;
    asm("{ .reg .u64 t; cvta.to.shared.u64 t, %1; cvt.u32.u64 %0, t; }" : "=r"(a) : "l"(p));
    return a;
}
__device__ __forceinline__ void cp16(u32 s, const void* g){
    asm volatile("cp.async.cg.shared.global [%0], [%1], 16;" :: "r"(s), "l"(g) : "memory");
}
__device__ __forceinline__ void cp_commit(){
    asm volatile("cp.async.commit_group;" ::: "memory");
}
template<int NG> __device__ __forceinline__ void cp_wait(){
    asm volatile("cp.async.wait_group %0;" :: "n"(NG) : "memory");
}
__device__ __forceinline__ void ldsm4(u32* r, u32 a){
    asm volatile("ldmatrix.sync.aligned.m8n8.x4.shared.b16 {%0,%1,%2,%3}, [%4];"
        : "=r"(r[0]), "=r"(r[1]), "=r"(r[2]), "=r"(r[3]) : "r"(a));
}
__device__ __forceinline__ void hmma16(float* c, const u32* a, u32 b0, u32 b1){
    asm volatile(
        "mma.sync.aligned.m16n8k16.row.col.f32.f16.f16.f32 "
        "{%0,%1,%2,%3},{%4,%5,%6,%7},{%8,%9},{%0,%1,%2,%3};"
        : "+f"(c[0]), "+f"(c[1]), "+f"(c[2]), "+f"(c[3])
        : "r"(a[0]), "r"(a[1]), "r"(a[2]), "r"(a[3]), "r"(b0), "r"(b1));
}

// ---------------- single-fp16 HMMA GEMM body ----------------
#define STAGE_BYTES 32768u    // A(16K) B(16K)
#define SM_MMA_TOTAL (3*32768)

enum { TC_NONE=0, TC_SILU, TC_ADDX, TC_RELU2, TC_SIGM, TC_CVMIX, TC_TANH };

template<int EPI>
__device__ __forceinline__
void mma_body(const __half* __restrict__ A16, const __half* __restrict__ B16,
              float* __restrict__ C, int M, int N, int K, int ldc, int nvalid,
              const float* __restrict__ aux0, const float* __restrict__ aux1,
              __half* __restrict__ Ch)
{
    extern __shared__ char sm_dyn[];
    const u32 sb = smem_u32(sm_dyn);
    const int tid  = threadIdx.x;
    const int wid  = tid >> 5;
    const int lane = tid & 31;
    const int m0 = blockIdx.y * 128;
    const int n0 = blockIdx.x * 128;
    const int wm = (wid & 1) * 64;
    const int wn = (wid >> 1) * 32;

    const int col16 = tid & 7;
    const int lrow  = tid >> 3;
    const u32 soff  = (u32)(lrow * 128 + col16 * 16);
    const u32 swz   = soff ^ ((soff >> 3) & 0x70);
    const size_t rstep = (size_t)32 * K * 2;
    const char* gA = (const char*)A16 + ((size_t)(m0 + lrow) * K + col16 * 8) * 2;
    const char* gB = (const char*)B16 + ((size_t)(n0 + lrow) * K + col16 * 8) * 2;

    auto load_stage = [&](int s){
        u32 base = sb + (u32)(s % 3) * STAGE_BYTES + swz;
        size_t ko = (size_t)s * 128;   // 64 fp16 = 128B along K
        #pragma unroll
        for (int i = 0; i < 4; i++){
            cp16(base +          i*4096u, gA + ko + i*rstep);
            cp16(base + 16384u + i*4096u, gB + ko + i*rstep);
        }
        cp_commit();
    };

    const u32 a_row = (u32)(wm + ((lane >> 3) & 1) * 8 + (lane & 7));
    const u32 a_kb  = (u32)((lane >> 4) * 16);
    const u32 b_row = (u32)(wn + (lane >> 4) * 8 + (lane & 7));
    const u32 b_kb  = (u32)(((lane >> 3) & 1) * 16);

    float acc[4][4][4];
    #pragma unroll
    for (int mi = 0; mi < 4; mi++)
        #pragma unroll
        for (int ni = 0; ni < 4; ni++)
            #pragma unroll
            for (int q = 0; q < 4; q++) acc[mi][ni][q] = 0.f;

    auto compute_stage = [&](u32 base){
        #pragma unroll
        for (int kk = 0; kk < 4; kk++){
            u32 aa[4][4], bb[2][4];
            #pragma unroll
            for (int mi = 0; mi < 4; mi++){
                u32 off = (a_row + mi*16u) * 128u + (u32)kk*32u + a_kb;
                off ^= (off >> 3) & 0x70;
                ldsm4(aa[mi], base + off);
            }
            #pragma unroll
            for (int nj = 0; nj < 2; nj++){
                u32 off = (b_row + nj*16u) * 128u + (u32)kk*32u + b_kb;
                off ^= (off >> 3) & 0x70;
                ldsm4(bb[nj], base + 16384u + off);
            }
            #pragma unroll
            for (int mi = 0; mi < 4; mi++)
                #pragma unroll
                for (int ni = 0; ni < 4; ni++){
                    const u32* pb = &bb[ni >> 1][(ni & 1) * 2];
                    hmma16(acc[mi][ni], aa[mi], pb[0], pb[1]);
                }
        }
    };

    const int NS = K >> 6;
    load_stage(0);
    load_stage(1);
    for (int s = 0; s < NS; s++){
        if (s + 1 < NS) cp_wait<1>(); else cp_wait<0>();
        __syncthreads();
        if (s + 2 < NS) load_stage(s + 2);
        compute_stage(sb + (u32)(s % 3) * STAGE_BYTES);
    }

    #pragma unroll
    for (int mi = 0; mi < 4; mi++){
        #pragma unroll
        for (int ni = 0; ni < 4; ni++){
            const int n = n0 + wn + ni*8 + (lane & 3)*2;
            if (n >= nvalid) continue;
            #pragma unroll
            for (int half = 0; half < 2; half++){
                const int m = m0 + wm + mi*16 + (lane >> 2) + half*8;
                const size_t idx = (size_t)m * ldc + n;
                float v0 = acc[mi][ni][half*2 + 0];
                float v1 = acc[mi][ni][half*2 + 1];
                if (EPI == TC_SILU){
                    v0 = v0 / (1.f + expf(-v0));
                    v1 = v1 / (1.f + expf(-v1));
                } else if (EPI == TC_TANH){
                    v0 = tanhf(v0); v1 = tanhf(v1);
                } else if (EPI == TC_ADDX){
                    v0 += aux0[idx]; v1 += aux0[idx + 1];
                } else if (EPI == TC_SIGM){
                    v0 = 1.f / (1.f + expf(-v0));
                    v1 = 1.f / (1.f + expf(-v1));
                } else if (EPI == TC_CVMIX){
                    v0 = aux0[idx]     + aux1[idx]     * v0;
                    v1 = aux0[idx + 1] + aux1[idx + 1] * v1;
                } else if (EPI == TC_RELU2){
                    float r0 = v0 > 0.f ? v0 : 0.f;
                    float r1 = v1 > 0.f ? v1 : 0.f;
                    __half2 hp;
                    hp.x = __float2half_rn(r0 * r0);
                    hp.y = __float2half_rn(r1 * r1);
                    *reinterpret_cast<__half2*>(Ch + idx) = hp;
                    continue;
                }
                float2 o; o.x = v0; o.y = v1;
                *reinterpret_cast<float2*>(C + idx) = o;
            }
        }
    }
}

template<int EPI>
__global__ __launch_bounds__(256, 2)
void gemm_mma(const __half* __restrict__ A16, const __half* __restrict__ B16,
              float* __restrict__ C, int M, int N, int K, int ldc, int nvalid,
              const float* __restrict__ aux0, const float* __restrict__ aux1,
              __half* __restrict__ Ch)
{
    mma_body<EPI>(A16, B16, C, M, N, K, ldc, nvalid, aux0, aux1, Ch);
}

// merged r/k/v/g GEMM: z selects operand set; z==3 (g) applies silu
__global__ __launch_bounds__(256, 2)
void gemm_rkvg(const __half* __restrict__ A4, const __half* __restrict__ W4,
               float* __restrict__ C4)
{
    const int z = blockIdx.z;
    const size_t ao = (size_t)z * MM * Cc;
    const size_t wo = (size_t)z * Cc * Cc;
    if (z == 3)
        mma_body<TC_SILU>(A4 + ao, W4 + wo, C4 + ao, MM, Cc, Cc, Cc, Cc,
                          nullptr, nullptr, nullptr);
    else
        mma_body<TC_NONE>(A4 + ao, W4 + wo, C4 + ao, MM, Cc, Cc, Cc, Cc,
                          nullptr, nullptr, nullptr);
}

// ---------------- weight transposes ----------------
__global__ __launch_bounds__(256)
void wtrans16(const float* __restrict__ W, __half* __restrict__ Th, int K, int N)
{
    __shared__ float s[32][33];
    const int tx = threadIdx.x & 31, ty = threadIdx.x >> 5;
    const int n0 = blockIdx.x * 32, k0 = blockIdx.y * 32;
    #pragma unroll
    for (int r = 0; r < 32; r += 8)
        s[ty + r][tx] = W[(size_t)(k0 + ty + r) * N + n0 + tx];
    __syncthreads();
    #pragma unroll
    for (int r = 0; r < 32; r += 8)
        Th[(size_t)(n0 + ty + r) * K + k0 + tx] = __float2half_rn(s[tx][ty + r]);
}

__global__ __launch_bounds__(256)
void wtrans16p(const float* __restrict__ W, __half* __restrict__ Th, int K, int N)
{
    __shared__ float s[32][33];
    const int tx = threadIdx.x & 31, ty = threadIdx.x >> 5;
    const int n0 = blockIdx.x * 32, k0 = blockIdx.y * 32;
    #pragma unroll
    for (int r = 0; r < 32; r += 8){
        int n = n0 + tx;
        s[ty + r][tx] = (n < N) ? W[(size_t)(k0 + ty + r) * N + n] : 0.f;
    }
    __syncthreads();
    #pragma unroll
    for (int r = 0; r < 32; r += 8)
        Th[(size_t)(n0 + ty + r) * K + k0 + tx] = __float2half_rn(s[tx][ty + r]);
}

__global__ __launch_bounds__(256)
void wtrans6(const float* __restrict__ W0, const float* __restrict__ W1,
             const float* __restrict__ W2, const float* __restrict__ W3,
             const float* __restrict__ W4w, const float* __restrict__ W5,
             __half* __restrict__ T4, __half* __restrict__ To, __half* __restrict__ Tcr)
{
    __shared__ float s[32][33];
    const int z = blockIdx.z;
    const float* W = (z==0)?W0:(z==1)?W1:(z==2)?W2:(z==3)?W3:(z==4)?W4w:W5;
    __half* T = (z < 4) ? (T4 + (size_t)z * Cc * Cc) : (z == 4 ? To : Tcr);
    const int tx = threadIdx.x & 31, ty = threadIdx.x >> 5;
    const int n0 = blockIdx.x * 32, k0 = blockIdx.y * 32;
    #pragma unroll
    for (int r = 0; r < 32; r += 8)
        s[ty + r][tx] = W[(size_t)(k0 + ty + r) * Cc + n0 + tx];
    __syncthreads();
    #pragma unroll
    for (int r = 0; r < 32; r += 8)
        T[(size_t)(n0 + ty + r) * Cc + k0 + tx] = __float2half_rn(s[tx][ty + r]);
}

// ---------------- fused 5-way mix, grid.z = f ----------------
// f=0 -> xw; f=1(k)->slot1, f=2(v)->slot2, f=3(r)->slot0, f=4(g)->slot3
__global__ __launch_bounds__(256)
void mix5_kernel(const float* __restrict__ a, const float* __restrict__ w2,
                 const float* __restrict__ tm_maa,
                 __half* __restrict__ xw16, __half* __restrict__ a4)
{
    __shared__ float AsT[32][129];
    __shared__ float Ws[32][128];
    const int tid = threadIdx.x;
    const int f  = blockIdx.z;
    const int c0 = blockIdx.x * 128;
    const int m0 = blockIdx.y * 128;
    const int tcol = tid & 15, trow = tid >> 4;

    #pragma unroll
    for (int i = tid; i < 128 * 32; i += 256){
        int r = i >> 5, d = i & 31;
        AsT[d][r] = a[(size_t)(m0 + r) * 160 + f * 32 + d];
    }
    #pragma unroll
    for (int i = tid; i < 32 * 128; i += 256){
        int d = i >> 7, c = i & 127;
        Ws[d][c] = w2[((size_t)f * 32 + d) * Cc + c0 + c];
    }
    __syncthreads();

    float acc[8][8];
    #pragma unroll
    for (int i = 0; i < 8; i++)
        #pragma unroll
        for (int j = 0; j < 8; j++) acc[i][j] = 0.f;

    #pragma unroll 8
    for (int d = 0; d < 32; d++){
        float regM[8], regN[8];
        #pragma unroll
        for (int i = 0; i < 8; i++) regM[i] = AsT[d][trow*8 + i];
        *(float4*)&regN[0] = *(const float4*)&Ws[d][tcol*8];
        *(float4*)&regN[4] = *(const float4*)&Ws[d][tcol*8 + 4];
        #pragma unroll
        for (int i = 0; i < 8; i++)
            #pragma unroll
            for (int j = 0; j < 8; j++)
                acc[i][j] = fmaf(regM[i], regN[j], acc[i][j]);
    }

    const int slot = (f == 1) ? 1 : (f == 2) ? 2 : (f == 3) ? 0 : 3;
    __half* oh = (f == 0) ? xw16 : a4 + (size_t)slot * MM * Cc;
    const float* maa = tm_maa + (size_t)(1 + f) * Cc + c0 + tcol*8;

    #pragma unroll
    for (int i = 0; i < 8; i++){
        const size_t idx = (size_t)(m0 + trow*8 + i) * Cc + c0 + tcol*8;
        #pragma unroll
        for (int j = 0; j < 8; j += 2){
            float2 hv = *reinterpret_cast<const float2*>(&g_h[idx + j]);
            float2 xv = *reinterpret_cast<const float2*>(&g_xx[idx + j]);
            float v0 = hv.x + xv.x * (maa[j]     + acc[i][j]);
            float v1 = hv.y + xv.y * (maa[j + 1] + acc[i][j + 1]);
            __half2 hp;
            hp.x = __float2half_rn(v0);
            hp.y = __float2half_rn(v1);
            *reinterpret_cast<__half2*>(oh + idx + j) = hp;
        }
    }
}

// ---------------- small SIMT fp32 GEMM (td_w2 only) ----------------
#define BMt 128
#define BNt 128
#define BKt 8
#define TMt 8
#define TNt 8
__global__ __launch_bounds__(256)
void gemm_addvec(const float* __restrict__ A, const float* __restrict__ Bm,
                 float* __restrict__ Cm, int M, int N, int K, int lda, int ldc,
                 const float* __restrict__ aux0)
{
    __shared__ float As[BKt][BMt];
    __shared__ float Bs[BKt][BNt];
    const int bm = blockIdx.y * BMt;
    const int bn = blockIdx.x * BNt;
    const int tid = threadIdx.x;
    const int tcol = tid & 15;
    const int trow = tid >> 4;
    const int a_row = tid >> 1;
    const int a_col = (tid & 1) * 4;
    const int b_row = tid >> 5;
    const int b_col = (tid & 31) * 4;

    float acc[TMt][TNt];
    #pragma unroll
    for (int i = 0; i < TMt; i++)
        #pragma unroll
        for (int j = 0; j < TNt; j++) acc[i][j] = 0.f;

    for (int k0 = 0; k0 < K; k0 += BKt) {
        float4 av = *reinterpret_cast<const float4*>(A + (size_t)(bm + a_row)*lda + k0 + a_col);
        As[a_col+0][a_row] = av.x;
        As[a_col+1][a_row] = av.y;
        As[a_col+2][a_row] = av.z;
        As[a_col+3][a_row] = av.w;
        *reinterpret_cast<float4*>(&Bs[b_row][b_col]) =
            *reinterpret_cast<const float4*>(Bm + (size_t)(k0 + b_row)*N + bn + b_col);
        __syncthreads();
        #pragma unroll
        for (int kk = 0; kk < BKt; kk++) {
            float regM[TMt], regN[TNt];
            *(float4*)&regM[0] = *(const float4*)&As[kk][trow*TMt];
            *(float4*)&regM[4] = *(const float4*)&As[kk][trow*TMt + 4];
            *(float4*)&regN[0] = *(const float4*)&Bs[kk][tcol*TNt];
            *(float4*)&regN[4] = *(const float4*)&Bs[kk][tcol*TNt + 4];
            #pragma unroll
            for (int i = 0; i < TMt; i++)
                #pragma unroll
                for (int j = 0; j < TNt; j++)
                    acc[i][j] = fmaf(regM[i], regN[j], acc[i][j]);
        }
        __syncthreads();
    }

    #pragma unroll
    for (int i = 0; i < TMt; i++) {
        int m = bm + trow*TMt + i;
        #pragma unroll
        for (int j = 0; j < TNt; j++) {
            int n = bn + tcol*TNt + j;
            Cm[(size_t)m * ldc + n] = aux0[n] + acc[i][j];
        }
    }
}

// ---------------- LayerNorm over C per token ----------------
__global__ __launch_bounds__(256)
void ln_kernel(const float* __restrict__ x, const float* __restrict__ w,
               const float* __restrict__ b, float* __restrict__ out, float eps)
{
    const size_t base = (size_t)blockIdx.x * Cc;
    float sum = 0.f, sq = 0.f;
    for (int c = threadIdx.x; c < Cc; c += 256) { float v = x[base + c]; sum += v; sq += v*v; }
    #pragma unroll
    for (int o = 16; o; o >>= 1) {
        sum += __shfl_xor_sync(0xffffffffu, sum, o);
        sq  += __shfl_xor_sync(0xffffffffu, sq,  o);
    }
    __shared__ float s1[8], s2[8];
    int wid = threadIdx.x >> 5, lane = threadIdx.x & 31;
    if (!lane) { s1[wid] = sum; s2[wid] = sq; }
    __syncthreads();
    if (threadIdx.x == 0) {
        float ts = 0.f, tq = 0.f;
        #pragma unroll
        for (int i = 0; i < 8; i++) { ts += s1[i]; tq += s2[i]; }
        float m = ts / (float)Cc;
        float var = tq / (float)Cc - m*m;
        s1[0] = m; s2[0] = rsqrtf(var + eps);
    }
    __syncthreads();
    float m = s1[0], rstd = s2[0];
    for (int c = threadIdx.x; c < Cc; c += 256)
        out[base + c] = (x[base + c] - m) * rstd * w[c] + b[c];
}

// ---------------- token shift + first mix -> fp16 ----------------
__global__ void shift1_kernel(const float* __restrict__ tm_maa)
{
    size_t idx = (size_t)blockIdx.x * 256 + threadIdx.x;
    int c  = (int)(idx % Cc);
    int tt = (int)(idx / Cc);
    int t  = tt % Tt;
    float hv = g_h[idx];
    float hp = t ? g_h[idx - Cc] : 0.f;
    float d = hp - hv;
    g_xx[idx] = d;
    g_xxx16[idx] = __float2half_rn(hv + d * tm_maa[c]);
}

// ---------------- token shift (channel mixing) -> fp16 ----------------
__global__ void shift2_kernel(const float* __restrict__ cm_maa)
{
    size_t idx = (size_t)blockIdx.x * 256 + threadIdx.x;
    int c  = (int)(idx % Cc);
    int tt = (int)(idx / Cc);
    int t  = tt % Tt;
    float hv = g_h[idx];
    float hp = t ? g_h[idx - Cc] : 0.f;
    float d = hp - hv;
    g_xk216[idx] = __float2half_rn(hv + d * cm_maa[c]);
    g_xr216[idx] = __float2half_rn(hv + d * cm_maa[Cc + c]);
}

// ---------------- WKV6 recurrent scan: 256 threads, 16 rows/thread ----------
__global__ __launch_bounds__(256)
void wkv6_kernel(const float* __restrict__ u,
                 const float* __restrict__ rr, const float* __restrict__ kk,
                 const float* __restrict__ vv, const float* __restrict__ ww,
                 float* __restrict__ yy)
{
    const int bh = blockIdx.x;
    const int b  = bh >> 5;
    const int hh = bh & 31;
    const int tid = threadIdx.x;
    const int j = tid & 63;
    const int ib = (tid >> 6) * 16;
    __shared__ float4 sv[64];
    __shared__ float  yp[256];
    float S[16];
    #pragma unroll
    for (int i = 0; i < 16; i++) S[i] = 0.f;
    size_t off = (size_t)b * Tt * Cc + (size_t)hh * Nn;
    float ur = (tid < 64) ? u[hh * Nn + j] : 0.f;

    float rn = 0.f, kn = 0.f, wn = 0.f, vn;
    if (tid < 64){ rn = rr[off + j]; kn = kk[off + j]; wn = ww[off + j]; }
    vn = vv[off + j];

    for (int t = 0; t < Tt; t++) {
        float rc = rn, kc = kn, wc = wn, vc = vn;
        size_t offn = off + Cc;
        if (t + 1 < Tt){
            if (tid < 64){ rn = rr[offn + j]; kn = kk[offn + j]; wn = ww[offn + j]; }
            vn = vv[offn + j];
        }
        if (tid < 64)
            sv[j] = make_float4(rc, kc, ur * kc, expf(-expf(wc)));
        __syncthreads();
        float a0 = 0.f, a1 = 0.f;
        #pragma unroll
        for (int ii = 0; ii < 16; ii += 2) {
            float4 q0 = sv[ib + ii];
            float4 q1 = sv[ib + ii + 1];
            a0 = fmaf(q0.x, fmaf(q0.z, vc, S[ii]), a0);
            S[ii] = fmaf(S[ii], q0.w, q0.y * vc);
            a1 = fmaf(q1.x, fmaf(q1.z, vc, S[ii + 1]), a1);
            S[ii + 1] = fmaf(S[ii + 1], q1.w, q1.y * vc);
        }
        yp[tid] = a0 + a1;
        __syncthreads();
        if (tid < 64) yy[off + j] = yp[j] + yp[64 + j] + yp[128 + j] + yp[192 + j];
        off = offn;
    }
}

// ---------------- GroupNorm(H) * silu-gate -> att fp16 ----------------
__global__ __launch_bounds__(256)
void gnsilu_kernel(const float* __restrict__ lnw, const float* __restrict__ lnb,
                   const float* __restrict__ gg, const float* __restrict__ yy)
{
    int gw  = blockIdx.x * 8 + (threadIdx.x >> 5);
    int lane = threadIdx.x & 31;
    int t  = gw >> 5;
    int hh = gw & 31;
    size_t base = (size_t)t * Cc + (size_t)hh * Nn;
    float y0 = yy[base + lane], y1 = yy[base + 32 + lane];
    float sum = y0 + y1, sq = y0*y0 + y1*y1;
    #pragma unroll
    for (int o = 16; o; o >>= 1) {
        sum += __shfl_xor_sync(0xffffffffu, sum, o);
        sq  += __shfl_xor_sync(0xffffffffu, sq,  o);
    }
    float m = sum * (1.f / 64.f);
    float rstd = rsqrtf(sq * (1.f / 64.f) - m*m + 6.4e-4f);
    int ch = hh * Nn + lane;
    float gv0 = gg[base + lane], gv1 = gg[base + 32 + lane];
    float o0 = ((y0 - m) * rstd * lnw[ch]      + lnb[ch])      * gv0;
    float o1 = ((y1 - m) * rstd * lnw[ch + 32] + lnb[ch + 32]) * gv1;
    g_att16[base + lane]      = __float2half_rn(o0);
    g_att16[base + 32 + lane] = __float2half_rn(o1);
}

// ---------------- host launch ----------------
static inline dim3 mmagrid(int M, int N){ return dim3(N / 128, M / 128); }

#define SYMADDR(v, s) cudaGetSymbolAddress((void**)&v, s)

extern "C" void kernel_launch(void* const* d_in, const int* in_sizes, int n_in,
                              void* d_out, int out_size)
{
    (void)in_sizes; (void)n_in; (void)out_size;
    const float* x          = (const float*)d_in[0];
    const float* ln1_w      = (const float*)d_in[1];
    const float* ln1_b      = (const float*)d_in[2];
    const float* ln2_w      = (const float*)d_in[3];
    const float* ln2_b      = (const float*)d_in[4];
    const float* tm_maa     = (const float*)d_in[5];
    const float* maa_w1     = (const float*)d_in[6];
    const float* maa_w2     = (const float*)d_in[7];
    const float* time_decay = (const float*)d_in[8];
    const float* td_w1      = (const float*)d_in[9];
    const float* td_w2      = (const float*)d_in[10];
    const float* time_faaaa = (const float*)d_in[11];
    const float* Wr  = (const float*)d_in[12];
    const float* Wk  = (const float*)d_in[13];
    const float* Wv  = (const float*)d_in[14];
    const float* Wg  = (const float*)d_in[15];
    const float* Wo  = (const float*)d_in[16];
    const float* lnx_w = (const float*)d_in[17];
    const float* lnx_b = (const float*)d_in[18];
    const float* cm_maa = (const float*)d_in[19];
    const float* Wck = (const float*)d_in[20];
    const float* Wcr = (const float*)d_in[21];
    const float* Wcv = (const float*)d_in[22];
    float* out = (float*)d_out;

    float *ph, *pxx, *pa, *pw, *pwt, *py, *px1, *psig, *pout4;
    SYMADDR(ph, g_h);   SYMADDR(pxx, g_xx); SYMADDR(pa, g_a);
    SYMADDR(pw, g_w);   SYMADDR(pwt, g_wt); SYMADDR(py, g_y);
    SYMADDR(px1, g_x1); SYMADDR(psig, g_sig); SYMADDR(pout4, g_out4);

    __half *xxx16,*xw16,*a4,*att16,*xk216,*xr216,*kf16;
    SYMADDR(xxx16, g_xxx16); SYMADDR(xw16, g_xw16);
    SYMADDR(a4, g_act4);     SYMADDR(att16, g_att16);
    SYMADDR(xk216, g_xk216); SYMADDR(xr216, g_xr216);
    SYMADDR(kf16, g_kf16);

    __half *w4,*wo16,*wcr16,*wck16,*wcv16,*maaT,*tdT;
    SYMADDR(w4, g_W4_16);    SYMADDR(wo16, g_Wo16);
    SYMADDR(wcr16, g_Wcr16);
    SYMADDR(wck16, g_Wck16); SYMADDR(wcv16, g_Wcv16);
    SYMADDR(maaT, g_maaw1T); SYMADDR(tdT, g_tdw1T);

    cudaFuncSetAttribute(gemm_mma<TC_TANH>,  cudaFuncAttributeMaxDynamicSharedMemorySize, SM_MMA_TOTAL);
    cudaFuncSetAttribute(gemm_mma<TC_ADDX>,  cudaFuncAttributeMaxDynamicSharedMemorySize, SM_MMA_TOTAL);
    cudaFuncSetAttribute(gemm_mma<TC_RELU2>, cudaFuncAttributeMaxDynamicSharedMemorySize, SM_MMA_TOTAL);
    cudaFuncSetAttribute(gemm_mma<TC_SIGM>,  cudaFuncAttributeMaxDynamicSharedMemorySize, SM_MMA_TOTAL);
    cudaFuncSetAttribute(gemm_mma<TC_CVMIX>, cudaFuncAttributeMaxDynamicSharedMemorySize, SM_MMA_TOTAL);
    cudaFuncSetAttribute(gemm_rkvg,          cudaFuncAttributeMaxDynamicSharedMemorySize, SM_MMA_TOTAL);

    const int ELT_BLOCKS = (MM * Cc) / 256;

    // ---- time mixing ----
    ln_kernel<<<MM, 256>>>(x, ln1_w, ln1_b, ph, 1e-5f);
    shift1_kernel<<<ELT_BLOCKS, 256>>>(tm_maa);
    wtrans6<<<dim3(Cc/32, Cc/32, 6), 256>>>(Wr, Wk, Wv, Wg, Wo, Wcr, w4, wo16, wcr16);
    wtrans16p<<<dim3(256/32, Cc/32), 256>>>(maa_w1, maaT, Cc, 160);
    gemm_mma<TC_TANH><<<mmagrid(MM, 256), 256, SM_MMA_TOTAL>>>(xxx16, maaT, pa,
        MM, 256, Cc, 160, 160, nullptr, nullptr, nullptr);   // launch 5
    mix5_kernel<<<dim3(Cc/128, MM/128, 5), 256>>>(pa, maa_w2, tm_maa, xw16, a4);
    gemm_rkvg<<<dim3(Cc/128, MM/128, 4), 256, SM_MMA_TOTAL>>>(a4, w4, pout4);
    wtrans16p<<<dim3(128/32, Cc/32), 256>>>(td_w1, tdT, Cc, 64);
    gemm_mma<TC_TANH><<<mmagrid(MM, 128), 256, SM_MMA_TOTAL>>>(xw16, tdT, pwt,
        MM, 128, Cc, 64, 64, nullptr, nullptr, nullptr);
    gemm_addvec<<<dim3(Cc/128, MM/128), 256>>>(pwt, td_w2, pw, MM, Cc, 64, 64, Cc, time_decay);
    wkv6_kernel<<<Bq * Hh, 256>>>(time_faaaa,
        pout4 + (size_t)0*MM*Cc, pout4 + (size_t)1*MM*Cc, pout4 + (size_t)2*MM*Cc, pw, py);
    gnsilu_kernel<<<MM * Hh / 8, 256>>>(lnx_w, lnx_b, pout4 + (size_t)3*MM*Cc, py);
    gemm_mma<TC_ADDX><<<mmagrid(MM, Cc), 256, SM_MMA_TOTAL>>>(att16, wo16, px1,
        MM, Cc, Cc, Cc, Cc, x, nullptr, nullptr);

    // ---- channel mixing ----
    ln_kernel<<<MM, 256>>>(px1, ln2_w, ln2_b, ph, 1e-5f);
    shift2_kernel<<<ELT_BLOCKS, 256>>>(cm_maa);
    wtrans16<<<dim3(Ff/32, Cc/32), 256>>>(Wck, wck16, Cc, Ff);
    gemm_mma<TC_RELU2><<<mmagrid(MM, Ff), 256, SM_MMA_TOTAL>>>(xk216, wck16, nullptr,
        MM, Ff, Cc, Ff, Ff, nullptr, nullptr, kf16);
    gemm_mma<TC_SIGM><<<mmagrid(MM, Cc), 256, SM_MMA_TOTAL>>>(xr216, wcr16, psig,
        MM, Cc, Cc, Cc, Cc, nullptr, nullptr, nullptr);
    wtrans16<<<dim3(Cc/32, Ff/32), 256>>>(Wcv, wcv16, Ff, Cc);
    gemm_mma<TC_CVMIX><<<mmagrid(MM, Cc), 256, SM_MMA_TOTAL>>>(kf16, wcv16, out,
        MM, Cc, Ff, Cc, Cc, px1, psig, nullptr);
}

// round 8
// speedup vs baseline: 6.4487x; 1.0197x over previous
#include <cuda_runtime.h>
#include <cuda_fp16.h>
#include <math.h>

// ---------------- problem constants ----------------
#define Bq 2
#define Tt 2048
#define Cc 2048
#define Hh 32
#define Nn 64
#define Ff 7168
#define MM (Bq*Tt)          // 4096 tokens
#define NF1 (Ff + Cc)       // 9216 rows in merged [Wck^T ; Wcr^T] buffer

typedef unsigned int u32;
typedef unsigned long long u64;

// ---------------- device scratch (no allocs allowed) ----------------
__device__ float g_h  [(size_t)MM*Cc];
__device__ float g_xx [(size_t)MM*Cc];
__device__ float g_a  [(size_t)MM*160];
__device__ float g_w  [(size_t)MM*Cc];
__device__ float g_wt [(size_t)MM*64];
__device__ float g_y  [(size_t)MM*Cc];
__device__ float g_x1 [(size_t)MM*Cc];
__device__ float g_sig[(size_t)MM*Cc];
__device__ float g_out4[(size_t)4*MM*Cc];   // r,k,v,g

// fp16 activations (A operands, single precision-rounded)
__device__ __align__(16) __half g_xxx16[(size_t)MM*Cc];
__device__ __align__(16) __half g_xw16 [(size_t)MM*Cc];
__device__ __align__(16) __half g_act4 [(size_t)4*MM*Cc];   // xr,xk,xv,xg
__device__ __align__(16) __half g_att16[(size_t)MM*Cc];
__device__ __align__(16) __half g_xk216[(size_t)MM*Cc];
__device__ __align__(16) __half g_xr216[(size_t)MM*Cc];
__device__ __align__(16) __half g_kf16 [(size_t)MM*Ff];

// fp16 transposed weights ([N,K] K-major)
__device__ __align__(16) __half g_W4_16 [(size_t)4*Cc*Cc];  // Wr,Wk,Wv,Wg
__device__ __align__(16) __half g_Wo16  [(size_t)Cc*Cc];
__device__ __align__(16) __half g_Wffn1 [(size_t)NF1*Cc];   // [Wck^T ; Wcr^T]
__device__ __align__(16) __half g_Wcv16 [(size_t)Ff*Cc];    // [2048,7168]
__device__ __align__(16) __half g_maaw1T[(size_t)256*Cc];   // padded [256,2048]
__device__ __align__(16) __half g_tdw1T [(size_t)128*Cc];   // padded [128,2048]

// ---------------- PTX helpers (baseline PTX; no sm_103a-only features) ----
__device__ __forceinline__ u32 smem_u32(const void* p){
    u32 a;
    asm("{ .reg .u64 t; cvta.to.shared.u64 t, %1; cvt.u32.u64 %0, t; }" : "=r"(a) : "l"(p));
    return a;
}
__device__ __forceinline__ void cp16(u32 s, const void* g){
    asm volatile("cp.async.cg.shared.global [%0], [%1], 16;" :: "r"(s), "l"(g) : "memory");
}
__device__ __forceinline__ void cp_commit(){
    asm volatile("cp.async.commit_group;" ::: "memory");
}
template<int NG> __device__ __forceinline__ void cp_wait(){
    asm volatile("cp.async.wait_group %0;" :: "n"(NG) : "memory");
}
__device__ __forceinline__ void ldsm4(u32* r, u32 a){
    asm volatile("ldmatrix.sync.aligned.m8n8.x4.shared.b16 {%0,%1,%2,%3}, [%4];"
        : "=r"(r[0]), "=r"(r[1]), "=r"(r[2]), "=r"(r[3]) : "r"(a));
}
__device__ __forceinline__ void hmma16(float* c, const u32* a, u32 b0, u32 b1){
    asm volatile(
        "mma.sync.aligned.m16n8k16.row.col.f32.f16.f16.f32 "
        "{%0,%1,%2,%3},{%4,%5,%6,%7},{%8,%9},{%0,%1,%2,%3};"
        : "+f"(c[0]), "+f"(c[1]), "+f"(c[2]), "+f"(c[3])
        : "r"(a[0]), "r"(a[1]), "r"(a[2]), "r"(a[3]), "r"(b0), "r"(b1));
}

// ---------------- single-fp16 HMMA GEMM body ----------------
#define STAGE_BYTES 32768u    // A(16K) B(16K)
#define SM_MMA_TOTAL (3*32768)

enum { TC_NONE=0, TC_SILU, TC_ADDX, TC_SIGM, TC_CVMIX, TC_TANH, TC_RELU2H };

template<int EPI>
__device__ __forceinline__
void mma_body(const __half* __restrict__ A16, const __half* __restrict__ B16,
              float* __restrict__ C, int M, int N, int K, int ldc, int nvalid,
              const float* __restrict__ aux0, const float* __restrict__ aux1,
              __half* __restrict__ Ch)
{
    extern __shared__ char sm_dyn[];
    const u32 sb = smem_u32(sm_dyn);
    const int tid  = threadIdx.x;
    const int wid  = tid >> 5;
    const int lane = tid & 31;
    const int m0 = blockIdx.y * 128;
    const int n0 = blockIdx.x * 128;
    const int wm = (wid & 1) * 64;
    const int wn = (wid >> 1) * 32;

    const int col16 = tid & 7;
    const int lrow  = tid >> 3;
    const u32 soff  = (u32)(lrow * 128 + col16 * 16);
    const u32 swz   = soff ^ ((soff >> 3) & 0x70);
    const size_t rstep = (size_t)32 * K * 2;
    const char* gA = (const char*)A16 + ((size_t)(m0 + lrow) * K + col16 * 8) * 2;
    const char* gB = (const char*)B16 + ((size_t)(n0 + lrow) * K + col16 * 8) * 2;

    auto load_stage = [&](int s){
        u32 base = sb + (u32)(s % 3) * STAGE_BYTES + swz;
        size_t ko = (size_t)s * 128;   // 64 fp16 = 128B along K
        #pragma unroll
        for (int i = 0; i < 4; i++){
            cp16(base +          i*4096u, gA + ko + i*rstep);
            cp16(base + 16384u + i*4096u, gB + ko + i*rstep);
        }
        cp_commit();
    };

    const u32 a_row = (u32)(wm + ((lane >> 3) & 1) * 8 + (lane & 7));
    const u32 a_kb  = (u32)((lane >> 4) * 16);
    const u32 b_row = (u32)(wn + (lane >> 4) * 8 + (lane & 7));
    const u32 b_kb  = (u32)(((lane >> 3) & 1) * 16);

    float acc[4][4][4];
    #pragma unroll
    for (int mi = 0; mi < 4; mi++)
        #pragma unroll
        for (int ni = 0; ni < 4; ni++)
            #pragma unroll
            for (int q = 0; q < 4; q++) acc[mi][ni][q] = 0.f;

    auto compute_stage = [&](u32 base){
        #pragma unroll
        for (int kk = 0; kk < 4; kk++){
            u32 aa[4][4], bb[2][4];
            #pragma unroll
            for (int mi = 0; mi < 4; mi++){
                u32 off = (a_row + mi*16u) * 128u + (u32)kk*32u + a_kb;
                off ^= (off >> 3) & 0x70;
                ldsm4(aa[mi], base + off);
            }
            #pragma unroll
            for (int nj = 0; nj < 2; nj++){
                u32 off = (b_row + nj*16u) * 128u + (u32)kk*32u + b_kb;
                off ^= (off >> 3) & 0x70;
                ldsm4(bb[nj], base + 16384u + off);
            }
            #pragma unroll
            for (int mi = 0; mi < 4; mi++)
                #pragma unroll
                for (int ni = 0; ni < 4; ni++){
                    const u32* pb = &bb[ni >> 1][(ni & 1) * 2];
                    hmma16(acc[mi][ni], aa[mi], pb[0], pb[1]);
                }
        }
    };

    const int NS = K >> 6;
    load_stage(0);
    load_stage(1);
    for (int s = 0; s < NS; s++){
        if (s + 1 < NS) cp_wait<1>(); else cp_wait<0>();
        __syncthreads();
        if (s + 2 < NS) load_stage(s + 2);
        compute_stage(sb + (u32)(s % 3) * STAGE_BYTES);
    }

    #pragma unroll
    for (int mi = 0; mi < 4; mi++){
        #pragma unroll
        for (int ni = 0; ni < 4; ni++){
            const int n = n0 + wn + ni*8 + (lane & 3)*2;
            if (n >= nvalid) continue;
            #pragma unroll
            for (int half = 0; half < 2; half++){
                const int m = m0 + wm + mi*16 + (lane >> 2) + half*8;
                const size_t idx = (size_t)m * ldc + n;
                float v0 = acc[mi][ni][half*2 + 0];
                float v1 = acc[mi][ni][half*2 + 1];
                if (EPI == TC_RELU2H){
                    float r0 = v0 > 0.f ? v0 : 0.f;
                    float r1 = v1 > 0.f ? v1 : 0.f;
                    __half2 hp;
                    hp.x = __float2half_rn(r0 * r0);
                    hp.y = __float2half_rn(r1 * r1);
                    *reinterpret_cast<__half2*>(Ch + idx) = hp;
                    continue;
                }
                if (EPI == TC_SILU){
                    v0 = v0 / (1.f + expf(-v0));
                    v1 = v1 / (1.f + expf(-v1));
                } else if (EPI == TC_TANH){
                    v0 = tanhf(v0); v1 = tanhf(v1);
                } else if (EPI == TC_ADDX){
                    v0 += aux0[idx]; v1 += aux0[idx + 1];
                } else if (EPI == TC_SIGM){
                    v0 = 1.f / (1.f + expf(-v0));
                    v1 = 1.f / (1.f + expf(-v1));
                } else if (EPI == TC_CVMIX){
                    v0 = aux0[idx]     + aux1[idx]     * v0;
                    v1 = aux0[idx + 1] + aux1[idx + 1] * v1;
                }
                float2 o; o.x = v0; o.y = v1;
                *reinterpret_cast<float2*>(C + idx) = o;
            }
        }
    }
}

template<int EPI>
__global__ __launch_bounds__(256, 2)
void gemm_mma(const __half* __restrict__ A16, const __half* __restrict__ B16,
              float* __restrict__ C, int M, int N, int K, int ldc, int nvalid,
              const float* __restrict__ aux0, const float* __restrict__ aux1,
              __half* __restrict__ Ch)
{
    mma_body<EPI>(A16, B16, C, M, N, K, ldc, nvalid, aux0, aux1, Ch);
}

// merged r/k/v/g + td GEMM: z=0..3 rkvg (z==3 silu); z==4: td tanh (x==0 only)
__global__ __launch_bounds__(256, 2)
void gemm_rkvg5(const __half* __restrict__ A4, const __half* __restrict__ W4,
                float* __restrict__ C4,
                const __half* __restrict__ xw16, const __half* __restrict__ tdT,
                float* __restrict__ wt)
{
    const int z = blockIdx.z;
    if (z == 4){
        if (blockIdx.x != 0) return;
        mma_body<TC_TANH>(xw16, tdT, wt, MM, 128, Cc, 64, 64,
                          nullptr, nullptr, nullptr);
        return;
    }
    const size_t ao = (size_t)z * MM * Cc;
    const size_t wo = (size_t)z * Cc * Cc;
    if (z == 3)
        mma_body<TC_SILU>(A4 + ao, W4 + wo, C4 + ao, MM, Cc, Cc, Cc, Cc,
                          nullptr, nullptr, nullptr);
    else
        mma_body<TC_NONE>(A4 + ao, W4 + wo, C4 + ao, MM, Cc, Cc, Cc, Cc,
                          nullptr, nullptr, nullptr);
}

// merged ffn1: grid (72, 32). Tiles [0,56): relu2(xk2@Wck)->kf16.
// Tiles [56,72): sigmoid(xr2@Wcr)->psig, with block origin rebased so
// mma_body sees n0 in [0,2048).
__global__ __launch_bounds__(256, 2)
void gemm_ffn1(const __half* __restrict__ xk2, const __half* __restrict__ xr2,
               const __half* __restrict__ Wf, __half* __restrict__ kf,
               float* __restrict__ sig, int split)
{
    if ((int)blockIdx.x < split){
        mma_body<TC_RELU2H>(xk2, Wf, nullptr, MM, Ff, Cc, Ff, Ff,
                            nullptr, nullptr, kf);
    } else {
        // rebase n via pointer arithmetic: shift B so that this block's
        // n0 (= blockIdx.x*128) addresses Wcr row (n0 - Ff), and shift the
        // output base the same way. All accesses inside mma_body use
        // B16 + n-row and C + m*ldc + n with n = blockIdx.x*128 + ...,
        // so subtracting Ff rows/cols from the bases rebases exactly.
        mma_body<TC_SIGM>(xr2, Wf, sig - Ff, MM, NF1, Cc, Cc, NF1,
                          nullptr, nullptr, nullptr);
    }
}

// ---------------- weight transposes ----------------
__global__ __launch_bounds__(256)
void wtrans16(const float* __restrict__ W, __half* __restrict__ Th, int K, int N)
{
    __shared__ float s[32][33];
    const int tx = threadIdx.x & 31, ty = threadIdx.x >> 5;
    const int n0 = blockIdx.x * 32, k0 = blockIdx.y * 32;
    #pragma unroll
    for (int r = 0; r < 32; r += 8)
        s[ty + r][tx] = W[(size_t)(k0 + ty + r) * N + n0 + tx];
    __syncthreads();
    #pragma unroll
    for (int r = 0; r < 32; r += 8)
        Th[(size_t)(n0 + ty + r) * K + k0 + tx] = __float2half_rn(s[tx][ty + r]);
}

__global__ __launch_bounds__(256)
void wtrans16p(const float* __restrict__ W, __half* __restrict__ Th, int K, int N)
{
    __shared__ float s[32][33];
    const int tx = threadIdx.x & 31, ty = threadIdx.x >> 5;
    const int n0 = blockIdx.x * 32, k0 = blockIdx.y * 32;
    #pragma unroll
    for (int r = 0; r < 32; r += 8){
        int n = n0 + tx;
        s[ty + r][tx] = (n < N) ? W[(size_t)(k0 + ty + r) * N + n] : 0.f;
    }
    __syncthreads();
    #pragma unroll
    for (int r = 0; r < 32; r += 8)
        Th[(size_t)(n0 + ty + r) * K + k0 + tx] = __float2half_rn(s[tx][ty + r]);
}

__global__ __launch_bounds__(256)
void wtrans6(const float* __restrict__ W0, const float* __restrict__ W1,
             const float* __restrict__ W2, const float* __restrict__ W3,
             const float* __restrict__ W4w, const float* __restrict__ W5,
             __half* __restrict__ T4, __half* __restrict__ To, __half* __restrict__ Tcr)
{
    __shared__ float s[32][33];
    const int z = blockIdx.z;
    const float* W = (z==0)?W0:(z==1)?W1:(z==2)?W2:(z==3)?W3:(z==4)?W4w:W5;
    __half* T = (z < 4) ? (T4 + (size_t)z * Cc * Cc) : (z == 4 ? To : Tcr);
    const int tx = threadIdx.x & 31, ty = threadIdx.x >> 5;
    const int n0 = blockIdx.x * 32, k0 = blockIdx.y * 32;
    #pragma unroll
    for (int r = 0; r < 32; r += 8)
        s[ty + r][tx] = W[(size_t)(k0 + ty + r) * Cc + n0 + tx];
    __syncthreads();
    #pragma unroll
    for (int r = 0; r < 32; r += 8)
        T[(size_t)(n0 + ty + r) * Cc + k0 + tx] = __float2half_rn(s[tx][ty + r]);
}

// ---------------- fused 5-way mix, grid.z = f ----------------
__global__ __launch_bounds__(256)
void mix5_kernel(const float* __restrict__ a, const float* __restrict__ w2,
                 const float* __restrict__ tm_maa,
                 __half* __restrict__ xw16, __half* __restrict__ a4)
{
    __shared__ float AsT[32][129];
    __shared__ float Ws[32][128];
    const int tid = threadIdx.x;
    const int f  = blockIdx.z;
    const int c0 = blockIdx.x * 128;
    const int m0 = blockIdx.y * 128;
    const int tcol = tid & 15, trow = tid >> 4;

    #pragma unroll
    for (int i = tid; i < 128 * 32; i += 256){
        int r = i >> 5, d = i & 31;
        AsT[d][r] = a[(size_t)(m0 + r) * 160 + f * 32 + d];
    }
    #pragma unroll
    for (int i = tid; i < 32 * 128; i += 256){
        int d = i >> 7, c = i & 127;
        Ws[d][c] = w2[((size_t)f * 32 + d) * Cc + c0 + c];
    }
    __syncthreads();

    float acc[8][8];
    #pragma unroll
    for (int i = 0; i < 8; i++)
        #pragma unroll
        for (int j = 0; j < 8; j++) acc[i][j] = 0.f;

    #pragma unroll 8
    for (int d = 0; d < 32; d++){
        float regM[8], regN[8];
        #pragma unroll
        for (int i = 0; i < 8; i++) regM[i] = AsT[d][trow*8 + i];
        *(float4*)&regN[0] = *(const float4*)&Ws[d][tcol*8];
        *(float4*)&regN[4] = *(const float4*)&Ws[d][tcol*8 + 4];
        #pragma unroll
        for (int i = 0; i < 8; i++)
            #pragma unroll
            for (int j = 0; j < 8; j++)
                acc[i][j] = fmaf(regM[i], regN[j], acc[i][j]);
    }

    const int slot = (f == 1) ? 1 : (f == 2) ? 2 : (f == 3) ? 0 : 3;
    __half* oh = (f == 0) ? xw16 : a4 + (size_t)slot * MM * Cc;
    const float* maa = tm_maa + (size_t)(1 + f) * Cc + c0 + tcol*8;

    #pragma unroll
    for (int i = 0; i < 8; i++){
        const size_t idx = (size_t)(m0 + trow*8 + i) * Cc + c0 + tcol*8;
        #pragma unroll
        for (int j = 0; j < 8; j += 2){
            float2 hv = *reinterpret_cast<const float2*>(&g_h[idx + j]);
            float2 xv = *reinterpret_cast<const float2*>(&g_xx[idx + j]);
            float v0 = hv.x + xv.x * (maa[j]     + acc[i][j]);
            float v1 = hv.y + xv.y * (maa[j + 1] + acc[i][j + 1]);
            __half2 hp;
            hp.x = __float2half_rn(v0);
            hp.y = __float2half_rn(v1);
            *reinterpret_cast<__half2*>(oh + idx + j) = hp;
        }
    }
}

// ---------------- small SIMT fp32 GEMM (td_w2 only) ----------------
#define BMt 128
#define BNt 128
#define BKt 8
#define TMt 8
#define TNt 8
__global__ __launch_bounds__(256)
void gemm_addvec(const float* __restrict__ A, const float* __restrict__ Bm,
                 float* __restrict__ Cm, int M, int N, int K, int lda, int ldc,
                 const float* __restrict__ aux0)
{
    __shared__ float As[BKt][BMt];
    __shared__ float Bs[BKt][BNt];
    const int bm = blockIdx.y * BMt;
    const int bn = blockIdx.x * BNt;
    const int tid = threadIdx.x;
    const int tcol = tid & 15;
    const int trow = tid >> 4;
    const int a_row = tid >> 1;
    const int a_col = (tid & 1) * 4;
    const int b_row = tid >> 5;
    const int b_col = (tid & 31) * 4;

    float acc[TMt][TNt];
    #pragma unroll
    for (int i = 0; i < TMt; i++)
        #pragma unroll
        for (int j = 0; j < TNt; j++) acc[i][j] = 0.f;

    for (int k0 = 0; k0 < K; k0 += BKt) {
        float4 av = *reinterpret_cast<const float4*>(A + (size_t)(bm + a_row)*lda + k0 + a_col);
        As[a_col+0][a_row] = av.x;
        As[a_col+1][a_row] = av.y;
        As[a_col+2][a_row] = av.z;
        As[a_col+3][a_row] = av.w;
        *reinterpret_cast<float4*>(&Bs[b_row][b_col]) =
            *reinterpret_cast<const float4*>(Bm + (size_t)(k0 + b_row)*N + bn + b_col);
        __syncthreads();
        #pragma unroll
        for (int kk = 0; kk < BKt; kk++) {
            float regM[TMt], regN[TNt];
            *(float4*)&regM[0] = *(const float4*)&As[kk][trow*TMt];
            *(float4*)&regM[4] = *(const float4*)&As[kk][trow*TMt + 4];
            *(float4*)&regN[0] = *(const float4*)&Bs[kk][tcol*TNt];
            *(float4*)&regN[4] = *(const float4*)&Bs[kk][tcol*TNt + 4];
            #pragma unroll
            for (int i = 0; i < TMt; i++)
                #pragma unroll
                for (int j = 0; j < TNt; j++)
                    acc[i][j] = fmaf(regM[i], regN[j], acc[i][j]);
        }
        __syncthreads();
    }

    #pragma unroll
    for (int i = 0; i < TMt; i++) {
        int m = bm + trow*TMt + i;
        #pragma unroll
        for (int j = 0; j < TNt; j++) {
            int n = bn + tcol*TNt + j;
            Cm[(size_t)m * ldc + n] = aux0[n] + acc[i][j];
        }
    }
}

// ---------------- LayerNorm over C per token ----------------
__global__ __launch_bounds__(256)
void ln_kernel(const float* __restrict__ x, const float* __restrict__ w,
               const float* __restrict__ b, float* __restrict__ out, float eps)
{
    const size_t base = (size_t)blockIdx.x * Cc;
    float sum = 0.f, sq = 0.f;
    for (int c = threadIdx.x; c < Cc; c += 256) { float v = x[base + c]; sum += v; sq += v*v; }
    #pragma unroll
    for (int o = 16; o; o >>= 1) {
        sum += __shfl_xor_sync(0xffffffffu, sum, o);
        sq  += __shfl_xor_sync(0xffffffffu, sq,  o);
    }
    __shared__ float s1[8], s2[8];
    int wid = threadIdx.x >> 5, lane = threadIdx.x & 31;
    if (!lane) { s1[wid] = sum; s2[wid] = sq; }
    __syncthreads();
    if (threadIdx.x == 0) {
        float ts = 0.f, tq = 0.f;
        #pragma unroll
        for (int i = 0; i < 8; i++) { ts += s1[i]; tq += s2[i]; }
        float m = ts / (float)Cc;
        float var = tq / (float)Cc - m*m;
        s1[0] = m; s2[0] = rsqrtf(var + eps);
    }
    __syncthreads();
    float m = s1[0], rstd = s2[0];
    for (int c = threadIdx.x; c < Cc; c += 256)
        out[base + c] = (x[base + c] - m) * rstd * w[c] + b[c];
}

// ---------------- token shift + first mix -> fp16 ----------------
__global__ void shift1_kernel(const float* __restrict__ tm_maa)
{
    size_t idx = (size_t)blockIdx.x * 256 + threadIdx.x;
    int c  = (int)(idx % Cc);
    int tt = (int)(idx / Cc);
    int t  = tt % Tt;
    float hv = g_h[idx];
    float hp = t ? g_h[idx - Cc] : 0.f;
    float d = hp - hv;
    g_xx[idx] = d;
    g_xxx16[idx] = __float2half_rn(hv + d * tm_maa[c]);
}

// ---------------- token shift (channel mixing) -> fp16 ----------------
__global__ void shift2_kernel(const float* __restrict__ cm_maa)
{
    size_t idx = (size_t)blockIdx.x * 256 + threadIdx.x;
    int c  = (int)(idx % Cc);
    int tt = (int)(idx / Cc);
    int t  = tt % Tt;
    float hv = g_h[idx];
    float hp = t ? g_h[idx - Cc] : 0.f;
    float d = hp - hv;
    g_xk216[idx] = __float2half_rn(hv + d * cm_maa[c]);
    g_xr216[idx] = __float2half_rn(hv + d * cm_maa[Cc + c]);
}

// ---------------- WKV6 recurrent scan: 256 threads, 16 rows/thread ----------
__global__ __launch_bounds__(256)
void wkv6_kernel(const float* __restrict__ u,
                 const float* __restrict__ rr, const float* __restrict__ kk,
                 const float* __restrict__ vv, const float* __restrict__ ww,
                 float* __restrict__ yy)
{
    const int bh = blockIdx.x;
    const int b  = bh >> 5;
    const int hh = bh & 31;
    const int tid = threadIdx.x;
    const int j = tid & 63;
    const int ib = (tid >> 6) * 16;
    __shared__ float4 sv[64];
    __shared__ float  yp[256];
    float S[16];
    #pragma unroll
    for (int i = 0; i < 16; i++) S[i] = 0.f;
    size_t off = (size_t)b * Tt * Cc + (size_t)hh * Nn;
    float ur = (tid < 64) ? u[hh * Nn + j] : 0.f;

    float rn = 0.f, kn = 0.f, wn = 0.f, vn;
    if (tid < 64){ rn = rr[off + j]; kn = kk[off + j]; wn = ww[off + j]; }
    vn = vv[off + j];

    for (int t = 0; t < Tt; t++) {
        float rc = rn, kc = kn, wc = wn, vc = vn;
        size_t offn = off + Cc;
        if (t + 1 < Tt){
            if (tid < 64){ rn = rr[offn + j]; kn = kk[offn + j]; wn = ww[offn + j]; }
            vn = vv[offn + j];
        }
        if (tid < 64)
            sv[j] = make_float4(rc, kc, ur * kc, expf(-expf(wc)));
        __syncthreads();
        float a0 = 0.f, a1 = 0.f;
        #pragma unroll
        for (int ii = 0; ii < 16; ii += 2) {
            float4 q0 = sv[ib + ii];
            float4 q1 = sv[ib + ii + 1];
            a0 = fmaf(q0.x, fmaf(q0.z, vc, S[ii]), a0);
            S[ii] = fmaf(S[ii], q0.w, q0.y * vc);
            a1 = fmaf(q1.x, fmaf(q1.z, vc, S[ii + 1]), a1);
            S[ii + 1] = fmaf(S[ii + 1], q1.w, q1.y * vc);
        }
        yp[tid] = a0 + a1;
        __syncthreads();
        if (tid < 64) yy[off + j] = yp[j] + yp[64 + j] + yp[128 + j] + yp[192 + j];
        off = offn;
    }
}

// ---------------- GroupNorm(H) * silu-gate -> att fp16 ----------------
__global__ __launch_bounds__(256)
void gnsilu_kernel(const float* __restrict__ lnw, const float* __restrict__ lnb,
                   const float* __restrict__ gg, const float* __restrict__ yy)
{
    int gw  = blockIdx.x * 8 + (threadIdx.x >> 5);
    int lane = threadIdx.x & 31;
    int t  = gw >> 5;
    int hh = gw & 31;
    size_t base = (size_t)t * Cc + (size_t)hh * Nn;
    float y0 = yy[base + lane], y1 = yy[base + 32 + lane];
    float sum = y0 + y1, sq = y0*y0 + y1*y1;
    #pragma unroll
    for (int o = 16; o; o >>= 1) {
        sum += __shfl_xor_sync(0xffffffffu, sum, o);
        sq  += __shfl_xor_sync(0xffffffffu, sq,  o);
    }
    float m = sum * (1.f / 64.f);
    float rstd = rsqrtf(sq * (1.f / 64.f) - m*m + 6.4e-4f);
    int ch = hh * Nn + lane;
    float gv0 = gg[base + lane], gv1 = gg[base + 32 + lane];
    float o0 = ((y0 - m) * rstd * lnw[ch]      + lnb[ch])      * gv0;
    float o1 = ((y1 - m) * rstd * lnw[ch + 32] + lnb[ch + 32]) * gv1;
    g_att16[base + lane]      = __float2half_rn(o0);
    g_att16[base + 32 + lane] = __float2half_rn(o1);
}

// ---------------- host launch (single stream) ----------------
static inline dim3 mmagrid(int M, int N){ return dim3(N / 128, M / 128); }

#define SYMADDR(v, s) cudaGetSymbolAddress((void**)&v, s)

extern "C" void kernel_launch(void* const* d_in, const int* in_sizes, int n_in,
                              void* d_out, int out_size)
{
    (void)in_sizes; (void)n_in; (void)out_size;
    const float* x          = (const float*)d_in[0];
    const float* ln1_w      = (const float*)d_in[1];
    const float* ln1_b      = (const float*)d_in[2];
    const float* ln2_w      = (const float*)d_in[3];
    const float* ln2_b      = (const float*)d_in[4];
    const float* tm_maa     = (const float*)d_in[5];
    const float* maa_w1     = (const float*)d_in[6];
    const float* maa_w2     = (const float*)d_in[7];
    const float* time_decay = (const float*)d_in[8];
    const float* td_w1      = (const float*)d_in[9];
    const float* td_w2      = (const float*)d_in[10];
    const float* time_faaaa = (const float*)d_in[11];
    const float* Wr  = (const float*)d_in[12];
    const float* Wk  = (const float*)d_in[13];
    const float* Wv  = (const float*)d_in[14];
    const float* Wg  = (const float*)d_in[15];
    const float* Wo  = (const float*)d_in[16];
    const float* lnx_w = (const float*)d_in[17];
    const float* lnx_b = (const float*)d_in[18];
    const float* cm_maa = (const float*)d_in[19];
    const float* Wck = (const float*)d_in[20];
    const float* Wcr = (const float*)d_in[21];
    const float* Wcv = (const float*)d_in[22];
    float* out = (float*)d_out;

    float *ph, *pxx, *pa, *pw, *pwt, *py, *px1, *psig, *pout4;
    SYMADDR(ph, g_h);   SYMADDR(pxx, g_xx); SYMADDR(pa, g_a);
    SYMADDR(pw, g_w);   SYMADDR(pwt, g_wt); SYMADDR(py, g_y);
    SYMADDR(px1, g_x1); SYMADDR(psig, g_sig); SYMADDR(pout4, g_out4);

    __half *xxx16,*xw16,*a4,*att16,*xk216,*xr216,*kf16;
    SYMADDR(xxx16, g_xxx16); SYMADDR(xw16, g_xw16);
    SYMADDR(a4, g_act4);     SYMADDR(att16, g_att16);
    SYMADDR(xk216, g_xk216); SYMADDR(xr216, g_xr216);
    SYMADDR(kf16, g_kf16);

    __half *w4,*wo16,*wffn1,*wcv16,*maaT,*tdT;
    SYMADDR(w4, g_W4_16);    SYMADDR(wo16, g_Wo16);
    SYMADDR(wffn1, g_Wffn1); SYMADDR(wcv16, g_Wcv16);
    SYMADDR(maaT, g_maaw1T); SYMADDR(tdT, g_tdw1T);

    cudaFuncSetAttribute(gemm_mma<TC_TANH>,  cudaFuncAttributeMaxDynamicSharedMemorySize, SM_MMA_TOTAL);
    cudaFuncSetAttribute(gemm_mma<TC_ADDX>,  cudaFuncAttributeMaxDynamicSharedMemorySize, SM_MMA_TOTAL);
    cudaFuncSetAttribute(gemm_mma<TC_CVMIX>, cudaFuncAttributeMaxDynamicSharedMemorySize, SM_MMA_TOTAL);
    cudaFuncSetAttribute(gemm_rkvg5,         cudaFuncAttributeMaxDynamicSharedMemorySize, SM_MMA_TOTAL);
    cudaFuncSetAttribute(gemm_ffn1,          cudaFuncAttributeMaxDynamicSharedMemorySize, SM_MMA_TOTAL);

    const int ELT_BLOCKS = (MM * Cc) / 256;

    // ---- weight prep (input-only) ----
    wtrans16p<<<dim3(256/32, Cc/32), 256>>>(maa_w1, maaT, Cc, 160);
    wtrans6<<<dim3(Cc/32, Cc/32, 6), 256>>>(Wr, Wk, Wv, Wg, Wo, Wcr,
        w4, wo16, wffn1 + (size_t)Ff * Cc);
    wtrans16p<<<dim3(128/32, Cc/32), 256>>>(td_w1, tdT, Cc, 64);
    wtrans16<<<dim3(Ff/32, Cc/32), 256>>>(Wck, wffn1, Cc, Ff);
    wtrans16<<<dim3(Cc/32, Ff/32), 256>>>(Wcv, wcv16, Ff, Cc);

    // ---- time mixing ----
    ln_kernel<<<MM, 256>>>(x, ln1_w, ln1_b, ph, 1e-5f);
    shift1_kernel<<<ELT_BLOCKS, 256>>>(tm_maa);
    gemm_mma<TC_TANH><<<mmagrid(MM, 256), 256, SM_MMA_TOTAL>>>(xxx16, maaT, pa,
        MM, 256, Cc, 160, 160, nullptr, nullptr, nullptr);
    mix5_kernel<<<dim3(Cc/128, MM/128, 5), 256>>>(pa, maa_w2, tm_maa, xw16, a4);
    gemm_rkvg5<<<dim3(Cc/128, MM/128, 5), 256, SM_MMA_TOTAL>>>(a4, w4, pout4,
        xw16, tdT, pwt);
    gemm_addvec<<<dim3(Cc/128, MM/128), 256>>>(pwt, td_w2, pw, MM, Cc, 64, 64, Cc, time_decay);
    wkv6_kernel<<<Bq * Hh, 256>>>(time_faaaa,
        pout4 + (size_t)0*MM*Cc, pout4 + (size_t)1*MM*Cc, pout4 + (size_t)2*MM*Cc, pw, py);
    gnsilu_kernel<<<MM * Hh / 8, 256>>>(lnx_w, lnx_b, pout4 + (size_t)3*MM*Cc, py);
    gemm_mma<TC_ADDX><<<mmagrid(MM, Cc), 256, SM_MMA_TOTAL>>>(att16, wo16, px1,
        MM, Cc, Cc, Cc, Cc, x, nullptr, nullptr);

    // ---- channel mixing ----
    ln_kernel<<<MM, 256>>>(px1, ln2_w, ln2_b, ph, 1e-5f);
    shift2_kernel<<<ELT_BLOCKS, 256>>>(cm_maa);
    gemm_ffn1<<<dim3(NF1/128, MM/128), 256, SM_MMA_TOTAL>>>(xk216, xr216, wffn1,
        kf16, psig, Ff/128);
    gemm_mma<TC_CVMIX><<<mmagrid(MM, Cc), 256, SM_MMA_TOTAL>>>(kf16, wcv16, out,
        MM, Cc, Ff, Cc, Cc, px1, psig, nullptr);
}

// round 10
// speedup vs baseline: 9.2308x; 1.4314x over previous
#include <cuda_runtime.h>
#include <cuda_fp16.h>
#include <math.h>

// ---------------- problem constants ----------------
#define Bq 2
#define Tt 2048
#define Cc 2048
#define Hh 32
#define Nn 64
#define Ff 7168
#define MM (Bq*Tt)          // 4096 tokens
#define NF1 (Ff + Cc)       // 9216 rows in merged [Wck^T ; Wcr^T] buffer
#define CH 16               // scan chunks
#define CL (Tt/CH)          // 128 steps per chunk

typedef unsigned int u32;
typedef unsigned long long u64;

// ---------------- device scratch (no allocs allowed) ----------------
__device__ float g_h  [(size_t)MM*Cc];
__device__ float g_xx [(size_t)MM*Cc];
__device__ float g_a  [(size_t)MM*160];
__device__ float g_w  [(size_t)MM*Cc];
__device__ float g_wt [(size_t)MM*64];
__device__ float g_y  [(size_t)MM*Cc];
__device__ float g_x1 [(size_t)MM*Cc];
__device__ float g_sig[(size_t)MM*Cc];
__device__ float g_out4[(size_t)4*MM*Cc];   // r,k,v,g
__device__ float g_rq [(size_t)MM*Cc];      // r * cumdecay (scan phase A)
__device__ float g_P  [(size_t)64*CH*4096]; // chunk-final local states
__device__ float g_D  [(size_t)64*CH*64];   // chunk decay products
__device__ float g_S0 [(size_t)64*CH*4096]; // chunk initial states

// fp16 activations (A operands, single precision-rounded)
__device__ __align__(16) __half g_xxx16[(size_t)MM*Cc];
__device__ __align__(16) __half g_xw16 [(size_t)MM*Cc];
__device__ __align__(16) __half g_act4 [(size_t)4*MM*Cc];   // xr,xk,xv,xg
__device__ __align__(16) __half g_att16[(size_t)MM*Cc];
__device__ __align__(16) __half g_xk216[(size_t)MM*Cc];
__device__ __align__(16) __half g_xr216[(size_t)MM*Cc];
__device__ __align__(16) __half g_kf16 [(size_t)MM*Ff];

// fp16 transposed weights ([N,K] K-major)
__device__ __align__(16) __half g_W4_16 [(size_t)4*Cc*Cc];  // Wr,Wk,Wv,Wg
__device__ __align__(16) __half g_Wo16  [(size_t)Cc*Cc];
__device__ __align__(16) __half g_Wffn1 [(size_t)NF1*Cc];   // [Wck^T ; Wcr^T]
__device__ __align__(16) __half g_Wcv16 [(size_t)Ff*Cc];    // [2048,7168]
__device__ __align__(16) __half g_maaw1T[(size_t)256*Cc];   // padded [256,2048]
__device__ __align__(16) __half g_tdw1T [(size_t)128*Cc];   // padded [128,2048]

// ---------------- PTX helpers (baseline PTX; no sm_103a-only features) ----
__device__ __forceinline__ u32 smem_u32(const void* p){
    u32 a;
    asm("{ .reg .u64 t; cvta.to.shared.u64 t, %1; cvt.u32.u64 %0, t; }" : "=r"(a) : "l"(p));
    return a;
}
__device__ __forceinline__ void cp16(u32 s, const void* g){
    asm volatile("cp.async.cg.shared.global [%0], [%1], 16;" :: "r"(s), "l"(g) : "memory");
}
__device__ __forceinline__ void cp_commit(){
    asm volatile("cp.async.commit_group;" ::: "memory");
}
template<int NG> __device__ __forceinline__ void cp_wait(){
    asm volatile("cp.async.wait_group %0;" :: "n"(NG) : "memory");
}
__device__ __forceinline__ void ldsm4(u32* r, u32 a){
    asm volatile("ldmatrix.sync.aligned.m8n8.x4.shared.b16 {%0,%1,%2,%3}, [%4];"
        : "=r"(r[0]), "=r"(r[1]), "=r"(r[2]), "=r"(r[3]) : "r"(a));
}
__device__ __forceinline__ void hmma16(float* c, const u32* a, u32 b0, u32 b1){
    asm volatile(
        "mma.sync.aligned.m16n8k16.row.col.f32.f16.f16.f32 "
        "{%0,%1,%2,%3},{%4,%5,%6,%7},{%8,%9},{%0,%1,%2,%3};"
        : "+f"(c[0]), "+f"(c[1]), "+f"(c[2]), "+f"(c[3])
        : "r"(a[0]), "r"(a[1]), "r"(a[2]), "r"(a[3]), "r"(b0), "r"(b1));
}

// ---------------- single-fp16 HMMA GEMM body ----------------
#define STAGE_BYTES 32768u    // A(16K) B(16K)
#define SM_MMA_TOTAL (3*32768)

enum { TC_NONE=0, TC_SILU, TC_ADDX, TC_SIGM, TC_CVMIX, TC_TANH, TC_RELU2H };

template<int EPI>
__device__ __forceinline__
void mma_body(const __half* __restrict__ A16, const __half* __restrict__ B16,
              float* __restrict__ C, int M, int N, int K, int ldc, int nvalid,
              const float* __restrict__ aux0, const float* __restrict__ aux1,
              __half* __restrict__ Ch)
{
    extern __shared__ char sm_dyn[];
    const u32 sb = smem_u32(sm_dyn);
    const int tid  = threadIdx.x;
    const int wid  = tid >> 5;
    const int lane = tid & 31;
    const int m0 = blockIdx.y * 128;
    const int n0 = blockIdx.x * 128;
    const int wm = (wid & 1) * 64;
    const int wn = (wid >> 1) * 32;

    const int col16 = tid & 7;
    const int lrow  = tid >> 3;
    const u32 soff  = (u32)(lrow * 128 + col16 * 16);
    const u32 swz   = soff ^ ((soff >> 3) & 0x70);
    const size_t rstep = (size_t)32 * K * 2;
    const char* gA = (const char*)A16 + ((size_t)(m0 + lrow) * K + col16 * 8) * 2;
    const char* gB = (const char*)B16 + ((size_t)(n0 + lrow) * K + col16 * 8) * 2;

    auto load_stage = [&](int s){
        u32 base = sb + (u32)(s % 3) * STAGE_BYTES + swz;
        size_t ko = (size_t)s * 128;   // 64 fp16 = 128B along K
        #pragma unroll
        for (int i = 0; i < 4; i++){
            cp16(base +          i*4096u, gA + ko + i*rstep);
            cp16(base + 16384u + i*4096u, gB + ko + i*rstep);
        }
        cp_commit();
    };

    const u32 a_row = (u32)(wm + ((lane >> 3) & 1) * 8 + (lane & 7));
    const u32 a_kb  = (u32)((lane >> 4) * 16);
    const u32 b_row = (u32)(wn + (lane >> 4) * 8 + (lane & 7));
    const u32 b_kb  = (u32)(((lane >> 3) & 1) * 16);

    float acc[4][4][4];
    #pragma unroll
    for (int mi = 0; mi < 4; mi++)
        #pragma unroll
        for (int ni = 0; ni < 4; ni++)
            #pragma unroll
            for (int q = 0; q < 4; q++) acc[mi][ni][q] = 0.f;

    auto compute_stage = [&](u32 base){
        #pragma unroll
        for (int kk = 0; kk < 4; kk++){
            u32 aa[4][4], bb[2][4];
            #pragma unroll
            for (int mi = 0; mi < 4; mi++){
                u32 off = (a_row + mi*16u) * 128u + (u32)kk*32u + a_kb;
                off ^= (off >> 3) & 0x70;
                ldsm4(aa[mi], base + off);
            }
            #pragma unroll
            for (int nj = 0; nj < 2; nj++){
                u32 off = (b_row + nj*16u) * 128u + (u32)kk*32u + b_kb;
                off ^= (off >> 3) & 0x70;
                ldsm4(bb[nj], base + 16384u + off);
            }
            #pragma unroll
            for (int mi = 0; mi < 4; mi++)
                #pragma unroll
                for (int ni = 0; ni < 4; ni++){
                    const u32* pb = &bb[ni >> 1][(ni & 1) * 2];
                    hmma16(acc[mi][ni], aa[mi], pb[0], pb[1]);
                }
        }
    };

    const int NS = K >> 6;
    load_stage(0);
    load_stage(1);
    for (int s = 0; s < NS; s++){
        if (s + 1 < NS) cp_wait<1>(); else cp_wait<0>();
        __syncthreads();
        if (s + 2 < NS) load_stage(s + 2);
        compute_stage(sb + (u32)(s % 3) * STAGE_BYTES);
    }

    #pragma unroll
    for (int mi = 0; mi < 4; mi++){
        #pragma unroll
        for (int ni = 0; ni < 4; ni++){
            const int n = n0 + wn + ni*8 + (lane & 3)*2;
            if (n >= nvalid) continue;
            #pragma unroll
            for (int half = 0; half < 2; half++){
                const int m = m0 + wm + mi*16 + (lane >> 2) + half*8;
                const size_t idx = (size_t)m * ldc + n;
                float v0 = acc[mi][ni][half*2 + 0];
                float v1 = acc[mi][ni][half*2 + 1];
                if (EPI == TC_RELU2H){
                    float r0 = v0 > 0.f ? v0 : 0.f;
                    float r1 = v1 > 0.f ? v1 : 0.f;
                    __half2 hp;
                    hp.x = __float2half_rn(r0 * r0);
                    hp.y = __float2half_rn(r1 * r1);
                    *reinterpret_cast<__half2*>(Ch + idx) = hp;
                    continue;
                }
                if (EPI == TC_SILU){
                    v0 = v0 / (1.f + expf(-v0));
                    v1 = v1 / (1.f + expf(-v1));
                } else if (EPI == TC_TANH){
                    v0 = tanhf(v0); v1 = tanhf(v1);
                } else if (EPI == TC_ADDX){
                    v0 += aux0[idx]; v1 += aux0[idx + 1];
                } else if (EPI == TC_SIGM){
                    v0 = 1.f / (1.f + expf(-v0));
                    v1 = 1.f / (1.f + expf(-v1));
                } else if (EPI == TC_CVMIX){
                    v0 = aux0[idx]     + aux1[idx]     * v0;
                    v1 = aux0[idx + 1] + aux1[idx + 1] * v1;
                }
                float2 o; o.x = v0; o.y = v1;
                *reinterpret_cast<float2*>(C + idx) = o;
            }
        }
    }
}

template<int EPI>
__global__ __launch_bounds__(256, 2)
void gemm_mma(const __half* __restrict__ A16, const __half* __restrict__ B16,
              float* __restrict__ C, int M, int N, int K, int ldc, int nvalid,
              const float* __restrict__ aux0, const float* __restrict__ aux1,
              __half* __restrict__ Ch)
{
    mma_body<EPI>(A16, B16, C, M, N, K, ldc, nvalid, aux0, aux1, Ch);
}

// merged r/k/v/g + td GEMM: z=0..3 rkvg (z==3 silu); z==4: td tanh (x==0 only)
__global__ __launch_bounds__(256, 2)
void gemm_rkvg5(const __half* __restrict__ A4, const __half* __restrict__ W4,
                float* __restrict__ C4,
                const __half* __restrict__ xw16, const __half* __restrict__ tdT,
                float* __restrict__ wt)
{
    const int z = blockIdx.z;
    if (z == 4){
        if (blockIdx.x != 0) return;
        mma_body<TC_TANH>(xw16, tdT, wt, MM, 128, Cc, 64, 64,
                          nullptr, nullptr, nullptr);
        return;
    }
    const size_t ao = (size_t)z * MM * Cc;
    const size_t wo = (size_t)z * Cc * Cc;
    if (z == 3)
        mma_body<TC_SILU>(A4 + ao, W4 + wo, C4 + ao, MM, Cc, Cc, Cc, Cc,
                          nullptr, nullptr, nullptr);
    else
        mma_body<TC_NONE>(A4 + ao, W4 + wo, C4 + ao, MM, Cc, Cc, Cc, Cc,
                          nullptr, nullptr, nullptr);
}

// merged ffn1: grid (72, 32). Tiles [0,56): relu2(xk2@Wck)->kf16.
// Tiles [56,72): sigmoid(xr2@Wcr)->psig (bases shifted by -Ff to rebase n).
__global__ __launch_bounds__(256, 2)
void gemm_ffn1(const __half* __restrict__ xk2, const __half* __restrict__ xr2,
               const __half* __restrict__ Wf, __half* __restrict__ kf,
               float* __restrict__ sig, int split)
{
    if ((int)blockIdx.x < split){
        mma_body<TC_RELU2H>(xk2, Wf, nullptr, MM, Ff, Cc, Ff, Ff,
                            nullptr, nullptr, kf);
    } else {
        mma_body<TC_SIGM>(xr2, Wf, sig - Ff, MM, NF1, Cc, Cc, NF1,
                          nullptr, nullptr, nullptr);
    }
}

// ---------------- weight transposes ----------------
__global__ __launch_bounds__(256)
void wtrans16(const float* __restrict__ W, __half* __restrict__ Th, int K, int N)
{
    __shared__ float s[32][33];
    const int tx = threadIdx.x & 31, ty = threadIdx.x >> 5;
    const int n0 = blockIdx.x * 32, k0 = blockIdx.y * 32;
    #pragma unroll
    for (int r = 0; r < 32; r += 8)
        s[ty + r][tx] = W[(size_t)(k0 + ty + r) * N + n0 + tx];
    __syncthreads();
    #pragma unroll
    for (int r = 0; r < 32; r += 8)
        Th[(size_t)(n0 + ty + r) * K + k0 + tx] = __float2half_rn(s[tx][ty + r]);
}

__global__ __launch_bounds__(256)
void wtrans16p(const float* __restrict__ W, __half* __restrict__ Th, int K, int N)
{
    __shared__ float s[32][33];
    const int tx = threadIdx.x & 31, ty = threadIdx.x >> 5;
    const int n0 = blockIdx.x * 32, k0 = blockIdx.y * 32;
    #pragma unroll
    for (int r = 0; r < 32; r += 8){
        int n = n0 + tx;
        s[ty + r][tx] = (n < N) ? W[(size_t)(k0 + ty + r) * N + n] : 0.f;
    }
    __syncthreads();
    #pragma unroll
    for (int r = 0; r < 32; r += 8)
        Th[(size_t)(n0 + ty + r) * K + k0 + tx] = __float2half_rn(s[tx][ty + r]);
}

__global__ __launch_bounds__(256)
void wtrans6(const float* __restrict__ W0, const float* __restrict__ W1,
             const float* __restrict__ W2, const float* __restrict__ W3,
             const float* __restrict__ W4w, const float* __restrict__ W5,
             __half* __restrict__ T4, __half* __restrict__ To, __half* __restrict__ Tcr)
{
    __shared__ float s[32][33];
    const int z = blockIdx.z;
    const float* W = (z==0)?W0:(z==1)?W1:(z==2)?W2:(z==3)?W3:(z==4)?W4w:W5;
    __half* T = (z < 4) ? (T4 + (size_t)z * Cc * Cc) : (z == 4 ? To : Tcr);
    const int tx = threadIdx.x & 31, ty = threadIdx.x >> 5;
    const int n0 = blockIdx.x * 32, k0 = blockIdx.y * 32;
    #pragma unroll
    for (int r = 0; r < 32; r += 8)
        s[ty + r][tx] = W[(size_t)(k0 + ty + r) * Cc + n0 + tx];
    __syncthreads();
    #pragma unroll
    for (int r = 0; r < 32; r += 8)
        T[(size_t)(n0 + ty + r) * Cc + k0 + tx] = __float2half_rn(s[tx][ty + r]);
}

// ---------------- fused 5-way mix, grid.z = f ----------------
__global__ __launch_bounds__(256)
void mix5_kernel(const float* __restrict__ a, const float* __restrict__ w2,
                 const float* __restrict__ tm_maa,
                 __half* __restrict__ xw16, __half* __restrict__ a4)
{
    __shared__ float AsT[32][129];
    __shared__ float Ws[32][128];
    const int tid = threadIdx.x;
    const int f  = blockIdx.z;
    const int c0 = blockIdx.x * 128;
    const int m0 = blockIdx.y * 128;
    const int tcol = tid & 15, trow = tid >> 4;

    #pragma unroll
    for (int i = tid; i < 128 * 32; i += 256){
        int r = i >> 5, d = i & 31;
        AsT[d][r] = a[(size_t)(m0 + r) * 160 + f * 32 + d];
    }
    #pragma unroll
    for (int i = tid; i < 32 * 128; i += 256){
        int d = i >> 7, c = i & 127;
        Ws[d][c] = w2[((size_t)f * 32 + d) * Cc + c0 + c];
    }
    __syncthreads();

    float acc[8][8];
    #pragma unroll
    for (int i = 0; i < 8; i++)
        #pragma unroll
        for (int j = 0; j < 8; j++) acc[i][j] = 0.f;

    #pragma unroll 8
    for (int d = 0; d < 32; d++){
        float regM[8], regN[8];
        #pragma unroll
        for (int i = 0; i < 8; i++) regM[i] = AsT[d][trow*8 + i];
        *(float4*)&regN[0] = *(const float4*)&Ws[d][tcol*8];
        *(float4*)&regN[4] = *(const float4*)&Ws[d][tcol*8 + 4];
        #pragma unroll
        for (int i = 0; i < 8; i++)
            #pragma unroll
            for (int j = 0; j < 8; j++)
                acc[i][j] = fmaf(regM[i], regN[j], acc[i][j]);
    }

    const int slot = (f == 1) ? 1 : (f == 2) ? 2 : (f == 3) ? 0 : 3;
    __half* oh = (f == 0) ? xw16 : a4 + (size_t)slot * MM * Cc;
    const float* maa = tm_maa + (size_t)(1 + f) * Cc + c0 + tcol*8;

    #pragma unroll
    for (int i = 0; i < 8; i++){
        const size_t idx = (size_t)(m0 + trow*8 + i) * Cc + c0 + tcol*8;
        #pragma unroll
        for (int j = 0; j < 8; j += 2){
            float2 hv = *reinterpret_cast<const float2*>(&g_h[idx + j]);
            float2 xv = *reinterpret_cast<const float2*>(&g_xx[idx + j]);
            float v0 = hv.x + xv.x * (maa[j]     + acc[i][j]);
            float v1 = hv.y + xv.y * (maa[j + 1] + acc[i][j + 1]);
            __half2 hp;
            hp.x = __float2half_rn(v0);
            hp.y = __float2half_rn(v1);
            *reinterpret_cast<__half2*>(oh + idx + j) = hp;
        }
    }
}

// ---------------- small SIMT fp32 GEMM (td_w2 only) ----------------
#define BMt 128
#define BNt 128
#define BKt 8
#define TMt 8
#define TNt 8
__global__ __launch_bounds__(256)
void gemm_addvec(const float* __restrict__ A, const float* __restrict__ Bm,
                 float* __restrict__ Cm, int M, int N, int K, int lda, int ldc,
                 const float* __restrict__ aux0)
{
    __shared__ float As[BKt][BMt];
    __shared__ float Bs[BKt][BNt];
    const int bm = blockIdx.y * BMt;
    const int bn = blockIdx.x * BNt;
    const int tid = threadIdx.x;
    const int tcol = tid & 15;
    const int trow = tid >> 4;
    const int a_row = tid >> 1;
    const int a_col = (tid & 1) * 4;
    const int b_row = tid >> 5;
    const int b_col = (tid & 31) * 4;

    float acc[TMt][TNt];
    #pragma unroll
    for (int i = 0; i < TMt; i++)
        #pragma unroll
        for (int j = 0; j < TNt; j++) acc[i][j] = 0.f;

    for (int k0 = 0; k0 < K; k0 += BKt) {
        float4 av = *reinterpret_cast<const float4*>(A + (size_t)(bm + a_row)*lda + k0 + a_col);
        As[a_col+0][a_row] = av.x;
        As[a_col+1][a_row] = av.y;
        As[a_col+2][a_row] = av.z;
        As[a_col+3][a_row] = av.w;
        *reinterpret_cast<float4*>(&Bs[b_row][b_col]) =
            *reinterpret_cast<const float4*>(Bm + (size_t)(k0 + b_row)*N + bn + b_col);
        __syncthreads();
        #pragma unroll
        for (int kk = 0; kk < BKt; kk++) {
            float regM[TMt], regN[TNt];
            *(float4*)&regM[0] = *(const float4*)&As[kk][trow*TMt];
            *(float4*)&regM[4] = *(const float4*)&As[kk][trow*TMt + 4];
            *(float4*)&regN[0] = *(const float4*)&Bs[kk][tcol*TNt];
            *(float4*)&regN[4] = *(const float4*)&Bs[kk][tcol*TNt + 4];
            #pragma unroll
            for (int i = 0; i < TMt; i++)
                #pragma unroll
                for (int j = 0; j < TNt; j++)
                    acc[i][j] = fmaf(regM[i], regN[j], acc[i][j]);
        }
        __syncthreads();
    }

    #pragma unroll
    for (int i = 0; i < TMt; i++) {
        int m = bm + trow*TMt + i;
        #pragma unroll
        for (int j = 0; j < TNt; j++) {
            int n = bn + tcol*TNt + j;
            Cm[(size_t)m * ldc + n] = aux0[n] + acc[i][j];
        }
    }
}

// ---------------- LayerNorm over C per token ----------------
__global__ __launch_bounds__(256)
void ln_kernel(const float* __restrict__ x, const float* __restrict__ w,
               const float* __restrict__ b, float* __restrict__ out, float eps)
{
    const size_t base = (size_t)blockIdx.x * Cc;
    float sum = 0.f, sq = 0.f;
    for (int c = threadIdx.x; c < Cc; c += 256) { float v = x[base + c]; sum += v; sq += v*v; }
    #pragma unroll
    for (int o = 16; o; o >>= 1) {
        sum += __shfl_xor_sync(0xffffffffu, sum, o);
        sq  += __shfl_xor_sync(0xffffffffu, sq,  o);
    }
    __shared__ float s1[8], s2[8];
    int wid = threadIdx.x >> 5, lane = threadIdx.x & 31;
    if (!lane) { s1[wid] = sum; s2[wid] = sq; }
    __syncthreads();
    if (threadIdx.x == 0) {
        float ts = 0.f, tq = 0.f;
        #pragma unroll
        for (int i = 0; i < 8; i++) { ts += s1[i]; tq += s2[i]; }
        float m = ts / (float)Cc;
        float var = tq / (float)Cc - m*m;
        s1[0] = m; s2[0] = rsqrtf(var + eps);
    }
    __syncthreads();
    float m = s1[0], rstd = s2[0];
    for (int c = threadIdx.x; c < Cc; c += 256)
        out[base + c] = (x[base + c] - m) * rstd * w[c] + b[c];
}

// ---------------- token shift + first mix -> fp16 ----------------
__global__ void shift1_kernel(const float* __restrict__ tm_maa)
{
    size_t idx = (size_t)blockIdx.x * 256 + threadIdx.x;
    int c  = (int)(idx % Cc);
    int tt = (int)(idx / Cc);
    int t  = tt % Tt;
    float hv = g_h[idx];
    float hp = t ? g_h[idx - Cc] : 0.f;
    float d = hp - hv;
    g_xx[idx] = d;
    g_xxx16[idx] = __float2half_rn(hv + d * tm_maa[c]);
}

// ---------------- token shift (channel mixing) -> fp16 ----------------
__global__ void shift2_kernel(const float* __restrict__ cm_maa)
{
    size_t idx = (size_t)blockIdx.x * 256 + threadIdx.x;
    int c  = (int)(idx % Cc);
    int tt = (int)(idx / Cc);
    int t  = tt % Tt;
    float hv = g_h[idx];
    float hp = t ? g_h[idx - Cc] : 0.f;
    float d = hp - hv;
    g_xk216[idx] = __float2half_rn(hv + d * cm_maa[c]);
    g_xr216[idx] = __float2half_rn(hv + d * cm_maa[Cc + c]);
}

// ---------------- WKV6 chunk-parallel scan ----------------
// Phase A: grid 64*CH blocks. Chunk-local scan from S=0; emits local y,
// rq = r*cumdecay, chunk-final state P, chunk decay product D.
__global__ __launch_bounds__(256)
void wkv6_partA(const float* __restrict__ u,
                const float* __restrict__ rr, const float* __restrict__ kk,
                const float* __restrict__ vv, const float* __restrict__ ww,
                float* __restrict__ yy, float* __restrict__ rq,
                float* __restrict__ Pc, float* __restrict__ Dc)
{
    const int blk = blockIdx.x;
    const int bh = blk >> 4;       // / CH
    const int ch = blk & (CH - 1);
    const int b = bh >> 5, hh = bh & 31;
    const int tid = threadIdx.x;
    const int j = tid & 63;
    const int ib = (tid >> 6) * 16;
    __shared__ float4 sv[64];
    __shared__ float  yp[256];
    float S[16];
    #pragma unroll
    for (int i = 0; i < 16; i++) S[i] = 0.f;
    size_t off = (size_t)b * Tt * Cc + (size_t)ch * CL * Cc + (size_t)hh * Nn;
    float ur = (tid < 64) ? u[hh * Nn + j] : 0.f;
    float cum = 1.f;

    float rn = 0.f, kn = 0.f, wn = 0.f, vn;
    if (tid < 64){ rn = rr[off + j]; kn = kk[off + j]; wn = ww[off + j]; }
    vn = vv[off + j];

    for (int t = 0; t < CL; t++) {
        float rc = rn, kc = kn, wc = wn, vc = vn;
        size_t offn = off + Cc;
        if (t + 1 < CL){
            if (tid < 64){ rn = rr[offn + j]; kn = kk[offn + j]; wn = ww[offn + j]; }
            vn = vv[offn + j];
        }
        if (tid < 64){
            float d = expf(-expf(wc));
            rq[off + j] = rc * cum;
            cum *= d;
            sv[j] = make_float4(rc, kc, ur * kc, d);
        }
        __syncthreads();
        float a0 = 0.f, a1 = 0.f;
        #pragma unroll
        for (int ii = 0; ii < 16; ii += 2) {
            float4 q0 = sv[ib + ii];
            float4 q1 = sv[ib + ii + 1];
            a0 = fmaf(q0.x, fmaf(q0.z, vc, S[ii]), a0);
            S[ii] = fmaf(S[ii], q0.w, q0.y * vc);
            a1 = fmaf(q1.x, fmaf(q1.z, vc, S[ii + 1]), a1);
            S[ii + 1] = fmaf(S[ii + 1], q1.w, q1.y * vc);
        }
        yp[tid] = a0 + a1;
        __syncthreads();
        if (tid < 64) yy[off + j] = yp[j] + yp[64 + j] + yp[128 + j] + yp[192 + j];
        off = offn;
    }
    const size_t pbase = ((size_t)bh * CH + ch) * 4096;
    #pragma unroll
    for (int ii = 0; ii < 16; ii++)
        Pc[pbase + (size_t)(ib + ii) * 64 + j] = S[ii];
    if (tid < 64) Dc[((size_t)bh * CH + ch) * 64 + j] = cum;
}

// Phase B: grid 64 blocks. Sequential chunk combine; emits S0 per chunk.
__global__ __launch_bounds__(256)
void wkv6_partB(const float* __restrict__ Pc, const float* __restrict__ Dc,
                float* __restrict__ S0)
{
    const int bh = blockIdx.x;
    const int tid = threadIdx.x;
    const int e0 = tid * 16;
    const int i  = e0 >> 6;      // state row (same for all 16 elems)
    float4 s[4];
    #pragma unroll
    for (int q = 0; q < 4; q++) s[q] = make_float4(0.f, 0.f, 0.f, 0.f);
    for (int ch = 0; ch < CH; ch++){
        const size_t base = ((size_t)bh * CH + ch) * 4096 + e0;
        #pragma unroll
        for (int q = 0; q < 4; q++)
            *reinterpret_cast<float4*>(&S0[base + q*4]) = s[q];
        const float d = Dc[((size_t)bh * CH + ch) * 64 + i];
        #pragma unroll
        for (int q = 0; q < 4; q++){
            float4 p = *reinterpret_cast<const float4*>(&Pc[base + q*4]);
            s[q].x = fmaf(s[q].x, d, p.x);
            s[q].y = fmaf(s[q].y, d, p.y);
            s[q].z = fmaf(s[q].z, d, p.z);
            s[q].w = fmaf(s[q].w, d, p.w);
        }
    }
}

// Phase C: grid 64*CH*2 blocks. y += RQ[64t x 64i] @ S0[64i x 64j].
// smem rows padded to 68 floats (272B) so float4 row accesses stay 16B-aligned.
__global__ __launch_bounds__(256)
void wkv6_partC(const float* __restrict__ rq, const float* __restrict__ S0,
                float* __restrict__ yy)
{
    const int x = blockIdx.x;
    const int half = x & 1;
    const int ch = (x >> 1) & (CH - 1);
    const int bh = x >> 5;
    if (ch == 0) return;          // S0 = 0 for first chunk
    const int b = bh >> 5, hh = bh & 31;
    __shared__ float sS0[64][68];
    __shared__ float sRq[64][68];
    const int tid = threadIdx.x;
    const size_t off = (size_t)b * Tt * Cc
                     + (size_t)(ch * CL + half * 64) * Cc + (size_t)hh * Nn;
    const size_t sbase = ((size_t)bh * CH + ch) * 4096;

    {
        const int e0 = tid * 16;
        const int r = e0 >> 6, c = e0 & 63;
        #pragma unroll
        for (int q = 0; q < 4; q++){
            float4 v = *reinterpret_cast<const float4*>(&S0[sbase + e0 + q*4]);
            *reinterpret_cast<float4*>(&sS0[r][c + q*4]) = v;
            float4 w = *reinterpret_cast<const float4*>(&rq[off + (size_t)r * Cc + c + q*4]);
            *reinterpret_cast<float4*>(&sRq[r][c + q*4]) = w;
        }
    }
    __syncthreads();

    const int tr = tid >> 2;
    const int jq = (tid & 3) * 16;
    float acc[16];
    #pragma unroll
    for (int q = 0; q < 16; q++) acc[q] = 0.f;
    #pragma unroll 4
    for (int i = 0; i < 64; i++){
        float rv = sRq[tr][i];
        #pragma unroll
        for (int q = 0; q < 16; q++)
            acc[q] = fmaf(rv, sS0[i][jq + q], acc[q]);
    }
    const size_t ybase = off + (size_t)tr * Cc + jq;
    #pragma unroll
    for (int q = 0; q < 16; q += 4){
        float4 y4 = *reinterpret_cast<float4*>(&yy[ybase + q]);
        y4.x += acc[q];     y4.y += acc[q + 1];
        y4.z += acc[q + 2]; y4.w += acc[q + 3];
        *reinterpret_cast<float4*>(&yy[ybase + q]) = y4;
    }
}

// ---------------- GroupNorm(H) * silu-gate -> att fp16 ----------------
__global__ __launch_bounds__(256)
void gnsilu_kernel(const float* __restrict__ lnw, const float* __restrict__ lnb,
                   const float* __restrict__ gg, const float* __restrict__ yy)
{
    int gw  = blockIdx.x * 8 + (threadIdx.x >> 5);
    int lane = threadIdx.x & 31;
    int t  = gw >> 5;
    int hh = gw & 31;
    size_t base = (size_t)t * Cc + (size_t)hh * Nn;
    float y0 = yy[base + lane], y1 = yy[base + 32 + lane];
    float sum = y0 + y1, sq = y0*y0 + y1*y1;
    #pragma unroll
    for (int o = 16; o; o >>= 1) {
        sum += __shfl_xor_sync(0xffffffffu, sum, o);
        sq  += __shfl_xor_sync(0xffffffffu, sq,  o);
    }
    float m = sum * (1.f / 64.f);
    float rstd = rsqrtf(sq * (1.f / 64.f) - m*m + 6.4e-4f);
    int ch = hh * Nn + lane;
    float gv0 = gg[base + lane], gv1 = gg[base + 32 + lane];
    float o0 = ((y0 - m) * rstd * lnw[ch]      + lnb[ch])      * gv0;
    float o1 = ((y1 - m) * rstd * lnw[ch + 32] + lnb[ch + 32]) * gv1;
    g_att16[base + lane]      = __float2half_rn(o0);
    g_att16[base + 32 + lane] = __float2half_rn(o1);
}

// ---------------- host launch (single stream) ----------------
static inline dim3 mmagrid(int M, int N){ return dim3(N / 128, M / 128); }

#define SYMADDR(v, s) cudaGetSymbolAddress((void**)&v, s)

extern "C" void kernel_launch(void* const* d_in, const int* in_sizes, int n_in,
                              void* d_out, int out_size)
{
    (void)in_sizes; (void)n_in; (void)out_size;
    const float* x          = (const float*)d_in[0];
    const float* ln1_w      = (const float*)d_in[1];
    const float* ln1_b      = (const float*)d_in[2];
    const float* ln2_w      = (const float*)d_in[3];
    const float* ln2_b      = (const float*)d_in[4];
    const float* tm_maa     = (const float*)d_in[5];
    const float* maa_w1     = (const float*)d_in[6];
    const float* maa_w2     = (const float*)d_in[7];
    const float* time_decay = (const float*)d_in[8];
    const float* td_w1      = (const float*)d_in[9];
    const float* td_w2      = (const float*)d_in[10];
    const float* time_faaaa = (const float*)d_in[11];
    const float* Wr  = (const float*)d_in[12];
    const float* Wk  = (const float*)d_in[13];
    const float* Wv  = (const float*)d_in[14];
    const float* Wg  = (const float*)d_in[15];
    const float* Wo  = (const float*)d_in[16];
    const float* lnx_w = (const float*)d_in[17];
    const float* lnx_b = (const float*)d_in[18];
    const float* cm_maa = (const float*)d_in[19];
    const float* Wck = (const float*)d_in[20];
    const float* Wcr = (const float*)d_in[21];
    const float* Wcv = (const float*)d_in[22];
    float* out = (float*)d_out;

    float *ph, *pxx, *pa, *pw, *pwt, *py, *px1, *psig, *pout4, *prq, *pP, *pD, *pS0;
    SYMADDR(ph, g_h);   SYMADDR(pxx, g_xx); SYMADDR(pa, g_a);
    SYMADDR(pw, g_w);   SYMADDR(pwt, g_wt); SYMADDR(py, g_y);
    SYMADDR(px1, g_x1); SYMADDR(psig, g_sig); SYMADDR(pout4, g_out4);
    SYMADDR(prq, g_rq); SYMADDR(pP, g_P);   SYMADDR(pD, g_D);  SYMADDR(pS0, g_S0);

    __half *xxx16,*xw16,*a4,*att16,*xk216,*xr216,*kf16;
    SYMADDR(xxx16, g_xxx16); SYMADDR(xw16, g_xw16);
    SYMADDR(a4, g_act4);     SYMADDR(att16, g_att16);
    SYMADDR(xk216, g_xk216); SYMADDR(xr216, g_xr216);
    SYMADDR(kf16, g_kf16);

    __half *w4,*wo16,*wffn1,*wcv16,*maaT,*tdT;
    SYMADDR(w4, g_W4_16);    SYMADDR(wo16, g_Wo16);
    SYMADDR(wffn1, g_Wffn1); SYMADDR(wcv16, g_Wcv16);
    SYMADDR(maaT, g_maaw1T); SYMADDR(tdT, g_tdw1T);

    cudaFuncSetAttribute(gemm_mma<TC_TANH>,  cudaFuncAttributeMaxDynamicSharedMemorySize, SM_MMA_TOTAL);
    cudaFuncSetAttribute(gemm_mma<TC_ADDX>,  cudaFuncAttributeMaxDynamicSharedMemorySize, SM_MMA_TOTAL);
    cudaFuncSetAttribute(gemm_mma<TC_CVMIX>, cudaFuncAttributeMaxDynamicSharedMemorySize, SM_MMA_TOTAL);
    cudaFuncSetAttribute(gemm_rkvg5,         cudaFuncAttributeMaxDynamicSharedMemorySize, SM_MMA_TOTAL);
    cudaFuncSetAttribute(gemm_ffn1,          cudaFuncAttributeMaxDynamicSharedMemorySize, SM_MMA_TOTAL);

    const int ELT_BLOCKS = (MM * Cc) / 256;

    // ---- time mixing (maa GEMM placed 4th so ncu -s5 captures it) ----
    ln_kernel<<<MM, 256>>>(x, ln1_w, ln1_b, ph, 1e-5f);                       // 1
    shift1_kernel<<<ELT_BLOCKS, 256>>>(tm_maa);                               // 2
    wtrans16p<<<dim3(256/32, Cc/32), 256>>>(maa_w1, maaT, Cc, 160);           // 3
    gemm_mma<TC_TANH><<<mmagrid(MM, 256), 256, SM_MMA_TOTAL>>>(xxx16, maaT, pa,
        MM, 256, Cc, 160, 160, nullptr, nullptr, nullptr);                    // 4 <- profiled
    wtrans6<<<dim3(Cc/32, Cc/32, 6), 256>>>(Wr, Wk, Wv, Wg, Wo, Wcr,
        w4, wo16, wffn1 + (size_t)Ff * Cc);                                   // 5
    wtrans16p<<<dim3(128/32, Cc/32), 256>>>(td_w1, tdT, Cc, 64);              // 6
    wtrans16<<<dim3(Ff/32, Cc/32), 256>>>(Wck, wffn1, Cc, Ff);                // 7
    wtrans16<<<dim3(Cc/32, Ff/32), 256>>>(Wcv, wcv16, Ff, Cc);                // 8
    mix5_kernel<<<dim3(Cc/128, MM/128, 5), 256>>>(pa, maa_w2, tm_maa, xw16, a4);
    gemm_rkvg5<<<dim3(Cc/128, MM/128, 5), 256, SM_MMA_TOTAL>>>(a4, w4, pout4,
        xw16, tdT, pwt);
    gemm_addvec<<<dim3(Cc/128, MM/128), 256>>>(pwt, td_w2, pw, MM, Cc, 64, 64, Cc, time_decay);
    wkv6_partA<<<64 * CH, 256>>>(time_faaaa,
        pout4 + (size_t)0*MM*Cc, pout4 + (size_t)1*MM*Cc, pout4 + (size_t)2*MM*Cc,
        pw, py, prq, pP, pD);
    wkv6_partB<<<64, 256>>>(pP, pD, pS0);
    wkv6_partC<<<64 * CH * 2, 256>>>(prq, pS0, py);
    gnsilu_kernel<<<MM * Hh / 8, 256>>>(lnx_w, lnx_b, pout4 + (size_t)3*MM*Cc, py);
    gemm_mma<TC_ADDX><<<mmagrid(MM, Cc), 256, SM_MMA_TOTAL>>>(att16, wo16, px1,
        MM, Cc, Cc, Cc, Cc, x, nullptr, nullptr);

    // ---- channel mixing ----
    ln_kernel<<<MM, 256>>>(px1, ln2_w, ln2_b, ph, 1e-5f);
    shift2_kernel<<<ELT_BLOCKS, 256>>>(cm_maa);
    gemm_ffn1<<<dim3(NF1/128, MM/128), 256, SM_MMA_TOTAL>>>(xk216, xr216, wffn1,
        kf16, psig, Ff/128);
    gemm_mma<TC_CVMIX><<<mmagrid(MM, Cc), 256, SM_MMA_TOTAL>>>(kf16, wcv16, out,
        MM, Cc, Ff, Cc, Cc, px1, psig, nullptr);
}